// round 2
// baseline (speedup 1.0000x reference)
#include <cuda_runtime.h>
#include <math.h>

#define BATCH  65536
#define DIM    512
#define NPROTO 1024

// Scratch (allocation-free rule: __device__ globals)
__device__ float g_z[(size_t)BATCH * DIM];     // 128 MB: z = x@W^T + b
__device__ float g_zsq[BATCH];
__device__ float g_psq[NPROTO];

// ---------------- reductions ----------------
__device__ __forceinline__ float wsum(float v) {
#pragma unroll
    for (int o = 16; o; o >>= 1) v += __shfl_xor_sync(0xffffffffu, v, o);
    return v;
}
__device__ __forceinline__ float wmax(float v) {
#pragma unroll
    for (int o = 16; o; o >>= 1) v = fmaxf(v, __shfl_xor_sync(0xffffffffu, v, o));
    return v;
}

// row-wise sum of squares for 512-wide rows (one block of 128 threads per row)
__global__ __launch_bounds__(128) void row_sumsq_512(const float* __restrict__ X,
                                                     float* __restrict__ out) {
    size_t row = blockIdx.x;
    const float4* p = (const float4*)(X + row * 512);
    float4 v = p[threadIdx.x];
    float s = v.x * v.x + v.y * v.y + v.z * v.z + v.w * v.w;
    s = wsum(s);
    __shared__ float red[4];
    if ((threadIdx.x & 31) == 0) red[threadIdx.x >> 5] = s;
    __syncthreads();
    if (threadIdx.x == 0) out[row] = red[0] + red[1] + red[2] + red[3];
}

// in-place softmax over rows of 1024 (one block of 256 threads per row)
__global__ __launch_bounds__(256) void softmax_1024(float* __restrict__ Wt) {
    size_t row = blockIdx.x;
    float4* p = (float4*)(Wt + row * 1024);
    float4 v = p[threadIdx.x];

    __shared__ float red[8];
    float m = fmaxf(fmaxf(v.x, v.y), fmaxf(v.z, v.w));
    m = wmax(m);
    if ((threadIdx.x & 31) == 0) red[threadIdx.x >> 5] = m;
    __syncthreads();
    if (threadIdx.x < 32) {
        float t = (threadIdx.x < 8) ? red[threadIdx.x] : -INFINITY;
        t = wmax(t);
        if (threadIdx.x == 0) red[0] = t;
    }
    __syncthreads();
    m = red[0];
    __syncthreads();

    v.x = expf(v.x - m); v.y = expf(v.y - m);
    v.z = expf(v.z - m); v.w = expf(v.w - m);
    float s = v.x + v.y + v.z + v.w;
    s = wsum(s);
    __shared__ float red2[8];
    if ((threadIdx.x & 31) == 0) red2[threadIdx.x >> 5] = s;
    __syncthreads();
    if (threadIdx.x < 32) {
        float t = (threadIdx.x < 8) ? red2[threadIdx.x] : 0.0f;
        t = wsum(t);
        if (threadIdx.x == 0) red2[0] = t;
    }
    __syncthreads();
    float inv = 1.0f / red2[0];
    v.x *= inv; v.y *= inv; v.z *= inv; v.w *= inv;
    p[threadIdx.x] = v;
}

// ---------------- packed f32x2 mainloop helpers ----------------
// acc[ip][j] packs rows (2ip, 2ip+1) of the 8x8 per-thread tile for column j.
struct AccPack {
    unsigned long long v[4][8];
};

__device__ __forceinline__ void mainloop_step(
    AccPack& acc, const float (*As)[132], const float (*Bs)[132],
    int lrow, int lcol) {
#pragma unroll
    for (int kk = 0; kk < 16; ++kk) {
        // A: natural 64-bit pairs (rows interleaved 2 at a time)
        ulonglong2 a01 = *(const ulonglong2*)&As[kk][lrow];
        ulonglong2 a23 = *(const ulonglong2*)&As[kk][lrow + 4];
        unsigned long long a[4] = {a01.x, a01.y, a23.x, a23.y};
        // B: 8 scalars, duplicated into 64-bit lanes
        float bf[8];
        *(float4*)&bf[0] = *(const float4*)&Bs[kk][lcol];
        *(float4*)&bf[4] = *(const float4*)&Bs[kk][lcol + 4];
        unsigned long long bd[8];
#pragma unroll
        for (int j = 0; j < 8; j++) {
            unsigned int bi = __float_as_uint(bf[j]);
            asm("mov.b64 %0, {%1, %1};" : "=l"(bd[j]) : "r"(bi));
        }
#pragma unroll
        for (int ip = 0; ip < 4; ip++)
#pragma unroll
            for (int j = 0; j < 8; j++)
                asm("fma.rn.f32x2 %0, %1, %2, %0;"
                    : "+l"(acc.v[ip][j]) : "l"(a[ip]), "l"(bd[j]));
    }
}

__device__ __forceinline__ void unpack_acc(const AccPack& acc, float (*c)[8]) {
#pragma unroll
    for (int ip = 0; ip < 4; ip++)
#pragma unroll
        for (int j = 0; j < 8; j++) {
            unsigned int lo, hi;
            asm("mov.b64 {%0, %1}, %2;" : "=r"(lo), "=r"(hi) : "l"(acc.v[ip][j]));
            c[2 * ip + 0][j] = __uint_as_float(lo);
            c[2 * ip + 1][j] = __uint_as_float(hi);
        }
}

// ---------------- GEMMs: 128x128 tile, BK=16, 8x8 per thread, 256 threads ----
// NT: A [M,K] row-major, Bm [N,K] row-major, C = A @ Bm^T (+ epilogue)
// MODE 0: C = A@Bm^T + bias[col]  (encoder fc)
// MODE 1: C = -sqrt(max(zsq[row]+psq[col]-2*(A@Bm^T), 1e-12)) / temp  (scores)
template <int MODE>
__global__ __launch_bounds__(256, 2) void gemm_nt_128(
    const float* __restrict__ A, const float* __restrict__ Bm,
    float* __restrict__ C, const float* __restrict__ bias,
    const float* __restrict__ zsq, const float* __restrict__ psq,
    const float* __restrict__ temp_raw, int K, int ldc) {
    __shared__ __align__(16) float As[16][132];
    __shared__ __align__(16) float Bs[16][132];
    const int tid = threadIdx.x;
    const size_t bm = (size_t)blockIdx.x * 128;
    const size_t bn = (size_t)blockIdx.y * 128;
    const int lrow = (tid >> 4) << 3;   // 0..120
    const int lcol = (tid & 15) << 3;   // 0..120

    AccPack acc;
#pragma unroll
    for (int ip = 0; ip < 4; ip++)
#pragma unroll
        for (int j = 0; j < 8; j++) acc.v[ip][j] = 0ull;

    const float* Abase = A + bm * K;
    const float* Bbase = Bm + bn * K;

    for (int k0 = 0; k0 < K; k0 += 16) {
#pragma unroll
        for (int it = 0; it < 2; ++it) {
            int f = tid + it * 256;          // 0..511
            int r = f >> 2;                  // 0..127
            int kc = (f & 3) << 2;           // 0,4,8,12
            float4 va = *(const float4*)(Abase + (size_t)r * K + k0 + kc);
            As[kc + 0][r] = va.x; As[kc + 1][r] = va.y;
            As[kc + 2][r] = va.z; As[kc + 3][r] = va.w;
            float4 vb = *(const float4*)(Bbase + (size_t)r * K + k0 + kc);
            Bs[kc + 0][r] = vb.x; Bs[kc + 1][r] = vb.y;
            Bs[kc + 2][r] = vb.z; Bs[kc + 3][r] = vb.w;
        }
        __syncthreads();
        mainloop_step(acc, As, Bs, lrow, lcol);
        __syncthreads();
    }

    float c[8][8];
    unpack_acc(acc, c);

    if (MODE == 0) {
        float bv[8];
        *(float4*)&bv[0] = *(const float4*)&bias[bn + lcol];
        *(float4*)&bv[4] = *(const float4*)&bias[bn + lcol + 4];
#pragma unroll
        for (int i = 0; i < 8; i++) {
            float* crow = C + (bm + lrow + i) * ldc + bn + lcol;
            float o[8];
#pragma unroll
            for (int j = 0; j < 8; j++) o[j] = c[i][j] + bv[j];
            *(float4*)crow = *(float4*)&o[0];
            *(float4*)(crow + 4) = *(float4*)&o[4];
        }
    } else {
        float t = temp_raw[0];
        float temp = 1.0f / (1.0f + expf(-t)) * 0.999f + 0.001f;
        float invt = 1.0f / temp;
        float pv[8];
        *(float4*)&pv[0] = *(const float4*)&psq[bn + lcol];
        *(float4*)&pv[4] = *(const float4*)&psq[bn + lcol + 4];
#pragma unroll
        for (int i = 0; i < 8; i++) {
            float zr = zsq[bm + lrow + i];
            float o[8];
#pragma unroll
            for (int j = 0; j < 8; j++) {
                float d2 = fmaxf(zr + pv[j] - 2.0f * c[i][j], 1e-12f);
                o[j] = -sqrtf(d2) * invt;
            }
            float* crow = C + (bm + lrow + i) * ldc + bn + lcol;
            *(float4*)crow = *(float4*)&o[0];
            *(float4*)(crow + 4) = *(float4*)&o[4];
        }
    }
}

// NN: A [M,K] row-major, Bm [K,N] row-major, C = A @ Bm
__global__ __launch_bounds__(256, 2) void gemm_nn_128(
    const float* __restrict__ A, const float* __restrict__ Bm,
    float* __restrict__ C, int K, int ldb, int ldc) {
    __shared__ __align__(16) float As[16][132];
    __shared__ __align__(16) float Bs[16][132];
    const int tid = threadIdx.x;
    const size_t bm = (size_t)blockIdx.x * 128;
    const size_t bn = (size_t)blockIdx.y * 128;
    const int lrow = (tid >> 4) << 3;
    const int lcol = (tid & 15) << 3;

    AccPack acc;
#pragma unroll
    for (int ip = 0; ip < 4; ip++)
#pragma unroll
        for (int j = 0; j < 8; j++) acc.v[ip][j] = 0ull;

    const float* Abase = A + bm * K;

    for (int k0 = 0; k0 < K; k0 += 16) {
#pragma unroll
        for (int it = 0; it < 2; ++it) {
            int f = tid + it * 256;
            // A tile (transpose into As)
            int r = f >> 2;
            int kc = (f & 3) << 2;
            float4 va = *(const float4*)(Abase + (size_t)r * K + k0 + kc);
            As[kc + 0][r] = va.x; As[kc + 1][r] = va.y;
            As[kc + 2][r] = va.z; As[kc + 3][r] = va.w;
            // B tile (direct): 16 rows x 128 cols
            int kr = f >> 5;            // 0..15
            int nc = (f & 31) << 2;     // 0..124
            float4 vb = *(const float4*)(Bm + (size_t)(k0 + kr) * ldb + bn + nc);
            *(float4*)&Bs[kr][nc] = vb;
        }
        __syncthreads();
        mainloop_step(acc, As, Bs, lrow, lcol);
        __syncthreads();
    }

    float c[8][8];
    unpack_acc(acc, c);

#pragma unroll
    for (int i = 0; i < 8; i++) {
        float* crow = C + (bm + lrow + i) * ldc + bn + lcol;
        *(float4*)crow = *(float4*)&c[i][0];
        *(float4*)(crow + 4) = *(float4*)&c[i][4];
    }
}

extern "C" void kernel_launch(void* const* d_in, const int* in_sizes, int n_in,
                              void* d_out, int out_size) {
    const float* x  = (const float*)d_in[0];   // [B, D]
    const float* W  = (const float*)d_in[1];   // [D, D]
    const float* b  = (const float*)d_in[2];   // [D]
    const float* P  = (const float*)d_in[3];   // [N, D]
    const float* tr = (const float*)d_in[4];   // [1]

    float* blended = (float*)d_out;                          // [B, D]
    float* weights = (float*)d_out + (size_t)BATCH * DIM;    // [B, N]

    float *z, *zsq, *psq;
    cudaGetSymbolAddress((void**)&z,   g_z);
    cudaGetSymbolAddress((void**)&zsq, g_zsq);
    cudaGetSymbolAddress((void**)&psq, g_psq);

    // 1) prototype squared norms
    row_sumsq_512<<<NPROTO, 128>>>(P, psq);

    // 2) z = x @ W^T + b
    gemm_nt_128<0><<<dim3(BATCH / 128, DIM / 128), 256>>>(
        x, W, z, b, nullptr, nullptr, nullptr, DIM, DIM);

    // 3) z squared norms
    row_sumsq_512<<<BATCH, 128>>>(z, zsq);

    // 4) scores = -sqrt(max(zsq + psq - 2 z@P^T, 1e-12)) / temp
    gemm_nt_128<1><<<dim3(BATCH / 128, NPROTO / 128), 256>>>(
        z, P, weights, nullptr, zsq, psq, tr, DIM, NPROTO);

    // 5) softmax rows -> weights
    softmax_1024<<<BATCH, 256>>>(weights);

    // 6) blended = weights @ P
    gemm_nn_128<<<dim3(BATCH / 128, DIM / 128), 256>>>(
        weights, P, blended, NPROTO, DIM, DIM);
}

// round 4
// speedup vs baseline: 2.2194x; 2.2194x over previous
#include <cuda_runtime.h>
#include <cuda_fp16.h>
#include <math.h>
#include <stdint.h>

#define BATCH  65536
#define DIM    512
#define NPROTO 1024

// Scratch (allocation-free rule: __device__ globals)
__device__ float g_z[(size_t)BATCH * DIM];        // z = x@W^T + b
__device__ float g_pt[(size_t)DIM * NPROTO];      // P^T [512,1024]
__device__ float g_zsq[BATCH];
__device__ float g_psq[NPROTO];

// ======================= helpers =======================
__device__ __forceinline__ uint32_t smem_u32(const void* p) {
    uint32_t a;
    asm("{ .reg .u64 t; cvta.to.shared.u64 t, %1; cvt.u32.u64 %0, t; }" : "=r"(a) : "l"(p));
    return a;
}

#define LDSM4(r, addr) \
    asm volatile("ldmatrix.sync.aligned.m8n8.x4.shared.b16 {%0,%1,%2,%3}, [%4];" \
        : "=r"((r)[0]), "=r"((r)[1]), "=r"((r)[2]), "=r"((r)[3]) : "r"(addr))

#define MMA16816(d, a, b0, b1) \
    asm volatile("mma.sync.aligned.m16n8k16.row.col.f32.f16.f16.f32 " \
        "{%0,%1,%2,%3}, {%4,%5,%6,%7}, {%8,%9}, {%0,%1,%2,%3};" \
        : "+f"((d)[0]), "+f"((d)[1]), "+f"((d)[2]), "+f"((d)[3]) \
        : "r"((a)[0]), "r"((a)[1]), "r"((a)[2]), "r"((a)[3]), "r"(b0), "r"(b1))

__device__ __forceinline__ void sts64(uint32_t a, uint32_t x, uint32_t y) {
    asm volatile("st.shared.v2.b32 [%0], {%1,%2};" :: "r"(a), "r"(x), "r"(y) : "memory");
}

// split float pair -> hi (fp16x2) and lo (fp16x2)
__device__ __forceinline__ void split2(float x, float y, uint32_t& hi, uint32_t& lo) {
    __half hx = __float2half_rn(x), hy = __float2half_rn(y);
    __half2 h2 = __halves2half2(hx, hy);
    hi = *(uint32_t*)&h2;
    __half2 l2 = __floats2half2_rn(x - __half2float(hx), y - __half2float(hy));
    lo = *(uint32_t*)&l2;
}

// SMEM: per buf 4 matrices (Ahi, Alo, Bhi, Blo), each 128 rows x 24 halfwords (48B)
#define MATB   6144u                    // 128*48
#define BUFB   (4u * MATB)              // 24576
#define SMEM_TOTAL (2 * BUFB)           // 49152

// ======================= HMMA GEMM NT =======================
// C[M,N] = A[M,K] @ Bm[N,K]^T  via 3x fp16-split mma.sync
// MODE 0: +bias[col] ; MODE 1: -sqrt(max(zsq+psq-2s,1e-12))/temp ; MODE 2: plain
template <int MODE>
__global__ __launch_bounds__(256, 2) void hmma_gemm_nt(
    const float* __restrict__ A, const float* __restrict__ Bm,
    float* __restrict__ C, const float* __restrict__ bias,
    const float* __restrict__ zsq, const float* __restrict__ psq,
    const float* __restrict__ temp_raw, int K, int ldc) {
    extern __shared__ __align__(128) char smem[];
    const uint32_t sb = smem_u32(smem);
    const int tid = threadIdx.x;
    const int wid = tid >> 5, lane = tid & 31;
    const size_t bm = (size_t)blockIdx.x * 128;
    const size_t bn = (size_t)blockIdx.y * 128;
    const int warp_m = (wid >> 1) * 32;
    const int warp_n = (wid & 1) * 64;

    float acc[2][8][4];
#pragma unroll
    for (int i = 0; i < 2; i++)
#pragma unroll
        for (int j = 0; j < 8; j++)
#pragma unroll
            for (int k = 0; k < 4; k++) acc[i][j][k] = 0.0f;

    const float* Abase = A + bm * K;
    const float* Bbase = Bm + bn * K;
    const int NC = K >> 4;

    // fill mapping: idx in [0,512): r = idx>>2 (row), q = idx&3 (float4 within 16 cols)
    const int f_r0 = tid >> 2, f_q0 = tid & 3;
    const int f_r1 = (tid + 256) >> 2, f_q1 = f_q0;  // same q, row +64

    // ---- prologue fill chunk 0 into buf 0 ----
    {
#pragma unroll
        for (int it = 0; it < 2; ++it) {
            int r = it ? f_r1 : f_r0, q = it ? f_q1 : f_q0;
            float4 va = *(const float4*)(Abase + (size_t)r * K + q * 4);
            float4 vb = *(const float4*)(Bbase + (size_t)r * K + q * 4);
            uint32_t off = (uint32_t)(r * 48 + q * 8);
            uint32_t h0, l0, h1, l1;
            split2(va.x, va.y, h0, l0); split2(va.z, va.w, h1, l1);
            sts64(sb + off, h0, h1);
            sts64(sb + MATB + off, l0, l1);
            split2(vb.x, vb.y, h0, l0); split2(vb.z, vb.w, h1, l1);
            sts64(sb + 2 * MATB + off, h0, h1);
            sts64(sb + 3 * MATB + off, l0, l1);
        }
    }
    __syncthreads();

    // ldmatrix lane address components
    const int a_row = lane & 15;
    const int a_kb = ((lane >> 4) << 3) * 2;          // byte offset in k
    const int b_n = ((lane >> 4) << 3) + (lane & 7);
    const int b_kb = (lane & 8) * 2;

    float4 pa[2], pb[2];
    for (int c = 0; c < NC; ++c) {
        const int buf = c & 1;
        const uint32_t base = sb + buf * BUFB;

        if (c + 1 < NC) {
            const int k0 = (c + 1) << 4;
            pa[0] = *(const float4*)(Abase + (size_t)f_r0 * K + k0 + f_q0 * 4);
            pb[0] = *(const float4*)(Bbase + (size_t)f_r0 * K + k0 + f_q0 * 4);
            pa[1] = *(const float4*)(Abase + (size_t)f_r1 * K + k0 + f_q1 * 4);
            pb[1] = *(const float4*)(Bbase + (size_t)f_r1 * K + k0 + f_q1 * 4);
        }

        uint32_t ah[2][4], al[2][4];
#pragma unroll
        for (int i = 0; i < 2; i++) {
            uint32_t ra = base + (uint32_t)((warp_m + i * 16 + a_row) * 48) + a_kb;
            LDSM4(ah[i], ra);
            LDSM4(al[i], ra + MATB);
        }
#pragma unroll
        for (int jp = 0; jp < 4; jp++) {
            uint32_t rb = base + 2 * MATB +
                          (uint32_t)((warp_n + jp * 16 + b_n) * 48) + b_kb;
            uint32_t bh[4], bl[4];
            LDSM4(bh, rb);
            LDSM4(bl, rb + MATB);
#pragma unroll
            for (int i = 0; i < 2; i++) {
                MMA16816(acc[i][jp * 2 + 0], ah[i], bh[0], bh[1]);
                MMA16816(acc[i][jp * 2 + 0], ah[i], bl[0], bl[1]);
                MMA16816(acc[i][jp * 2 + 0], al[i], bh[0], bh[1]);
                MMA16816(acc[i][jp * 2 + 1], ah[i], bh[2], bh[3]);
                MMA16816(acc[i][jp * 2 + 1], ah[i], bl[2], bl[3]);
                MMA16816(acc[i][jp * 2 + 1], al[i], bh[2], bh[3]);
            }
        }

        if (c + 1 < NC) {
            const uint32_t nbase = sb + (buf ^ 1) * BUFB;
#pragma unroll
            for (int it = 0; it < 2; ++it) {
                int r = it ? f_r1 : f_r0, q = it ? f_q1 : f_q0;
                float4 va = pa[it], vb = pb[it];
                uint32_t off = (uint32_t)(r * 48 + q * 8);
                uint32_t h0, l0, h1, l1;
                split2(va.x, va.y, h0, l0); split2(va.z, va.w, h1, l1);
                sts64(nbase + off, h0, h1);
                sts64(nbase + MATB + off, l0, l1);
                split2(vb.x, vb.y, h0, l0); split2(vb.z, vb.w, h1, l1);
                sts64(nbase + 2 * MATB + off, h0, h1);
                sts64(nbase + 3 * MATB + off, l0, l1);
            }
        }
        __syncthreads();
    }

    // ---- epilogue ----
    float invt = 0.0f;
    if (MODE == 1) {
        float t = temp_raw[0];
        float temp = 1.0f / (1.0f + expf(-t)) * 0.999f + 0.001f;
        invt = 1.0f / temp;
    }
    const int rbase = warp_m + (lane >> 2);
    const int cbase = warp_n + (lane & 3) * 2;
#pragma unroll
    for (int i = 0; i < 2; i++) {
#pragma unroll
        for (int h = 0; h < 2; h++) {
            const size_t row = bm + rbase + i * 16 + h * 8;
            float zr = (MODE == 1) ? zsq[row] : 0.0f;
            float* crow = C + row * ldc + bn;
#pragma unroll
            for (int j = 0; j < 8; j++) {
                const int cg = cbase + j * 8;
                float v0 = acc[i][j][h * 2 + 0];
                float v1 = acc[i][j][h * 2 + 1];
                if (MODE == 0) {
                    v0 += bias[bn + cg];
                    v1 += bias[bn + cg + 1];
                } else if (MODE == 1) {
                    float d0 = fmaxf(zr + psq[bn + cg] - 2.0f * v0, 1e-12f);
                    float d1 = fmaxf(zr + psq[bn + cg + 1] - 2.0f * v1, 1e-12f);
                    v0 = -sqrtf(d0) * invt;
                    v1 = -sqrtf(d1) * invt;
                }
                *(float2*)(crow + cg) = make_float2(v0, v1);
            }
        }
    }
}

// ======================= small kernels =======================
__device__ __forceinline__ float wsum(float v) {
#pragma unroll
    for (int o = 16; o; o >>= 1) v += __shfl_xor_sync(0xffffffffu, v, o);
    return v;
}
__device__ __forceinline__ float wmax(float v) {
#pragma unroll
    for (int o = 16; o; o >>= 1) v = fmaxf(v, __shfl_xor_sync(0xffffffffu, v, o));
    return v;
}

__global__ __launch_bounds__(128) void row_sumsq_512(const float* __restrict__ X,
                                                     float* __restrict__ out) {
    size_t row = blockIdx.x;
    const float4* p = (const float4*)(X + row * 512);
    float4 v = p[threadIdx.x];
    float s = v.x * v.x + v.y * v.y + v.z * v.z + v.w * v.w;
    s = wsum(s);
    __shared__ float red[4];
    if ((threadIdx.x & 31) == 0) red[threadIdx.x >> 5] = s;
    __syncthreads();
    if (threadIdx.x == 0) out[row] = red[0] + red[1] + red[2] + red[3];
}

__global__ __launch_bounds__(256) void softmax_1024(float* __restrict__ Wt) {
    size_t row = blockIdx.x;
    float4* p = (float4*)(Wt + row * 1024);
    float4 v = p[threadIdx.x];

    __shared__ float red[8];
    float m = fmaxf(fmaxf(v.x, v.y), fmaxf(v.z, v.w));
    m = wmax(m);
    if ((threadIdx.x & 31) == 0) red[threadIdx.x >> 5] = m;
    __syncthreads();
    if (threadIdx.x < 32) {
        float t = (threadIdx.x < 8) ? red[threadIdx.x] : -INFINITY;
        t = wmax(t);
        if (threadIdx.x == 0) red[0] = t;
    }
    __syncthreads();
    m = red[0];
    __syncthreads();

    v.x = expf(v.x - m); v.y = expf(v.y - m);
    v.z = expf(v.z - m); v.w = expf(v.w - m);
    float s = v.x + v.y + v.z + v.w;
    s = wsum(s);
    __shared__ float red2[8];
    if ((threadIdx.x & 31) == 0) red2[threadIdx.x >> 5] = s;
    __syncthreads();
    if (threadIdx.x < 32) {
        float t = (threadIdx.x < 8) ? red2[threadIdx.x] : 0.0f;
        t = wsum(t);
        if (threadIdx.x == 0) red2[0] = t;
    }
    __syncthreads();
    float inv = 1.0f / red2[0];
    v.x *= inv; v.y *= inv; v.z *= inv; v.w *= inv;
    p[threadIdx.x] = v;
}

// transpose P [1024,512] -> PT [512,1024]
__global__ __launch_bounds__(256) void transpose_P(const float* __restrict__ P,
                                                   float* __restrict__ PT) {
    __shared__ float t[32][33];
    int bx = blockIdx.x * 32;
    int by = blockIdx.y * 32;
    int tx = threadIdx.x & 31, ty = (threadIdx.x >> 5) * 4;
#pragma unroll
    for (int i = 0; i < 4; i++)
        t[ty + i][tx] = P[(size_t)(by + ty + i) * 512 + bx + tx];
    __syncthreads();
#pragma unroll
    for (int i = 0; i < 4; i++)
        PT[(size_t)(bx + ty + i) * 1024 + by + tx] = t[tx][ty + i];
}

extern "C" void kernel_launch(void* const* d_in, const int* in_sizes, int n_in,
                              void* d_out, int out_size) {
    const float* x  = (const float*)d_in[0];
    const float* W  = (const float*)d_in[1];
    const float* b  = (const float*)d_in[2];
    const float* P  = (const float*)d_in[3];
    const float* tr = (const float*)d_in[4];

    float* blended = (float*)d_out;
    float* weights = (float*)d_out + (size_t)BATCH * DIM;

    float *z, *pt, *zsq, *psq;
    cudaGetSymbolAddress((void**)&z,   g_z);
    cudaGetSymbolAddress((void**)&pt,  g_pt);
    cudaGetSymbolAddress((void**)&zsq, g_zsq);
    cudaGetSymbolAddress((void**)&psq, g_psq);

    cudaFuncSetAttribute(hmma_gemm_nt<0>, cudaFuncAttributeMaxDynamicSharedMemorySize, SMEM_TOTAL);
    cudaFuncSetAttribute(hmma_gemm_nt<1>, cudaFuncAttributeMaxDynamicSharedMemorySize, SMEM_TOTAL);
    cudaFuncSetAttribute(hmma_gemm_nt<2>, cudaFuncAttributeMaxDynamicSharedMemorySize, SMEM_TOTAL);

    // prototype norms + transpose
    row_sumsq_512<<<NPROTO, 128>>>(P, psq);
    transpose_P<<<dim3(16, 32), 256>>>(P, pt);

    // 1) z = x @ W^T + b
    hmma_gemm_nt<0><<<dim3(BATCH / 128, DIM / 128), 256, SMEM_TOTAL>>>(
        x, W, z, b, nullptr, nullptr, nullptr, DIM, DIM);

    // 2) z norms
    row_sumsq_512<<<BATCH, 128>>>(z, zsq);

    // 3) scores
    hmma_gemm_nt<1><<<dim3(BATCH / 128, NPROTO / 128), 256, SMEM_TOTAL>>>(
        z, P, weights, nullptr, zsq, psq, tr, DIM, NPROTO);

    // 4) softmax
    softmax_1024<<<BATCH, 256>>>(weights);

    // 5) blended = weights @ P  (as NT with PT)
    hmma_gemm_nt<2><<<dim3(BATCH / 128, DIM / 128), 256, SMEM_TOTAL>>>(
        weights, pt, blended, nullptr, nullptr, nullptr, nullptr, NPROTO, DIM);
}

// round 5
// speedup vs baseline: 2.3619x; 1.0642x over previous
#include <cuda_runtime.h>
#include <cuda_fp16.h>
#include <math.h>
#include <stdint.h>

#define BATCH  65536
#define DIM    512
#define NPROTO 1024

// ---------------- device scratch (fp16 hi/lo split operands) ----------------
__device__ __half g_xh[(size_t)BATCH * DIM],  g_xl[(size_t)BATCH * DIM];
__device__ __half g_zh[(size_t)BATCH * DIM],  g_zl[(size_t)BATCH * DIM];
__device__ __half g_Wh[(size_t)DIM * DIM],    g_Wl[(size_t)DIM * DIM];
__device__ __half g_Ph[(size_t)NPROTO * DIM], g_Pl[(size_t)NPROTO * DIM];
__device__ __half g_PTh[(size_t)DIM * NPROTO], g_PTl[(size_t)DIM * NPROTO];
__device__ __half g_wgh[(size_t)BATCH * NPROTO], g_wgl[(size_t)BATCH * NPROTO];
__device__ float g_zsq[BATCH];
__device__ float g_psq[NPROTO];

// ======================= helpers =======================
__device__ __forceinline__ uint32_t smem_u32(const void* p) {
    uint32_t a;
    asm("{ .reg .u64 t; cvta.to.shared.u64 t, %1; cvt.u32.u64 %0, t; }" : "=r"(a) : "l"(p));
    return a;
}

#define LDSM4(r, addr) \
    asm volatile("ldmatrix.sync.aligned.m8n8.x4.shared.b16 {%0,%1,%2,%3}, [%4];" \
        : "=r"((r)[0]), "=r"((r)[1]), "=r"((r)[2]), "=r"((r)[3]) : "r"(addr))

#define MMA16816(d, a, b0, b1) \
    asm volatile("mma.sync.aligned.m16n8k16.row.col.f32.f16.f16.f32 " \
        "{%0,%1,%2,%3}, {%4,%5,%6,%7}, {%8,%9}, {%0,%1,%2,%3};" \
        : "+f"((d)[0]), "+f"((d)[1]), "+f"((d)[2]), "+f"((d)[3]) \
        : "r"((a)[0]), "r"((a)[1]), "r"((a)[2]), "r"((a)[3]), "r"(b0), "r"(b1))

__device__ __forceinline__ void split_pair(float x, float y, uint32_t& hi, uint32_t& lo) {
    __half hx = __float2half_rn(x), hy = __float2half_rn(y);
    __half2 h2 = __halves2half2(hx, hy);
    hi = *(uint32_t*)&h2;
    __half2 l2 = __floats2half2_rn(x - __half2float(hx), y - __half2float(hy));
    lo = *(uint32_t*)&l2;
}

// SMEM: per buf 4 matrices (Ahi, Alo, Bhi, Blo), each 128 rows x 24 halves (48B)
#define MATB   6144u
#define BUFB   (4u * MATB)
#define SMEM_TOTAL (2 * BUFB)   // 49152

// ======================= HMMA GEMM NT (fp16 split operands) =======================
// C[M,N] = A[M,K] @ Bm[N,K]^T, A/B given as hi/lo fp16 matrices.
// NPASS=3: AhBh + AhBl + AlBh ; NPASS=2: AhBh + AhBl (A_lo unused)
// MODE 0: z-epilogue: +bias, write zh/zl (fp16) + atomicAdd zsq
// MODE 1: dist epilogue -> fp32 scores ; MODE 2: plain fp32
template <int MODE, int NPASS>
__global__ __launch_bounds__(256, 2) void hmma_gemm(
    const __half* __restrict__ Ah, const __half* __restrict__ Al,
    const __half* __restrict__ Bh, const __half* __restrict__ Bl,
    float* __restrict__ C, const float* __restrict__ bias,
    float* __restrict__ zsq, __half* __restrict__ zh, __half* __restrict__ zl,
    const float* __restrict__ psq, const float* __restrict__ temp_raw,
    int K, int ldc) {
    extern __shared__ __align__(128) char smem[];
    const uint32_t sb = smem_u32(smem);
    const int tid = threadIdx.x;
    const int wid = tid >> 5, lane = tid & 31;
    const size_t bm = (size_t)blockIdx.y * 128;
    const size_t bn = (size_t)blockIdx.x * 128;
    const int warp_m = (wid >> 1) * 32;
    const int warp_n = (wid & 1) * 64;

    float acc[2][8][4];
#pragma unroll
    for (int i = 0; i < 2; i++)
#pragma unroll
        for (int j = 0; j < 8; j++)
#pragma unroll
            for (int k = 0; k < 4; k++) acc[i][j][k] = 0.0f;

    const __half* Ahg = Ah + bm * K;
    const __half* Alg = Al + bm * K;
    const __half* Bhg = Bh + bn * K;
    const __half* Blg = Bl + bn * K;
    const int NC = K >> 4;

    // fill mapping: each thread does one 16B segment per matrix per chunk
    const int f_r = tid >> 1;            // row 0..127
    const int f_s = (tid & 1) << 3;      // half-offset 0 or 8
    const uint32_t soff = (uint32_t)(f_r * 48 + (tid & 1) * 16);

    // ---- prologue: chunk 0 -> buf 0 ----
    {
        uint4 va = *(const uint4*)(Ahg + (size_t)f_r * K + f_s);
        *(uint4*)(smem + soff) = va;
        if (NPASS == 3) {
            uint4 vl = *(const uint4*)(Alg + (size_t)f_r * K + f_s);
            *(uint4*)(smem + MATB + soff) = vl;
        }
        uint4 vbh = *(const uint4*)(Bhg + (size_t)f_r * K + f_s);
        *(uint4*)(smem + 2 * MATB + soff) = vbh;
        uint4 vbl = *(const uint4*)(Blg + (size_t)f_r * K + f_s);
        *(uint4*)(smem + 3 * MATB + soff) = vbl;
    }
    __syncthreads();

    // ldmatrix lane address components
    const int a_row = lane & 15;
    const int a_kb = ((lane >> 4) << 3) * 2;
    const int b_n = ((lane >> 4) << 3) + (lane & 7);
    const int b_kb = (lane & 8) * 2;

    uint4 pah, pal, pbh, pbl;
    for (int c = 0; c < NC; ++c) {
        const int buf = c & 1;
        const uint32_t base = sb + buf * BUFB;

        if (c + 1 < NC) {
            const int k0 = (c + 1) << 4;
            pah = *(const uint4*)(Ahg + (size_t)f_r * K + k0 + f_s);
            if (NPASS == 3) pal = *(const uint4*)(Alg + (size_t)f_r * K + k0 + f_s);
            pbh = *(const uint4*)(Bhg + (size_t)f_r * K + k0 + f_s);
            pbl = *(const uint4*)(Blg + (size_t)f_r * K + k0 + f_s);
        }

        uint32_t ah[2][4], al[2][4];
#pragma unroll
        for (int i = 0; i < 2; i++) {
            uint32_t ra = base + (uint32_t)((warp_m + i * 16 + a_row) * 48) + a_kb;
            LDSM4(ah[i], ra);
            if (NPASS == 3) LDSM4(al[i], ra + MATB);
        }
#pragma unroll
        for (int jp = 0; jp < 4; jp++) {
            uint32_t rb = base + 2 * MATB +
                          (uint32_t)((warp_n + jp * 16 + b_n) * 48) + b_kb;
            uint32_t bh[4], bl[4];
            LDSM4(bh, rb);
            LDSM4(bl, rb + MATB);
#pragma unroll
            for (int i = 0; i < 2; i++) {
                MMA16816(acc[i][jp * 2 + 0], ah[i], bh[0], bh[1]);
                MMA16816(acc[i][jp * 2 + 0], ah[i], bl[0], bl[1]);
                if (NPASS == 3) MMA16816(acc[i][jp * 2 + 0], al[i], bh[0], bh[1]);
                MMA16816(acc[i][jp * 2 + 1], ah[i], bh[2], bh[3]);
                MMA16816(acc[i][jp * 2 + 1], ah[i], bl[2], bl[3]);
                if (NPASS == 3) MMA16816(acc[i][jp * 2 + 1], al[i], bh[2], bh[3]);
            }
        }

        if (c + 1 < NC) {
            const uint32_t nb = (buf ^ 1) * BUFB;
            *(uint4*)(smem + nb + soff) = pah;
            if (NPASS == 3) *(uint4*)(smem + nb + MATB + soff) = pal;
            *(uint4*)(smem + nb + 2 * MATB + soff) = pbh;
            *(uint4*)(smem + nb + 3 * MATB + soff) = pbl;
        }
        __syncthreads();
    }

    // ---- epilogue ----
    float invt = 0.0f;
    if (MODE == 1) {
        float t = temp_raw[0];
        float temp = 1.0f / (1.0f + expf(-t)) * 0.999f + 0.001f;
        invt = 1.0f / temp;
    }
    const int rbase = warp_m + (lane >> 2);
    const int cbase = warp_n + (lane & 3) * 2;
#pragma unroll
    for (int i = 0; i < 2; i++) {
#pragma unroll
        for (int h = 0; h < 2; h++) {
            const size_t row = bm + rbase + i * 16 + h * 8;
            if (MODE == 0) {
                float s = 0.0f;
#pragma unroll
                for (int j = 0; j < 8; j++) {
                    const int cg = cbase + j * 8;
                    float v0 = acc[i][j][h * 2 + 0] + bias[bn + cg];
                    float v1 = acc[i][j][h * 2 + 1] + bias[bn + cg + 1];
                    s += v0 * v0 + v1 * v1;
                    __half h0 = __float2half_rn(v0), h1 = __float2half_rn(v1);
                    __half2 hh = __halves2half2(h0, h1);
                    __half2 ll = __floats2half2_rn(v0 - __half2float(h0),
                                                   v1 - __half2float(h1));
                    *(__half2*)(zh + row * (size_t)ldc + bn + cg) = hh;
                    *(__half2*)(zl + row * (size_t)ldc + bn + cg) = ll;
                }
                s += __shfl_xor_sync(0xffffffffu, s, 1);
                s += __shfl_xor_sync(0xffffffffu, s, 2);
                if ((lane & 3) == 0) atomicAdd(zsq + row, s);
            } else {
                float zr = (MODE == 1) ? zsq[row] : 0.0f;
                float* crow = C + row * (size_t)ldc + bn;
#pragma unroll
                for (int j = 0; j < 8; j++) {
                    const int cg = cbase + j * 8;
                    float v0 = acc[i][j][h * 2 + 0];
                    float v1 = acc[i][j][h * 2 + 1];
                    if (MODE == 1) {
                        float d0 = fmaxf(zr + psq[bn + cg] - 2.0f * v0, 1e-12f);
                        float d1 = fmaxf(zr + psq[bn + cg + 1] - 2.0f * v1, 1e-12f);
                        v0 = -sqrtf(d0) * invt;
                        v1 = -sqrtf(d1) * invt;
                    }
                    *(float2*)(crow + cg) = make_float2(v0, v1);
                }
            }
        }
    }
}

// ======================= small kernels =======================
__device__ __forceinline__ float wsum(float v) {
#pragma unroll
    for (int o = 16; o; o >>= 1) v += __shfl_xor_sync(0xffffffffu, v, o);
    return v;
}
__device__ __forceinline__ float wmax(float v) {
#pragma unroll
    for (int o = 16; o; o >>= 1) v = fmaxf(v, __shfl_xor_sync(0xffffffffu, v, o));
    return v;
}

__global__ __launch_bounds__(128) void row_sumsq_512(const float* __restrict__ X,
                                                     float* __restrict__ out) {
    size_t row = blockIdx.x;
    const float4* p = (const float4*)(X + row * 512);
    float4 v = p[threadIdx.x];
    float s = v.x * v.x + v.y * v.y + v.z * v.z + v.w * v.w;
    s = wsum(s);
    __shared__ float red[4];
    if ((threadIdx.x & 31) == 0) red[threadIdx.x >> 5] = s;
    __syncthreads();
    if (threadIdx.x == 0) out[row] = red[0] + red[1] + red[2] + red[3];
}

// softmax over rows of 1024; writes fp32 weights AND fp16 hi/lo copies
__global__ __launch_bounds__(256) void softmax_1024(float* __restrict__ Wt,
                                                    __half* __restrict__ wh,
                                                    __half* __restrict__ wl) {
    size_t row = blockIdx.x;
    float4* p = (float4*)(Wt + row * 1024);
    float4 v = p[threadIdx.x];

    __shared__ float red[8];
    float m = fmaxf(fmaxf(v.x, v.y), fmaxf(v.z, v.w));
    m = wmax(m);
    if ((threadIdx.x & 31) == 0) red[threadIdx.x >> 5] = m;
    __syncthreads();
    if (threadIdx.x < 32) {
        float t = (threadIdx.x < 8) ? red[threadIdx.x] : -INFINITY;
        t = wmax(t);
        if (threadIdx.x == 0) red[0] = t;
    }
    __syncthreads();
    m = red[0];
    __syncthreads();

    v.x = expf(v.x - m); v.y = expf(v.y - m);
    v.z = expf(v.z - m); v.w = expf(v.w - m);
    float s = v.x + v.y + v.z + v.w;
    s = wsum(s);
    __shared__ float red2[8];
    if ((threadIdx.x & 31) == 0) red2[threadIdx.x >> 5] = s;
    __syncthreads();
    if (threadIdx.x < 32) {
        float t = (threadIdx.x < 8) ? red2[threadIdx.x] : 0.0f;
        t = wsum(t);
        if (threadIdx.x == 0) red2[0] = t;
    }
    __syncthreads();
    float inv = 1.0f / red2[0];
    v.x *= inv; v.y *= inv; v.z *= inv; v.w *= inv;
    p[threadIdx.x] = v;

    uint32_t h0, l0, h1, l1;
    split_pair(v.x, v.y, h0, l0);
    split_pair(v.z, v.w, h1, l1);
    size_t off = row * 1024 + threadIdx.x * 4;
    *(uint2*)(wh + off) = make_uint2(h0, h1);
    *(uint2*)(wl + off) = make_uint2(l0, l1);
}

// split fp32 array into fp16 hi/lo
__global__ __launch_bounds__(256) void split_mat(const float4* __restrict__ src,
                                                 uint2* __restrict__ hi,
                                                 uint2* __restrict__ lo, int n4) {
    int i = blockIdx.x * 256 + threadIdx.x;
    if (i >= n4) return;
    float4 v = src[i];
    uint32_t h0, l0, h1, l1;
    split_pair(v.x, v.y, h0, l0);
    split_pair(v.z, v.w, h1, l1);
    hi[i] = make_uint2(h0, h1);
    lo[i] = make_uint2(l0, l1);
}

// transpose P [1024,512] -> PT hi/lo [512,1024] fp16
__global__ __launch_bounds__(256) void transpose_split_P(const float* __restrict__ P,
                                                         __half* __restrict__ pth,
                                                         __half* __restrict__ ptl) {
    __shared__ float t[32][33];
    int bx = blockIdx.x * 32;
    int by = blockIdx.y * 32;
    int tx = threadIdx.x & 31, ty = (threadIdx.x >> 5) * 4;
#pragma unroll
    for (int i = 0; i < 4; i++)
        t[ty + i][tx] = P[(size_t)(by + ty + i) * 512 + bx + tx];
    __syncthreads();
#pragma unroll
    for (int i = 0; i < 4; i++) {
        float v = t[tx][ty + i];
        __half hv = __float2half_rn(v);
        size_t off = (size_t)(bx + ty + i) * 1024 + by + tx;
        pth[off] = hv;
        ptl[off] = __float2half_rn(v - __half2float(hv));
    }
}

extern "C" void kernel_launch(void* const* d_in, const int* in_sizes, int n_in,
                              void* d_out, int out_size) {
    const float* x  = (const float*)d_in[0];
    const float* W  = (const float*)d_in[1];
    const float* b  = (const float*)d_in[2];
    const float* P  = (const float*)d_in[3];
    const float* tr = (const float*)d_in[4];

    float* blended = (float*)d_out;
    float* weights = (float*)d_out + (size_t)BATCH * DIM;

    __half *xh, *xl, *zh, *zl, *Wh, *Wl, *Ph, *Pl, *PTh, *PTl, *wgh, *wgl;
    float *zsq, *psq;
    cudaGetSymbolAddress((void**)&xh, g_xh);   cudaGetSymbolAddress((void**)&xl, g_xl);
    cudaGetSymbolAddress((void**)&zh, g_zh);   cudaGetSymbolAddress((void**)&zl, g_zl);
    cudaGetSymbolAddress((void**)&Wh, g_Wh);   cudaGetSymbolAddress((void**)&Wl, g_Wl);
    cudaGetSymbolAddress((void**)&Ph, g_Ph);   cudaGetSymbolAddress((void**)&Pl, g_Pl);
    cudaGetSymbolAddress((void**)&PTh, g_PTh); cudaGetSymbolAddress((void**)&PTl, g_PTl);
    cudaGetSymbolAddress((void**)&wgh, g_wgh); cudaGetSymbolAddress((void**)&wgl, g_wgl);
    cudaGetSymbolAddress((void**)&zsq, g_zsq); cudaGetSymbolAddress((void**)&psq, g_psq);

    cudaFuncSetAttribute(hmma_gemm<0, 3>, cudaFuncAttributeMaxDynamicSharedMemorySize, SMEM_TOTAL);
    cudaFuncSetAttribute(hmma_gemm<1, 3>, cudaFuncAttributeMaxDynamicSharedMemorySize, SMEM_TOTAL);
    cudaFuncSetAttribute(hmma_gemm<2, 2>, cudaFuncAttributeMaxDynamicSharedMemorySize, SMEM_TOTAL);

    cudaMemsetAsync(zsq, 0, BATCH * sizeof(float));
    row_sumsq_512<<<NPROTO, 128>>>(P, psq);

    // pre-split inputs
    split_mat<<<(BATCH * DIM / 4 + 255) / 256, 256>>>((const float4*)x, (uint2*)xh, (uint2*)xl, BATCH * DIM / 4);
    split_mat<<<(DIM * DIM / 4 + 255) / 256, 256>>>((const float4*)W, (uint2*)Wh, (uint2*)Wl, DIM * DIM / 4);
    split_mat<<<(NPROTO * DIM / 4 + 255) / 256, 256>>>((const float4*)P, (uint2*)Ph, (uint2*)Pl, NPROTO * DIM / 4);
    transpose_split_P<<<dim3(16, 32), 256>>>(P, PTh, PTl);

    // 1) z = x@W^T + b  -> zh/zl + zsq
    hmma_gemm<0, 3><<<dim3(DIM / 128, BATCH / 128), 256, SMEM_TOTAL>>>(
        xh, xl, Wh, Wl, nullptr, b, zsq, zh, zl, nullptr, nullptr, DIM, DIM);

    // 2) scores -> weights region (fp32)
    hmma_gemm<1, 3><<<dim3(NPROTO / 128, BATCH / 128), 256, SMEM_TOTAL>>>(
        zh, zl, Ph, Pl, weights, nullptr, zsq, nullptr, nullptr, psq, tr, DIM, NPROTO);

    // 3) softmax -> weights fp32 + wgh/wgl fp16
    softmax_1024<<<BATCH, 256>>>(weights, wgh, wgl);

    // 4) blended = weights @ P (2-pass split)
    hmma_gemm<2, 2><<<dim3(DIM / 128, BATCH / 128), 256, SMEM_TOTAL>>>(
        wgh, wgl, PTh, PTl, blended, nullptr, nullptr, nullptr, nullptr, nullptr, nullptr, NPROTO, DIM);
}

// round 6
// speedup vs baseline: 2.3844x; 1.0095x over previous
#include <cuda_runtime.h>
#include <cuda_fp16.h>
#include <math.h>
#include <stdint.h>

#define BATCH  65536
#define DIM    512
#define NPROTO 1024

// ---------------- device scratch ----------------
__device__ __half g_zh[(size_t)BATCH * DIM],  g_zl[(size_t)BATCH * DIM];
__device__ __half g_Wh[(size_t)DIM * DIM],    g_Wl[(size_t)DIM * DIM];
__device__ __half g_Ph[(size_t)NPROTO * DIM], g_Pl[(size_t)NPROTO * DIM];
__device__ __half g_PTh[(size_t)DIM * NPROTO], g_PTl[(size_t)DIM * NPROTO];
__device__ float g_zsq[BATCH];
__device__ float g_psq[NPROTO];

// ======================= helpers =======================
__device__ __forceinline__ uint32_t smem_u32(const void* p) {
    uint32_t a;
    asm("{ .reg .u64 t; cvta.to.shared.u64 t, %1; cvt.u32.u64 %0, t; }" : "=r"(a) : "l"(p));
    return a;
}

#define LDSM4(r, addr) \
    asm volatile("ldmatrix.sync.aligned.m8n8.x4.shared.b16 {%0,%1,%2,%3}, [%4];" \
        : "=r"((r)[0]), "=r"((r)[1]), "=r"((r)[2]), "=r"((r)[3]) : "r"(addr))

#define MMA16816(d, a, b0, b1) \
    asm volatile("mma.sync.aligned.m16n8k16.row.col.f32.f16.f16.f32 " \
        "{%0,%1,%2,%3}, {%4,%5,%6,%7}, {%8,%9}, {%0,%1,%2,%3};" \
        : "+f"((d)[0]), "+f"((d)[1]), "+f"((d)[2]), "+f"((d)[3]) \
        : "r"((a)[0]), "r"((a)[1]), "r"((a)[2]), "r"((a)[3]), "r"(b0), "r"(b1))

__device__ __forceinline__ void split_pair(float x, float y, uint32_t& hi, uint32_t& lo) {
    __half hx = __float2half_rn(x), hy = __float2half_rn(y);
    __half2 h2 = __halves2half2(hx, hy);
    hi = *(uint32_t*)&h2;
    __half2 l2 = __floats2half2_rn(x - __half2float(hx), y - __half2float(hy));
    lo = *(uint32_t*)&l2;
}
// 8 floats -> hi uint4 (fp16x8) and lo uint4
__device__ __forceinline__ void cvt8(const float4& a, const float4& b,
                                     uint4& hi, uint4& lo) {
    split_pair(a.x, a.y, hi.x, lo.x);
    split_pair(a.z, a.w, hi.y, lo.y);
    split_pair(b.x, b.y, hi.z, lo.z);
    split_pair(b.z, b.w, hi.w, lo.w);
}
// 8 floats -> hi only
__device__ __forceinline__ uint4 cvt8hi(const float4& a, const float4& b) {
    __half2 h0 = __floats2half2_rn(a.x, a.y);
    __half2 h1 = __floats2half2_rn(a.z, a.w);
    __half2 h2 = __floats2half2_rn(b.x, b.y);
    __half2 h3 = __floats2half2_rn(b.z, b.w);
    return make_uint4(*(uint32_t*)&h0, *(uint32_t*)&h1, *(uint32_t*)&h2, *(uint32_t*)&h3);
}

// fast exp on FMA pipe (args in [-10, 0] here; poly rel err ~1e-7)
__device__ __forceinline__ float fexp(float x) {
    float y = x * 1.4426950408889634f;
    float t = y + 12582912.0f;            // round to nearest int (2^23*1.5 trick)
    float n = t - 12582912.0f;
    float f = y - n;
    float p = 1.3333558146e-3f;
    p = fmaf(p, f, 9.6181291076e-3f);
    p = fmaf(p, f, 5.5504108664e-2f);
    p = fmaf(p, f, 2.4022650696e-1f);
    p = fmaf(p, f, 6.9314718056e-1f);
    p = fmaf(p, f, 1.0f);
    return __int_as_float(__float_as_int(p) + (((int)n) << 23));
}

// SMEM: per buf 4 matrices (Ahi, Alo, Bhi, Blo), each 128 rows x 24 halves (48B)
#define MATB   6144u
#define BUFB   (4u * MATB)
#define SMEM_TOTAL (2 * BUFB)   // 49152

// ======================= HMMA GEMM NT =======================
// C[M,N] = A[M,K] @ Bm[N,K]^T.
// ASRC 0: A pre-split fp16 (Aptr=hi, Al=lo). ASRC 1: A fp32, split in fill.
// NPASS 3: AhBh+AhBl+AlBh ; NPASS 2: AhBh+AhBl (A lo unused)
// MODE 0: +bias, write zh/zl fp16 + atomicAdd zsq ; MODE 1: dist ; MODE 2: plain
template <int MODE, int NPASS, int ASRC>
__global__ __launch_bounds__(256, 2) void hmma_gemm(
    const void* __restrict__ Aptr, const __half* __restrict__ Al,
    const __half* __restrict__ Bh, const __half* __restrict__ Bl,
    float* __restrict__ C, const float* __restrict__ bias,
    float* __restrict__ zsq, __half* __restrict__ zh, __half* __restrict__ zl,
    const float* __restrict__ psq, const float* __restrict__ temp_raw,
    int K, int ldc) {
    extern __shared__ __align__(128) char smem[];
    const uint32_t sb = smem_u32(smem);
    const int tid = threadIdx.x;
    const int wid = tid >> 5, lane = tid & 31;
    const size_t bm = (size_t)blockIdx.y * 128;
    const size_t bn = (size_t)blockIdx.x * 128;
    const int warp_m = (wid >> 1) * 32;
    const int warp_n = (wid & 1) * 64;

    float acc[2][8][4];
#pragma unroll
    for (int i = 0; i < 2; i++)
#pragma unroll
        for (int j = 0; j < 8; j++)
#pragma unroll
            for (int k = 0; k < 4; k++) acc[i][j][k] = 0.0f;

    const __half* Ahg = (ASRC == 0) ? ((const __half*)Aptr) + bm * K : nullptr;
    const __half* Alg = (ASRC == 0) ? Al + bm * K : nullptr;
    const float*  Afg = (ASRC == 1) ? ((const float*)Aptr) + bm * K : nullptr;
    const __half* Bhg = Bh + bn * K;
    const __half* Blg = Bl + bn * K;
    const int NC = K >> 4;

    // fill mapping: row = tid>>1, 8-element segment = (tid&1)*8
    const int f_r = tid >> 1;
    const int f_s = (tid & 1) << 3;
    const uint32_t soff = (uint32_t)(f_r * 48 + (tid & 1) * 16);

    // ---- prologue: chunk 0 -> buf 0 ----
    {
        if (ASRC == 0) {
            *(uint4*)(smem + soff) = *(const uint4*)(Ahg + (size_t)f_r * K + f_s);
            if (NPASS == 3)
                *(uint4*)(smem + MATB + soff) = *(const uint4*)(Alg + (size_t)f_r * K + f_s);
        } else {
            float4 a0 = *(const float4*)(Afg + (size_t)f_r * K + f_s);
            float4 a1 = *(const float4*)(Afg + (size_t)f_r * K + f_s + 4);
            if (NPASS == 3) {
                uint4 hi, lo;
                cvt8(a0, a1, hi, lo);
                *(uint4*)(smem + soff) = hi;
                *(uint4*)(smem + MATB + soff) = lo;
            } else {
                *(uint4*)(smem + soff) = cvt8hi(a0, a1);
            }
        }
        *(uint4*)(smem + 2 * MATB + soff) = *(const uint4*)(Bhg + (size_t)f_r * K + f_s);
        *(uint4*)(smem + 3 * MATB + soff) = *(const uint4*)(Blg + (size_t)f_r * K + f_s);
    }
    __syncthreads();

    const int a_row = lane & 15;
    const int a_kb = ((lane >> 4) << 3) * 2;
    const int b_n = ((lane >> 4) << 3) + (lane & 7);
    const int b_kb = (lane & 8) * 2;

    uint4 pah, pal, pbh, pbl;
    float4 pfa0, pfa1;
    for (int c = 0; c < NC; ++c) {
        const int buf = c & 1;
        const uint32_t base = sb + buf * BUFB;

        if (c + 1 < NC) {
            const int k0 = (c + 1) << 4;
            if (ASRC == 0) {
                pah = *(const uint4*)(Ahg + (size_t)f_r * K + k0 + f_s);
                if (NPASS == 3) pal = *(const uint4*)(Alg + (size_t)f_r * K + k0 + f_s);
            } else {
                pfa0 = *(const float4*)(Afg + (size_t)f_r * K + k0 + f_s);
                pfa1 = *(const float4*)(Afg + (size_t)f_r * K + k0 + f_s + 4);
            }
            pbh = *(const uint4*)(Bhg + (size_t)f_r * K + k0 + f_s);
            pbl = *(const uint4*)(Blg + (size_t)f_r * K + k0 + f_s);
        }

        uint32_t ah[2][4], al[2][4];
#pragma unroll
        for (int i = 0; i < 2; i++) {
            uint32_t ra = base + (uint32_t)((warp_m + i * 16 + a_row) * 48) + a_kb;
            LDSM4(ah[i], ra);
            if (NPASS == 3) LDSM4(al[i], ra + MATB);
        }
#pragma unroll
        for (int jp = 0; jp < 4; jp++) {
            uint32_t rb = base + 2 * MATB +
                          (uint32_t)((warp_n + jp * 16 + b_n) * 48) + b_kb;
            uint32_t bh[4], bl[4];
            LDSM4(bh, rb);
            LDSM4(bl, rb + MATB);
#pragma unroll
            for (int i = 0; i < 2; i++) {
                MMA16816(acc[i][jp * 2 + 0], ah[i], bh[0], bh[1]);
                MMA16816(acc[i][jp * 2 + 0], ah[i], bl[0], bl[1]);
                if (NPASS == 3) MMA16816(acc[i][jp * 2 + 0], al[i], bh[0], bh[1]);
                MMA16816(acc[i][jp * 2 + 1], ah[i], bh[2], bh[3]);
                MMA16816(acc[i][jp * 2 + 1], ah[i], bl[2], bl[3]);
                if (NPASS == 3) MMA16816(acc[i][jp * 2 + 1], al[i], bh[2], bh[3]);
            }
        }

        if (c + 1 < NC) {
            const uint32_t nb = (buf ^ 1) * BUFB;
            if (ASRC == 0) {
                *(uint4*)(smem + nb + soff) = pah;
                if (NPASS == 3) *(uint4*)(smem + nb + MATB + soff) = pal;
            } else {
                if (NPASS == 3) {
                    uint4 hi, lo;
                    cvt8(pfa0, pfa1, hi, lo);
                    *(uint4*)(smem + nb + soff) = hi;
                    *(uint4*)(smem + nb + MATB + soff) = lo;
                } else {
                    *(uint4*)(smem + nb + soff) = cvt8hi(pfa0, pfa1);
                }
            }
            *(uint4*)(smem + nb + 2 * MATB + soff) = pbh;
            *(uint4*)(smem + nb + 3 * MATB + soff) = pbl;
        }
        __syncthreads();
    }

    // ---- epilogue ----
    float invt = 0.0f;
    if (MODE == 1) {
        float t = temp_raw[0];
        float temp = 1.0f / (1.0f + expf(-t)) * 0.999f + 0.001f;
        invt = 1.0f / temp;
    }
    const int rbase = warp_m + (lane >> 2);
    const int cbase = warp_n + (lane & 3) * 2;
#pragma unroll
    for (int i = 0; i < 2; i++) {
#pragma unroll
        for (int h = 0; h < 2; h++) {
            const size_t row = bm + rbase + i * 16 + h * 8;
            if (MODE == 0) {
                float s = 0.0f;
#pragma unroll
                for (int j = 0; j < 8; j++) {
                    const int cg = cbase + j * 8;
                    float v0 = acc[i][j][h * 2 + 0] + bias[bn + cg];
                    float v1 = acc[i][j][h * 2 + 1] + bias[bn + cg + 1];
                    s += v0 * v0 + v1 * v1;
                    __half h0 = __float2half_rn(v0), h1 = __float2half_rn(v1);
                    __half2 hh = __halves2half2(h0, h1);
                    __half2 ll = __floats2half2_rn(v0 - __half2float(h0),
                                                   v1 - __half2float(h1));
                    *(__half2*)(zh + row * (size_t)ldc + bn + cg) = hh;
                    *(__half2*)(zl + row * (size_t)ldc + bn + cg) = ll;
                }
                s += __shfl_xor_sync(0xffffffffu, s, 1);
                s += __shfl_xor_sync(0xffffffffu, s, 2);
                if ((lane & 3) == 0) atomicAdd(zsq + row, s);
            } else {
                float zr = (MODE == 1) ? zsq[row] : 0.0f;
                float* crow = C + row * (size_t)ldc + bn;
#pragma unroll
                for (int j = 0; j < 8; j++) {
                    const int cg = cbase + j * 8;
                    float v0 = acc[i][j][h * 2 + 0];
                    float v1 = acc[i][j][h * 2 + 1];
                    if (MODE == 1) {
                        float d0 = fmaxf(zr + psq[bn + cg] - 2.0f * v0, 1e-12f);
                        float d1 = fmaxf(zr + psq[bn + cg + 1] - 2.0f * v1, 1e-12f);
                        v0 = -sqrtf(d0) * invt;
                        v1 = -sqrtf(d1) * invt;
                    }
                    *(float2*)(crow + cg) = make_float2(v0, v1);
                }
            }
        }
    }
}

// ======================= small kernels =======================
__device__ __forceinline__ float wsum(float v) {
#pragma unroll
    for (int o = 16; o; o >>= 1) v += __shfl_xor_sync(0xffffffffu, v, o);
    return v;
}
__device__ __forceinline__ float wmax(float v) {
#pragma unroll
    for (int o = 16; o; o >>= 1) v = fmaxf(v, __shfl_xor_sync(0xffffffffu, v, o));
    return v;
}

__global__ __launch_bounds__(128) void row_sumsq_512(const float* __restrict__ X,
                                                     float* __restrict__ out) {
    size_t row = blockIdx.x;
    const float4* p = (const float4*)(X + row * 512);
    float4 v = p[threadIdx.x];
    float s = v.x * v.x + v.y * v.y + v.z * v.z + v.w * v.w;
    s = wsum(s);
    __shared__ float red[4];
    if ((threadIdx.x & 31) == 0) red[threadIdx.x >> 5] = s;
    __syncthreads();
    if (threadIdx.x == 0) out[row] = red[0] + red[1] + red[2] + red[3];
}

// in-place softmax over rows of 1024, FFMA-pipe exp
__global__ __launch_bounds__(256) void softmax_1024(float* __restrict__ Wt) {
    size_t row = blockIdx.x;
    float4* p = (float4*)(Wt + row * 1024);
    float4 v = p[threadIdx.x];

    __shared__ float red[8];
    float m = fmaxf(fmaxf(v.x, v.y), fmaxf(v.z, v.w));
    m = wmax(m);
    if ((threadIdx.x & 31) == 0) red[threadIdx.x >> 5] = m;
    __syncthreads();
    if (threadIdx.x < 32) {
        float t = (threadIdx.x < 8) ? red[threadIdx.x] : -INFINITY;
        t = wmax(t);
        if (threadIdx.x == 0) red[0] = t;
    }
    __syncthreads();
    m = red[0];
    __syncthreads();

    v.x = fexp(v.x - m); v.y = fexp(v.y - m);
    v.z = fexp(v.z - m); v.w = fexp(v.w - m);
    float s = v.x + v.y + v.z + v.w;
    s = wsum(s);
    __shared__ float red2[8];
    if ((threadIdx.x & 31) == 0) red2[threadIdx.x >> 5] = s;
    __syncthreads();
    if (threadIdx.x < 32) {
        float t = (threadIdx.x < 8) ? red2[threadIdx.x] : 0.0f;
        t = wsum(t);
        if (threadIdx.x == 0) red2[0] = t;
    }
    __syncthreads();
    float inv = 1.0f / red2[0];
    v.x *= inv; v.y *= inv; v.z *= inv; v.w *= inv;
    p[threadIdx.x] = v;
}

// split fp32 array into fp16 hi/lo
__global__ __launch_bounds__(256) void split_mat(const float4* __restrict__ src,
                                                 uint2* __restrict__ hi,
                                                 uint2* __restrict__ lo, int n4) {
    int i = blockIdx.x * 256 + threadIdx.x;
    if (i >= n4) return;
    float4 v = src[i];
    uint32_t h0, l0, h1, l1;
    split_pair(v.x, v.y, h0, l0);
    split_pair(v.z, v.w, h1, l1);
    hi[i] = make_uint2(h0, h1);
    lo[i] = make_uint2(l0, l1);
}

// transpose P [1024,512] -> PT hi/lo [512,1024] fp16
__global__ __launch_bounds__(256) void transpose_split_P(const float* __restrict__ P,
                                                         __half* __restrict__ pth,
                                                         __half* __restrict__ ptl) {
    __shared__ float t[32][33];
    int bx = blockIdx.x * 32;
    int by = blockIdx.y * 32;
    int tx = threadIdx.x & 31, ty = (threadIdx.x >> 5) * 4;
#pragma unroll
    for (int i = 0; i < 4; i++)
        t[ty + i][tx] = P[(size_t)(by + ty + i) * 512 + bx + tx];
    __syncthreads();
#pragma unroll
    for (int i = 0; i < 4; i++) {
        float v = t[tx][ty + i];
        __half hv = __float2half_rn(v);
        size_t off = (size_t)(bx + ty + i) * 1024 + by + tx;
        pth[off] = hv;
        ptl[off] = __float2half_rn(v - __half2float(hv));
    }
}

extern "C" void kernel_launch(void* const* d_in, const int* in_sizes, int n_in,
                              void* d_out, int out_size) {
    const float* x  = (const float*)d_in[0];
    const float* W  = (const float*)d_in[1];
    const float* b  = (const float*)d_in[2];
    const float* P  = (const float*)d_in[3];
    const float* tr = (const float*)d_in[4];

    float* blended = (float*)d_out;
    float* weights = (float*)d_out + (size_t)BATCH * DIM;

    __half *zh, *zl, *Wh, *Wl, *Ph, *Pl, *PTh, *PTl;
    float *zsq, *psq;
    cudaGetSymbolAddress((void**)&zh, g_zh);   cudaGetSymbolAddress((void**)&zl, g_zl);
    cudaGetSymbolAddress((void**)&Wh, g_Wh);   cudaGetSymbolAddress((void**)&Wl, g_Wl);
    cudaGetSymbolAddress((void**)&Ph, g_Ph);   cudaGetSymbolAddress((void**)&Pl, g_Pl);
    cudaGetSymbolAddress((void**)&PTh, g_PTh); cudaGetSymbolAddress((void**)&PTl, g_PTl);
    cudaGetSymbolAddress((void**)&zsq, g_zsq); cudaGetSymbolAddress((void**)&psq, g_psq);

    cudaFuncSetAttribute((const void*)hmma_gemm<0, 3, 1>, cudaFuncAttributeMaxDynamicSharedMemorySize, SMEM_TOTAL);
    cudaFuncSetAttribute((const void*)hmma_gemm<1, 3, 0>, cudaFuncAttributeMaxDynamicSharedMemorySize, SMEM_TOTAL);
    cudaFuncSetAttribute((const void*)hmma_gemm<2, 2, 1>, cudaFuncAttributeMaxDynamicSharedMemorySize, SMEM_TOTAL);

    cudaMemsetAsync(zsq, 0, BATCH * sizeof(float));
    row_sumsq_512<<<NPROTO, 128>>>(P, psq);

    // pre-split small matrices
    split_mat<<<(DIM * DIM / 4 + 255) / 256, 256>>>((const float4*)W, (uint2*)Wh, (uint2*)Wl, DIM * DIM / 4);
    split_mat<<<(NPROTO * DIM / 4 + 255) / 256, 256>>>((const float4*)P, (uint2*)Ph, (uint2*)Pl, NPROTO * DIM / 4);
    transpose_split_P<<<dim3(16, 32), 256>>>(P, PTh, PTl);

    // 1) z = x@W^T + b  -> zh/zl + zsq  (x split on the fly)
    hmma_gemm<0, 3, 1><<<dim3(DIM / 128, BATCH / 128), 256, SMEM_TOTAL>>>(
        x, nullptr, Wh, Wl, nullptr, b, zsq, zh, zl, nullptr, nullptr, DIM, DIM);

    // 2) scores -> weights region (fp32)
    hmma_gemm<1, 3, 0><<<dim3(NPROTO / 128, BATCH / 128), 256, SMEM_TOTAL>>>(
        zh, zl, Ph, Pl, weights, nullptr, zsq, nullptr, nullptr, psq, tr, DIM, NPROTO);

    // 3) softmax in-place (fp32)
    softmax_1024<<<BATCH, 256>>>(weights);

    // 4) blended = weights @ P (2-pass, weights split on the fly)
    hmma_gemm<2, 2, 1><<<dim3(DIM / 128, BATCH / 128), 256, SMEM_TOTAL>>>(
        weights, nullptr, PTh, PTl, blended, nullptr, nullptr, nullptr, nullptr, nullptr, nullptr, NPROTO, DIM);
}

// round 8
// speedup vs baseline: 2.4971x; 1.0473x over previous
#include <cuda_runtime.h>
#include <cuda_fp16.h>
#include <math.h>
#include <stdint.h>

#define BATCH  65536
#define DIM    512
#define NPROTO 1024

// ---------------- device scratch ----------------
__device__ __half g_Wh[(size_t)DIM * DIM],     g_Wl[(size_t)DIM * DIM];
__device__ __half g_WTh[(size_t)DIM * DIM],    g_WTl[(size_t)DIM * DIM];
__device__ __half g_PTh[(size_t)DIM * NPROTO], g_PTl[(size_t)DIM * NPROTO];
__device__ __half g_Qh[(size_t)NPROTO * DIM],  g_Ql[(size_t)NPROTO * DIM];
__device__ float g_zsq[BATCH];
__device__ float g_psq2[NPROTO];   // psq - 2*P.b

// ======================= helpers =======================
__device__ __forceinline__ uint32_t smem_u32(const void* p) {
    uint32_t a;
    asm("{ .reg .u64 t; cvta.to.shared.u64 t, %1; cvt.u32.u64 %0, t; }" : "=r"(a) : "l"(p));
    return a;
}

#define LDSM4(r, addr) \
    asm volatile("ldmatrix.sync.aligned.m8n8.x4.shared.b16 {%0,%1,%2,%3}, [%4];" \
        : "=r"((r)[0]), "=r"((r)[1]), "=r"((r)[2]), "=r"((r)[3]) : "r"(addr))

#define MMA16816(d, a, b0, b1) \
    asm volatile("mma.sync.aligned.m16n8k16.row.col.f32.f16.f16.f32 " \
        "{%0,%1,%2,%3}, {%4,%5,%6,%7}, {%8,%9}, {%0,%1,%2,%3};" \
        : "+f"((d)[0]), "+f"((d)[1]), "+f"((d)[2]), "+f"((d)[3]) \
        : "r"((a)[0]), "r"((a)[1]), "r"((a)[2]), "r"((a)[3]), "r"(b0), "r"(b1))

__device__ __forceinline__ void split_pair(float x, float y, uint32_t& hi, uint32_t& lo) {
    __half hx = __float2half_rn(x), hy = __float2half_rn(y);
    __half2 h2 = __halves2half2(hx, hy);
    hi = *(uint32_t*)&h2;
    __half2 l2 = __floats2half2_rn(x - __half2float(hx), y - __half2float(hy));
    lo = *(uint32_t*)&l2;
}
__device__ __forceinline__ void cvt8(const float4& a, const float4& b,
                                     uint4& hi, uint4& lo) {
    split_pair(a.x, a.y, hi.x, lo.x);
    split_pair(a.z, a.w, hi.y, lo.y);
    split_pair(b.x, b.y, hi.z, lo.z);
    split_pair(b.z, b.w, hi.w, lo.w);
}
__device__ __forceinline__ uint4 cvt8hi(const float4& a, const float4& b) {
    __half2 h0 = __floats2half2_rn(a.x, a.y);
    __half2 h1 = __floats2half2_rn(a.z, a.w);
    __half2 h2 = __floats2half2_rn(b.x, b.y);
    __half2 h3 = __floats2half2_rn(b.z, b.w);
    return make_uint4(*(uint32_t*)&h0, *(uint32_t*)&h1, *(uint32_t*)&h2, *(uint32_t*)&h3);
}

// FFMA-pipe exp (args <= 0 here)
__device__ __forceinline__ float fexp(float x) {
    float y = x * 1.4426950408889634f;
    float t = y + 12582912.0f;
    float n = t - 12582912.0f;
    float f = y - n;
    float p = 1.3333558146e-3f;
    p = fmaf(p, f, 9.6181291076e-3f);
    p = fmaf(p, f, 5.5504108664e-2f);
    p = fmaf(p, f, 2.4022650696e-1f);
    p = fmaf(p, f, 6.9314718056e-1f);
    p = fmaf(p, f, 1.0f);
    return __int_as_float(__float_as_int(p) + (((int)n) << 23));
}

// SMEM: per buf 4 matrices (Ahi, Alo, Bhi, Blo), each 128 rows x 24 halves (48B)
#define MATB   6144u
#define BUFB   (4u * MATB)
#define SMEM_TOTAL (2 * BUFB)   // 49152

// ======================= HMMA GEMM NT =======================
// C[M,N] = A[M,K] @ Bm[N,K]^T.
// ASRC 0: A pre-split fp16 (Aptr=hi, Al=lo). ASRC 1: A fp32, split in fill.
// NPASS 3: AhBh+AhBl+AlBh ; 2: AhBh+AhBl ; 1: AhBh only
// MODE 0: zsq-only: acc+bias, row sum-of-squares via atomicAdd, no C write
// MODE 1: dist epilogue -> fp32 logits (uses zsq, psq2, temp)
// MODE 2: plain fp32 C
// MODE 3: split write: C as fp16 hi/lo into (oh, ol), no bias
template <int MODE, int NPASS, int ASRC>
__global__ __launch_bounds__(256, 2) void hmma_gemm(
    const void* __restrict__ Aptr, const __half* __restrict__ Al,
    const __half* __restrict__ Bh, const __half* __restrict__ Bl,
    float* __restrict__ C, const float* __restrict__ bias,
    float* __restrict__ zsq, __half* __restrict__ oh, __half* __restrict__ ol,
    const float* __restrict__ psq, const float* __restrict__ temp_raw,
    int K, int ldc) {
    extern __shared__ __align__(128) char smem[];
    const uint32_t sb = smem_u32(smem);
    const int tid = threadIdx.x;
    const int wid = tid >> 5, lane = tid & 31;
    const size_t bm = (size_t)blockIdx.y * 128;
    const size_t bn = (size_t)blockIdx.x * 128;
    const int warp_m = (wid >> 1) * 32;
    const int warp_n = (wid & 1) * 64;

    float acc[2][8][4];
#pragma unroll
    for (int i = 0; i < 2; i++)
#pragma unroll
        for (int j = 0; j < 8; j++)
#pragma unroll
            for (int k = 0; k < 4; k++) acc[i][j][k] = 0.0f;

    const __half* Ahg = (ASRC == 0) ? ((const __half*)Aptr) + bm * K : nullptr;
    const __half* Alg = (ASRC == 0) ? Al + bm * K : nullptr;
    const float*  Afg = (ASRC == 1) ? ((const float*)Aptr) + bm * K : nullptr;
    const __half* Bhg = Bh + bn * K;
    const __half* Blg = (NPASS >= 2) ? Bl + bn * K : nullptr;
    const int NC = K >> 4;

    const int f_r = tid >> 1;
    const int f_s = (tid & 1) << 3;
    const uint32_t soff = (uint32_t)(f_r * 48 + (tid & 1) * 16);

    // ---- prologue: chunk 0 -> buf 0 ----
    {
        if (ASRC == 0) {
            *(uint4*)(smem + soff) = *(const uint4*)(Ahg + (size_t)f_r * K + f_s);
            if (NPASS == 3)
                *(uint4*)(smem + MATB + soff) = *(const uint4*)(Alg + (size_t)f_r * K + f_s);
        } else {
            float4 a0 = *(const float4*)(Afg + (size_t)f_r * K + f_s);
            float4 a1 = *(const float4*)(Afg + (size_t)f_r * K + f_s + 4);
            if (NPASS == 3) {
                uint4 hi, lo;
                cvt8(a0, a1, hi, lo);
                *(uint4*)(smem + soff) = hi;
                *(uint4*)(smem + MATB + soff) = lo;
            } else {
                *(uint4*)(smem + soff) = cvt8hi(a0, a1);
            }
        }
        *(uint4*)(smem + 2 * MATB + soff) = *(const uint4*)(Bhg + (size_t)f_r * K + f_s);
        if (NPASS >= 2)
            *(uint4*)(smem + 3 * MATB + soff) = *(const uint4*)(Blg + (size_t)f_r * K + f_s);
    }
    __syncthreads();

    const int a_row = lane & 15;
    const int a_kb = ((lane >> 4) << 3) * 2;
    const int b_n = ((lane >> 4) << 3) + (lane & 7);
    const int b_kb = (lane & 8) * 2;

    uint4 pah, pal, pbh, pbl;
    float4 pfa0, pfa1;
    for (int c = 0; c < NC; ++c) {
        const int buf = c & 1;
        const uint32_t base = sb + buf * BUFB;

        if (c + 1 < NC) {
            const int k0 = (c + 1) << 4;
            if (ASRC == 0) {
                pah = *(const uint4*)(Ahg + (size_t)f_r * K + k0 + f_s);
                if (NPASS == 3) pal = *(const uint4*)(Alg + (size_t)f_r * K + k0 + f_s);
            } else {
                pfa0 = *(const float4*)(Afg + (size_t)f_r * K + k0 + f_s);
                pfa1 = *(const float4*)(Afg + (size_t)f_r * K + k0 + f_s + 4);
            }
            pbh = *(const uint4*)(Bhg + (size_t)f_r * K + k0 + f_s);
            if (NPASS >= 2) pbl = *(const uint4*)(Blg + (size_t)f_r * K + k0 + f_s);
        }

        uint32_t ah[2][4], al[2][4];
#pragma unroll
        for (int i = 0; i < 2; i++) {
            uint32_t ra = base + (uint32_t)((warp_m + i * 16 + a_row) * 48) + a_kb;
            LDSM4(ah[i], ra);
            if (NPASS == 3) LDSM4(al[i], ra + MATB);
        }
#pragma unroll
        for (int jp = 0; jp < 4; jp++) {
            uint32_t rb = base + 2 * MATB +
                          (uint32_t)((warp_n + jp * 16 + b_n) * 48) + b_kb;
            uint32_t bh[4], bl[4];
            LDSM4(bh, rb);
            if (NPASS >= 2) LDSM4(bl, rb + MATB);
#pragma unroll
            for (int i = 0; i < 2; i++) {
                MMA16816(acc[i][jp * 2 + 0], ah[i], bh[0], bh[1]);
                if (NPASS >= 2) MMA16816(acc[i][jp * 2 + 0], ah[i], bl[0], bl[1]);
                if (NPASS == 3) MMA16816(acc[i][jp * 2 + 0], al[i], bh[0], bh[1]);
                MMA16816(acc[i][jp * 2 + 1], ah[i], bh[2], bh[3]);
                if (NPASS >= 2) MMA16816(acc[i][jp * 2 + 1], ah[i], bl[2], bl[3]);
                if (NPASS == 3) MMA16816(acc[i][jp * 2 + 1], al[i], bh[2], bh[3]);
            }
        }

        if (c + 1 < NC) {
            const uint32_t nb = (buf ^ 1) * BUFB;
            if (ASRC == 0) {
                *(uint4*)(smem + nb + soff) = pah;
                if (NPASS == 3) *(uint4*)(smem + nb + MATB + soff) = pal;
            } else {
                if (NPASS == 3) {
                    uint4 hi, lo;
                    cvt8(pfa0, pfa1, hi, lo);
                    *(uint4*)(smem + nb + soff) = hi;
                    *(uint4*)(smem + nb + MATB + soff) = lo;
                } else {
                    *(uint4*)(smem + nb + soff) = cvt8hi(pfa0, pfa1);
                }
            }
            *(uint4*)(smem + nb + 2 * MATB + soff) = pbh;
            if (NPASS >= 2) *(uint4*)(smem + nb + 3 * MATB + soff) = pbl;
        }
        __syncthreads();
    }

    // ---- epilogue ----
    float invt = 0.0f;
    if (MODE == 1) {
        float t = temp_raw[0];
        float temp = 1.0f / (1.0f + expf(-t)) * 0.999f + 0.001f;
        invt = 1.0f / temp;
    }
    const int rbase = warp_m + (lane >> 2);
    const int cbase = warp_n + (lane & 3) * 2;
#pragma unroll
    for (int i = 0; i < 2; i++) {
#pragma unroll
        for (int h = 0; h < 2; h++) {
            const size_t row = bm + rbase + i * 16 + h * 8;
            if (MODE == 0) {
                float s = 0.0f;
#pragma unroll
                for (int j = 0; j < 8; j++) {
                    const int cg = cbase + j * 8;
                    float v0 = acc[i][j][h * 2 + 0] + bias[bn + cg];
                    float v1 = acc[i][j][h * 2 + 1] + bias[bn + cg + 1];
                    s += v0 * v0 + v1 * v1;
                }
                s += __shfl_xor_sync(0xffffffffu, s, 1);
                s += __shfl_xor_sync(0xffffffffu, s, 2);
                if ((lane & 3) == 0) atomicAdd(zsq + row, s);
            } else if (MODE == 3) {
#pragma unroll
                for (int j = 0; j < 8; j++) {
                    const int cg = cbase + j * 8;
                    uint32_t hi, lo;
                    split_pair(acc[i][j][h * 2 + 0], acc[i][j][h * 2 + 1], hi, lo);
                    *(uint32_t*)(oh + row * (size_t)ldc + bn + cg) = hi;
                    *(uint32_t*)(ol + row * (size_t)ldc + bn + cg) = lo;
                }
            } else {
                float zr = (MODE == 1) ? zsq[row] : 0.0f;
                float* crow = C + row * (size_t)ldc + bn;
#pragma unroll
                for (int j = 0; j < 8; j++) {
                    const int cg = cbase + j * 8;
                    float v0 = acc[i][j][h * 2 + 0];
                    float v1 = acc[i][j][h * 2 + 1];
                    if (MODE == 1) {
                        float d0 = fmaxf(zr + psq[bn + cg] - 2.0f * v0, 1e-12f);
                        float d1 = fmaxf(zr + psq[bn + cg + 1] - 2.0f * v1, 1e-12f);
                        v0 = -sqrtf(d0) * invt;
                        v1 = -sqrtf(d1) * invt;
                    }
                    *(float2*)(crow + cg) = make_float2(v0, v1);
                }
            }
        }
    }
}

// ======================= small kernels =======================
__device__ __forceinline__ float wsum(float v) {
#pragma unroll
    for (int o = 16; o; o >>= 1) v += __shfl_xor_sync(0xffffffffu, v, o);
    return v;
}
__device__ __forceinline__ float wmax(float v) {
#pragma unroll
    for (int o = 16; o; o >>= 1) v = fmaxf(v, __shfl_xor_sync(0xffffffffu, v, o));
    return v;
}

// psq2[row] = sum(P[row]^2) - 2 * dot(P[row], b)
// (d2 = zsq + psq - 2 z.p ; z.p = x.q + b.p  =>  d2 = zsq + (psq - 2 p.b) - 2 x.q)
__global__ __launch_bounds__(128) void row_psq2(const float* __restrict__ P,
                                                const float* __restrict__ b,
                                                float* __restrict__ out) {
    size_t row = blockIdx.x;
    const float4* p = (const float4*)(P + row * 512);
    float4 v = p[threadIdx.x];
    float4 bb = ((const float4*)b)[threadIdx.x];
    float s = v.x * v.x + v.y * v.y + v.z * v.z + v.w * v.w
            - 2.0f * (v.x * bb.x + v.y * bb.y + v.z * bb.z + v.w * bb.w);
    s = wsum(s);
    __shared__ float red[4];
    if ((threadIdx.x & 31) == 0) red[threadIdx.x >> 5] = s;
    __syncthreads();
    if (threadIdx.x == 0) out[row] = red[0] + red[1] + red[2] + red[3];
}

// in-place softmax over rows of 1024
__global__ __launch_bounds__(256) void softmax_1024(float* __restrict__ Wt) {
    size_t row = blockIdx.x;
    float4* p = (float4*)(Wt + row * 1024);
    float4 v = p[threadIdx.x];

    __shared__ float red[8];
    float m = fmaxf(fmaxf(v.x, v.y), fmaxf(v.z, v.w));
    m = wmax(m);
    if ((threadIdx.x & 31) == 0) red[threadIdx.x >> 5] = m;
    __syncthreads();
    if (threadIdx.x < 32) {
        float t = (threadIdx.x < 8) ? red[threadIdx.x] : -INFINITY;
        t = wmax(t);
        if (threadIdx.x == 0) red[0] = t;
    }
    __syncthreads();
    m = red[0];
    __syncthreads();

    v.x = fexp(v.x - m); v.y = fexp(v.y - m);
    v.z = fexp(v.z - m); v.w = fexp(v.w - m);
    float s = v.x + v.y + v.z + v.w;
    s = wsum(s);
    __shared__ float red2[8];
    if ((threadIdx.x & 31) == 0) red2[threadIdx.x >> 5] = s;
    __syncthreads();
    if (threadIdx.x < 32) {
        float t = (threadIdx.x < 8) ? red2[threadIdx.x] : 0.0f;
        t = wsum(t);
        if (threadIdx.x == 0) red2[0] = t;
    }
    __syncthreads();
    float inv = 1.0f / red2[0];
    v.x *= inv; v.y *= inv; v.z *= inv; v.w *= inv;
    p[threadIdx.x] = v;
}

// split fp32 array into fp16 hi/lo
__global__ __launch_bounds__(256) void split_mat(const float4* __restrict__ src,
                                                 uint2* __restrict__ hi,
                                                 uint2* __restrict__ lo, int n4) {
    int i = blockIdx.x * 256 + threadIdx.x;
    if (i >= n4) return;
    float4 v = src[i];
    uint32_t h0, l0, h1, l1;
    split_pair(v.x, v.y, h0, l0);
    split_pair(v.z, v.w, h1, l1);
    hi[i] = make_uint2(h0, h1);
    lo[i] = make_uint2(l0, l1);
}

// transpose + split: src [rows, cols] fp32 -> dst [cols, rows] fp16 hi/lo
__global__ __launch_bounds__(256) void transpose_split(const float* __restrict__ src,
                                                       __half* __restrict__ dh,
                                                       __half* __restrict__ dl,
                                                       int rows, int cols) {
    __shared__ float t[32][33];
    int bx = blockIdx.x * 32;   // col of src
    int by = blockIdx.y * 32;   // row of src
    int tx = threadIdx.x & 31, ty = (threadIdx.x >> 5) * 4;
#pragma unroll
    for (int i = 0; i < 4; i++)
        t[ty + i][tx] = src[(size_t)(by + ty + i) * cols + bx + tx];
    __syncthreads();
#pragma unroll
    for (int i = 0; i < 4; i++) {
        float v = t[tx][ty + i];
        __half hv = __float2half_rn(v);
        size_t off = (size_t)(bx + ty + i) * rows + by + tx;
        dh[off] = hv;
        dl[off] = __float2half_rn(v - __half2float(hv));
    }
}

extern "C" void kernel_launch(void* const* d_in, const int* in_sizes, int n_in,
                              void* d_out, int out_size) {
    const float* x  = (const float*)d_in[0];
    const float* W  = (const float*)d_in[1];
    const float* b  = (const float*)d_in[2];
    const float* P  = (const float*)d_in[3];
    const float* tr = (const float*)d_in[4];

    float* blended = (float*)d_out;
    float* weights = (float*)d_out + (size_t)BATCH * DIM;

    __half *Wh, *Wl, *WTh, *WTl, *PTh, *PTl, *Qh, *Ql;
    float *zsq, *psq2;
    cudaGetSymbolAddress((void**)&Wh, g_Wh);   cudaGetSymbolAddress((void**)&Wl, g_Wl);
    cudaGetSymbolAddress((void**)&WTh, g_WTh); cudaGetSymbolAddress((void**)&WTl, g_WTl);
    cudaGetSymbolAddress((void**)&PTh, g_PTh); cudaGetSymbolAddress((void**)&PTl, g_PTl);
    cudaGetSymbolAddress((void**)&Qh, g_Qh);   cudaGetSymbolAddress((void**)&Ql, g_Ql);
    cudaGetSymbolAddress((void**)&zsq, g_zsq); cudaGetSymbolAddress((void**)&psq2, g_psq2);

    cudaFuncSetAttribute((const void*)hmma_gemm<3, 3, 1>, cudaFuncAttributeMaxDynamicSharedMemorySize, SMEM_TOTAL);
    cudaFuncSetAttribute((const void*)hmma_gemm<0, 1, 1>, cudaFuncAttributeMaxDynamicSharedMemorySize, SMEM_TOTAL);
    cudaFuncSetAttribute((const void*)hmma_gemm<1, 3, 1>, cudaFuncAttributeMaxDynamicSharedMemorySize, SMEM_TOTAL);
    cudaFuncSetAttribute((const void*)hmma_gemm<2, 2, 1>, cudaFuncAttributeMaxDynamicSharedMemorySize, SMEM_TOTAL);

    cudaMemsetAsync(zsq, 0, BATCH * sizeof(float));

    // psq2 = |p|^2 - 2 p.b
    row_psq2<<<NPROTO, 128>>>(P, b, psq2);

    // operand prep (all tiny)
    split_mat<<<(DIM * DIM / 4 + 255) / 256, 256>>>((const float4*)W, (uint2*)Wh, (uint2*)Wl, DIM * DIM / 4);
    transpose_split<<<dim3(16, 16), 256>>>(W, WTh, WTl, DIM, DIM);     // WT[n,k]=W[k,n]
    transpose_split<<<dim3(16, 32), 256>>>(P, PTh, PTl, NPROTO, DIM);  // PT [512,1024]

    // Q = P @ W  (NT with B=W^T), 3-pass, write fp16 hi/lo
    hmma_gemm<3, 3, 1><<<dim3(DIM / 128, NPROTO / 128), 256, SMEM_TOTAL>>>(
        P, nullptr, WTh, WTl, nullptr, nullptr, nullptr, Qh, Ql, nullptr, nullptr, DIM, DIM);

    // zsq_i = |x_i @ W^T + b|^2   (1-pass, no C)
    hmma_gemm<0, 1, 1><<<dim3(DIM / 128, BATCH / 128), 256, SMEM_TOTAL>>>(
        x, nullptr, Wh, nullptr, nullptr, b, zsq, nullptr, nullptr, nullptr, nullptr, DIM, DIM);

    // logits = -sqrt(max(zsq_i + psq2_j - 2 x_i.q_j, 1e-12))/temp  (3-pass)
    hmma_gemm<1, 3, 1><<<dim3(NPROTO / 128, BATCH / 128), 256, SMEM_TOTAL>>>(
        x, nullptr, Qh, Ql, weights, nullptr, zsq, nullptr, nullptr, psq2, tr, DIM, NPROTO);

    // softmax in-place
    softmax_1024<<<BATCH, 256>>>(weights);

    // blended = weights @ P (2-pass)
    hmma_gemm<2, 2, 1><<<dim3(DIM / 128, BATCH / 128), 256, SMEM_TOTAL>>>(
        weights, nullptr, PTh, PTl, blended, nullptr, nullptr, nullptr, nullptr, nullptr, nullptr, NPROTO, DIM);
}

// round 9
// speedup vs baseline: 2.4982x; 1.0004x over previous
#include <cuda_runtime.h>
#include <cuda_fp16.h>
#include <math.h>
#include <stdint.h>

#define BATCH  65536
#define DIM    512
#define NPROTO 1024

// ---------------- device scratch ----------------
__device__ __half g_xh[(size_t)BATCH * DIM],   g_xl[(size_t)BATCH * DIM];
__device__ __half g_Wh[(size_t)DIM * DIM],     g_Wl[(size_t)DIM * DIM];
__device__ __half g_WTh[(size_t)DIM * DIM],    g_WTl[(size_t)DIM * DIM];
__device__ __half g_PTh[(size_t)DIM * NPROTO], g_PTl[(size_t)DIM * NPROTO];
__device__ __half g_Qh[(size_t)NPROTO * DIM],  g_Ql[(size_t)NPROTO * DIM];
__device__ __half g_wh[(size_t)BATCH * NPROTO];
__device__ float g_zsq[BATCH];
__device__ float g_psq2[NPROTO];   // psq - 2*P.b

// ======================= helpers =======================
__device__ __forceinline__ uint32_t smem_u32(const void* p) {
    uint32_t a;
    asm("{ .reg .u64 t; cvta.to.shared.u64 t, %1; cvt.u32.u64 %0, t; }" : "=r"(a) : "l"(p));
    return a;
}

#define LDSM4(r, addr) \
    asm volatile("ldmatrix.sync.aligned.m8n8.x4.shared.b16 {%0,%1,%2,%3}, [%4];" \
        : "=r"((r)[0]), "=r"((r)[1]), "=r"((r)[2]), "=r"((r)[3]) : "r"(addr))

#define MMA16816(d, a, b0, b1) \
    asm volatile("mma.sync.aligned.m16n8k16.row.col.f32.f16.f16.f32 " \
        "{%0,%1,%2,%3}, {%4,%5,%6,%7}, {%8,%9}, {%0,%1,%2,%3};" \
        : "+f"((d)[0]), "+f"((d)[1]), "+f"((d)[2]), "+f"((d)[3]) \
        : "r"((a)[0]), "r"((a)[1]), "r"((a)[2]), "r"((a)[3]), "r"(b0), "r"(b1))

__device__ __forceinline__ void split_pair(float x, float y, uint32_t& hi, uint32_t& lo) {
    __half hx = __float2half_rn(x), hy = __float2half_rn(y);
    __half2 h2 = __halves2half2(hx, hy);
    hi = *(uint32_t*)&h2;
    __half2 l2 = __floats2half2_rn(x - __half2float(hx), y - __half2float(hy));
    lo = *(uint32_t*)&l2;
}
__device__ __forceinline__ void cvt8(const float4& a, const float4& b,
                                     uint4& hi, uint4& lo) {
    split_pair(a.x, a.y, hi.x, lo.x);
    split_pair(a.z, a.w, hi.y, lo.y);
    split_pair(b.x, b.y, hi.z, lo.z);
    split_pair(b.z, b.w, hi.w, lo.w);
}

// FFMA-pipe exp (args <= 0 here)
__device__ __forceinline__ float fexp(float x) {
    float y = x * 1.4426950408889634f;
    float t = y + 12582912.0f;
    float n = t - 12582912.0f;
    float f = y - n;
    float p = 1.3333558146e-3f;
    p = fmaf(p, f, 9.6181291076e-3f);
    p = fmaf(p, f, 5.5504108664e-2f);
    p = fmaf(p, f, 2.4022650696e-1f);
    p = fmaf(p, f, 6.9314718056e-1f);
    p = fmaf(p, f, 1.0f);
    return __int_as_float(__float_as_int(p) + (((int)n) << 23));
}

// SMEM: per buf 4 matrices (Ahi, Alo, Bhi, Blo), each 128 rows x 24 halves (48B)
#define MATB   6144u
#define BUFB   (4u * MATB)
#define SMEM_TOTAL (2 * BUFB)   // 49152

// ======================= generic HMMA GEMM NT (pre-split A) =======================
// C[M,N] = A[M,K] @ Bm[N,K]^T.
// ASRC 0: A fp16 (Aptr=hi, Al=lo). ASRC 1: A fp32, full split in fill (3-pass only).
// NPASS 3: AhBh+AhBl+AlBh ; 2: AhBh+AhBl (A lo unused)
// MODE 2: plain fp32 C ; MODE 3: write fp16 hi/lo (oh, ol)
template <int MODE, int NPASS, int ASRC>
__global__ __launch_bounds__(256, 2) void hmma_gemm(
    const void* __restrict__ Aptr, const __half* __restrict__ Al,
    const __half* __restrict__ Bh, const __half* __restrict__ Bl,
    float* __restrict__ C, __half* __restrict__ oh, __half* __restrict__ ol,
    int K, int ldc) {
    extern __shared__ __align__(128) char smem[];
    const uint32_t sb = smem_u32(smem);
    const int tid = threadIdx.x;
    const int wid = tid >> 5, lane = tid & 31;
    const size_t bm = (size_t)blockIdx.y * 128;
    const size_t bn = (size_t)blockIdx.x * 128;
    const int warp_m = (wid >> 1) * 32;
    const int warp_n = (wid & 1) * 64;

    float acc[2][8][4];
#pragma unroll
    for (int i = 0; i < 2; i++)
#pragma unroll
        for (int j = 0; j < 8; j++)
#pragma unroll
            for (int k = 0; k < 4; k++) acc[i][j][k] = 0.0f;

    const __half* Ahg = (ASRC == 0) ? ((const __half*)Aptr) + bm * K : nullptr;
    const __half* Alg = (ASRC == 0 && NPASS == 3) ? Al + bm * K : nullptr;
    const float*  Afg = (ASRC == 1) ? ((const float*)Aptr) + bm * K : nullptr;
    const __half* Bhg = Bh + bn * K;
    const __half* Blg = Bl + bn * K;
    const int NC = K >> 4;

    const int f_r = tid >> 1;
    const int f_s = (tid & 1) << 3;
    const uint32_t soff = (uint32_t)(f_r * 48 + (tid & 1) * 16);

    // ---- prologue ----
    {
        if (ASRC == 0) {
            *(uint4*)(smem + soff) = *(const uint4*)(Ahg + (size_t)f_r * K + f_s);
            if (NPASS == 3)
                *(uint4*)(smem + MATB + soff) = *(const uint4*)(Alg + (size_t)f_r * K + f_s);
        } else {
            float4 a0 = *(const float4*)(Afg + (size_t)f_r * K + f_s);
            float4 a1 = *(const float4*)(Afg + (size_t)f_r * K + f_s + 4);
            uint4 hi, lo;
            cvt8(a0, a1, hi, lo);
            *(uint4*)(smem + soff) = hi;
            *(uint4*)(smem + MATB + soff) = lo;
        }
        *(uint4*)(smem + 2 * MATB + soff) = *(const uint4*)(Bhg + (size_t)f_r * K + f_s);
        *(uint4*)(smem + 3 * MATB + soff) = *(const uint4*)(Blg + (size_t)f_r * K + f_s);
    }
    __syncthreads();

    const int a_row = lane & 15;
    const int a_kb = ((lane >> 4) << 3) * 2;
    const int b_n = ((lane >> 4) << 3) + (lane & 7);
    const int b_kb = (lane & 8) * 2;

    uint4 pah, pal, pbh, pbl;
    float4 pfa0, pfa1;
    for (int c = 0; c < NC; ++c) {
        const int buf = c & 1;
        const uint32_t base = sb + buf * BUFB;

        if (c + 1 < NC) {
            const int k0 = (c + 1) << 4;
            if (ASRC == 0) {
                pah = *(const uint4*)(Ahg + (size_t)f_r * K + k0 + f_s);
                if (NPASS == 3) pal = *(const uint4*)(Alg + (size_t)f_r * K + k0 + f_s);
            } else {
                pfa0 = *(const float4*)(Afg + (size_t)f_r * K + k0 + f_s);
                pfa1 = *(const float4*)(Afg + (size_t)f_r * K + k0 + f_s + 4);
            }
            pbh = *(const uint4*)(Bhg + (size_t)f_r * K + k0 + f_s);
            pbl = *(const uint4*)(Blg + (size_t)f_r * K + k0 + f_s);
        }

        uint32_t ah[2][4], al[2][4];
#pragma unroll
        for (int i = 0; i < 2; i++) {
            uint32_t ra = base + (uint32_t)((warp_m + i * 16 + a_row) * 48) + a_kb;
            LDSM4(ah[i], ra);
            if (NPASS == 3) LDSM4(al[i], ra + MATB);
        }
#pragma unroll
        for (int jp = 0; jp < 4; jp++) {
            uint32_t rb = base + 2 * MATB +
                          (uint32_t)((warp_n + jp * 16 + b_n) * 48) + b_kb;
            uint32_t bh[4], bl[4];
            LDSM4(bh, rb);
            LDSM4(bl, rb + MATB);
#pragma unroll
            for (int i = 0; i < 2; i++) {
                MMA16816(acc[i][jp * 2 + 0], ah[i], bh[0], bh[1]);
                MMA16816(acc[i][jp * 2 + 0], ah[i], bl[0], bl[1]);
                if (NPASS == 3) MMA16816(acc[i][jp * 2 + 0], al[i], bh[0], bh[1]);
                MMA16816(acc[i][jp * 2 + 1], ah[i], bh[2], bh[3]);
                MMA16816(acc[i][jp * 2 + 1], ah[i], bl[2], bl[3]);
                if (NPASS == 3) MMA16816(acc[i][jp * 2 + 1], al[i], bh[2], bh[3]);
            }
        }

        if (c + 1 < NC) {
            const uint32_t nb = (buf ^ 1) * BUFB;
            if (ASRC == 0) {
                *(uint4*)(smem + nb + soff) = pah;
                if (NPASS == 3) *(uint4*)(smem + nb + MATB + soff) = pal;
            } else {
                uint4 hi, lo;
                cvt8(pfa0, pfa1, hi, lo);
                *(uint4*)(smem + nb + soff) = hi;
                *(uint4*)(smem + nb + MATB + soff) = lo;
            }
            *(uint4*)(smem + nb + 2 * MATB + soff) = pbh;
            *(uint4*)(smem + nb + 3 * MATB + soff) = pbl;
        }
        __syncthreads();
    }

    // ---- epilogue ----
    const int rbase = warp_m + (lane >> 2);
    const int cbase = warp_n + (lane & 3) * 2;
#pragma unroll
    for (int i = 0; i < 2; i++) {
#pragma unroll
        for (int h = 0; h < 2; h++) {
            const size_t row = bm + rbase + i * 16 + h * 8;
            if (MODE == 3) {
#pragma unroll
                for (int j = 0; j < 8; j++) {
                    const int cg = cbase + j * 8;
                    uint32_t hi, lo;
                    split_pair(acc[i][j][h * 2 + 0], acc[i][j][h * 2 + 1], hi, lo);
                    *(uint32_t*)(oh + row * (size_t)ldc + bn + cg) = hi;
                    *(uint32_t*)(ol + row * (size_t)ldc + bn + cg) = lo;
                }
            } else {
                float* crow = C + row * (size_t)ldc + bn;
#pragma unroll
                for (int j = 0; j < 8; j++) {
                    const int cg = cbase + j * 8;
                    *(float2*)(crow + cg) =
                        make_float2(acc[i][j][h * 2 + 0], acc[i][j][h * 2 + 1]);
                }
            }
        }
    }
}

// ======================= fused logits-raw + zsq kernel =======================
// grid (12, BATCH/128): x<8 -> Q-tile: Sraw = x.q (3-pass)
//                       x>=8 -> W-tile: zsq += |x.w + b|^2 (1-pass)
__global__ __launch_bounds__(256, 2) void fused_logits_zsq(
    const __half* __restrict__ xh, const __half* __restrict__ xl,
    const __half* __restrict__ Qh, const __half* __restrict__ Ql,
    const __half* __restrict__ Wh, const float* __restrict__ bias,
    float* __restrict__ Sraw, float* __restrict__ zsq) {
    extern __shared__ __align__(128) char smem[];
    const uint32_t sb = smem_u32(smem);
    const int tid = threadIdx.x;
    const int wid = tid >> 5, lane = tid & 31;
    const bool is_w = blockIdx.x >= 8;
    const size_t bm = (size_t)blockIdx.y * 128;
    const size_t bn = is_w ? (size_t)(blockIdx.x - 8) * 128 : (size_t)blockIdx.x * 128;
    const int warp_m = (wid >> 1) * 32;
    const int warp_n = (wid & 1) * 64;
    const int K = DIM, NC = DIM >> 4;

    float acc[2][8][4];
#pragma unroll
    for (int i = 0; i < 2; i++)
#pragma unroll
        for (int j = 0; j < 8; j++)
#pragma unroll
            for (int k = 0; k < 4; k++) acc[i][j][k] = 0.0f;

    const __half* Ahg = xh + bm * K;
    const __half* Alg = xl + bm * K;
    const __half* Bhg = (is_w ? Wh : Qh) + bn * K;
    const __half* Blg = (is_w ? Wh : Ql) + bn * K;  // dummy for W (never MMA'd)

    const int f_r = tid >> 1;
    const int f_s = (tid & 1) << 3;
    const uint32_t soff = (uint32_t)(f_r * 48 + (tid & 1) * 16);

    {
        *(uint4*)(smem + soff) = *(const uint4*)(Ahg + (size_t)f_r * K + f_s);
        *(uint4*)(smem + 2 * MATB + soff) = *(const uint4*)(Bhg + (size_t)f_r * K + f_s);
        if (!is_w) {
            *(uint4*)(smem + MATB + soff) = *(const uint4*)(Alg + (size_t)f_r * K + f_s);
            *(uint4*)(smem + 3 * MATB + soff) = *(const uint4*)(Blg + (size_t)f_r * K + f_s);
        }
    }
    __syncthreads();

    const int a_row = lane & 15;
    const int a_kb = ((lane >> 4) << 3) * 2;
    const int b_n = ((lane >> 4) << 3) + (lane & 7);
    const int b_kb = (lane & 8) * 2;

    uint4 pah, pal, pbh, pbl;
    for (int c = 0; c < NC; ++c) {
        const int buf = c & 1;
        const uint32_t base = sb + buf * BUFB;

        if (c + 1 < NC) {
            const int k0 = (c + 1) << 4;
            pah = *(const uint4*)(Ahg + (size_t)f_r * K + k0 + f_s);
            pbh = *(const uint4*)(Bhg + (size_t)f_r * K + k0 + f_s);
            if (!is_w) {
                pal = *(const uint4*)(Alg + (size_t)f_r * K + k0 + f_s);
                pbl = *(const uint4*)(Blg + (size_t)f_r * K + k0 + f_s);
            }
        }

        uint32_t ah[2][4], al[2][4];
#pragma unroll
        for (int i = 0; i < 2; i++) {
            uint32_t ra = base + (uint32_t)((warp_m + i * 16 + a_row) * 48) + a_kb;
            LDSM4(ah[i], ra);
            if (!is_w) LDSM4(al[i], ra + MATB);
        }
#pragma unroll
        for (int jp = 0; jp < 4; jp++) {
            uint32_t rb = base + 2 * MATB +
                          (uint32_t)((warp_n + jp * 16 + b_n) * 48) + b_kb;
            uint32_t bh[4], bl[4];
            LDSM4(bh, rb);
            if (!is_w) LDSM4(bl, rb + MATB);
#pragma unroll
            for (int i = 0; i < 2; i++) {
                MMA16816(acc[i][jp * 2 + 0], ah[i], bh[0], bh[1]);
                MMA16816(acc[i][jp * 2 + 1], ah[i], bh[2], bh[3]);
                if (!is_w) {
                    MMA16816(acc[i][jp * 2 + 0], ah[i], bl[0], bl[1]);
                    MMA16816(acc[i][jp * 2 + 0], al[i], bh[0], bh[1]);
                    MMA16816(acc[i][jp * 2 + 1], ah[i], bl[2], bl[3]);
                    MMA16816(acc[i][jp * 2 + 1], al[i], bh[2], bh[3]);
                }
            }
        }

        if (c + 1 < NC) {
            const uint32_t nb = (buf ^ 1) * BUFB;
            *(uint4*)(smem + nb + soff) = pah;
            *(uint4*)(smem + nb + 2 * MATB + soff) = pbh;
            if (!is_w) {
                *(uint4*)(smem + nb + MATB + soff) = pal;
                *(uint4*)(smem + nb + 3 * MATB + soff) = pbl;
            }
        }
        __syncthreads();
    }

    const int rbase = warp_m + (lane >> 2);
    const int cbase = warp_n + (lane & 3) * 2;
#pragma unroll
    for (int i = 0; i < 2; i++) {
#pragma unroll
        for (int h = 0; h < 2; h++) {
            const size_t row = bm + rbase + i * 16 + h * 8;
            if (is_w) {
                float s = 0.0f;
#pragma unroll
                for (int j = 0; j < 8; j++) {
                    const int cg = cbase + j * 8;
                    float v0 = acc[i][j][h * 2 + 0] + bias[bn + cg];
                    float v1 = acc[i][j][h * 2 + 1] + bias[bn + cg + 1];
                    s += v0 * v0 + v1 * v1;
                }
                s += __shfl_xor_sync(0xffffffffu, s, 1);
                s += __shfl_xor_sync(0xffffffffu, s, 2);
                if ((lane & 3) == 0) atomicAdd(zsq + row, s);
            } else {
                float* crow = Sraw + row * (size_t)NPROTO + bn;
#pragma unroll
                for (int j = 0; j < 8; j++) {
                    const int cg = cbase + j * 8;
                    *(float2*)(crow + cg) =
                        make_float2(acc[i][j][h * 2 + 0], acc[i][j][h * 2 + 1]);
                }
            }
        }
    }
}

// ======================= small kernels =======================
__device__ __forceinline__ float wsum(float v) {
#pragma unroll
    for (int o = 16; o; o >>= 1) v += __shfl_xor_sync(0xffffffffu, v, o);
    return v;
}
__device__ __forceinline__ float wmax(float v) {
#pragma unroll
    for (int o = 16; o; o >>= 1) v = fmaxf(v, __shfl_xor_sync(0xffffffffu, v, o));
    return v;
}

// psq2[row] = sum(P[row]^2) - 2 * dot(P[row], b)
__global__ __launch_bounds__(128) void row_psq2(const float* __restrict__ P,
                                                const float* __restrict__ b,
                                                float* __restrict__ out) {
    size_t row = blockIdx.x;
    const float4* p = (const float4*)(P + row * 512);
    float4 v = p[threadIdx.x];
    float4 bb = ((const float4*)b)[threadIdx.x];
    float s = v.x * v.x + v.y * v.y + v.z * v.z + v.w * v.w
            - 2.0f * (v.x * bb.x + v.y * bb.y + v.z * bb.z + v.w * bb.w);
    s = wsum(s);
    __shared__ float red[4];
    if ((threadIdx.x & 31) == 0) red[threadIdx.x >> 5] = s;
    __syncthreads();
    if (threadIdx.x == 0) out[row] = red[0] + red[1] + red[2] + red[3];
}

// dist + softmax over rows of 1024; reads raw dot, writes fp32 weights + fp16 hi
__global__ __launch_bounds__(256) void softmax_dist_1024(
    float* __restrict__ Wt, const float* __restrict__ zsq,
    const float* __restrict__ psq2, const float* __restrict__ temp_raw,
    __half* __restrict__ wh) {
    size_t row = blockIdx.x;
    float4* p = (float4*)(Wt + row * 1024);
    float4 s4 = p[threadIdx.x];
    float4 pq = ((const float4*)psq2)[threadIdx.x];
    float zr = zsq[row];
    float t = temp_raw[0];
    float temp = 1.0f / (1.0f + expf(-t)) * 0.999f + 0.001f;
    float invt = 1.0f / temp;

    float4 v;
    v.x = -sqrtf(fmaxf(zr + pq.x - 2.0f * s4.x, 1e-12f)) * invt;
    v.y = -sqrtf(fmaxf(zr + pq.y - 2.0f * s4.y, 1e-12f)) * invt;
    v.z = -sqrtf(fmaxf(zr + pq.z - 2.0f * s4.z, 1e-12f)) * invt;
    v.w = -sqrtf(fmaxf(zr + pq.w - 2.0f * s4.w, 1e-12f)) * invt;

    __shared__ float red[8];
    float m = fmaxf(fmaxf(v.x, v.y), fmaxf(v.z, v.w));
    m = wmax(m);
    if ((threadIdx.x & 31) == 0) red[threadIdx.x >> 5] = m;
    __syncthreads();
    if (threadIdx.x < 32) {
        float q = (threadIdx.x < 8) ? red[threadIdx.x] : -INFINITY;
        q = wmax(q);
        if (threadIdx.x == 0) red[0] = q;
    }
    __syncthreads();
    m = red[0];
    __syncthreads();

    v.x = fexp(v.x - m); v.y = fexp(v.y - m);
    v.z = fexp(v.z - m); v.w = fexp(v.w - m);
    float s = v.x + v.y + v.z + v.w;
    s = wsum(s);
    __shared__ float red2[8];
    if ((threadIdx.x & 31) == 0) red2[threadIdx.x >> 5] = s;
    __syncthreads();
    if (threadIdx.x < 32) {
        float q = (threadIdx.x < 8) ? red2[threadIdx.x] : 0.0f;
        q = wsum(q);
        if (threadIdx.x == 0) red2[0] = q;
    }
    __syncthreads();
    float inv = 1.0f / red2[0];
    v.x *= inv; v.y *= inv; v.z *= inv; v.w *= inv;
    p[threadIdx.x] = v;

    __half2 h0 = __floats2half2_rn(v.x, v.y);
    __half2 h1 = __floats2half2_rn(v.z, v.w);
    *(uint2*)(wh + row * 1024 + threadIdx.x * 4) =
        make_uint2(*(uint32_t*)&h0, *(uint32_t*)&h1);
}

// split fp32 array into fp16 hi/lo
__global__ __launch_bounds__(256) void split_mat(const float4* __restrict__ src,
                                                 uint2* __restrict__ hi,
                                                 uint2* __restrict__ lo, int n4) {
    int i = blockIdx.x * 256 + threadIdx.x;
    if (i >= n4) return;
    float4 v = src[i];
    uint32_t h0, l0, h1, l1;
    split_pair(v.x, v.y, h0, l0);
    split_pair(v.z, v.w, h1, l1);
    hi[i] = make_uint2(h0, h1);
    lo[i] = make_uint2(l0, l1);
}

// transpose + split: src [rows, cols] fp32 -> dst [cols, rows] fp16 hi/lo
__global__ __launch_bounds__(256) void transpose_split(const float* __restrict__ src,
                                                       __half* __restrict__ dh,
                                                       __half* __restrict__ dl,
                                                       int rows, int cols) {
    __shared__ float t[32][33];
    int bx = blockIdx.x * 32;
    int by = blockIdx.y * 32;
    int tx = threadIdx.x & 31, ty = (threadIdx.x >> 5) * 4;
#pragma unroll
    for (int i = 0; i < 4; i++)
        t[ty + i][tx] = src[(size_t)(by + ty + i) * cols + bx + tx];
    __syncthreads();
#pragma unroll
    for (int i = 0; i < 4; i++) {
        float v = t[tx][ty + i];
        __half hv = __float2half_rn(v);
        size_t off = (size_t)(bx + ty + i) * rows + by + tx;
        dh[off] = hv;
        dl[off] = __float2half_rn(v - __half2float(hv));
    }
}

extern "C" void kernel_launch(void* const* d_in, const int* in_sizes, int n_in,
                              void* d_out, int out_size) {
    const float* x  = (const float*)d_in[0];
    const float* W  = (const float*)d_in[1];
    const float* b  = (const float*)d_in[2];
    const float* P  = (const float*)d_in[3];
    const float* tr = (const float*)d_in[4];

    float* blended = (float*)d_out;
    float* weights = (float*)d_out + (size_t)BATCH * DIM;

    __half *xh, *xl, *Wh, *Wl, *WTh, *WTl, *PTh, *PTl, *Qh, *Ql, *wh;
    float *zsq, *psq2;
    cudaGetSymbolAddress((void**)&xh, g_xh);   cudaGetSymbolAddress((void**)&xl, g_xl);
    cudaGetSymbolAddress((void**)&Wh, g_Wh);   cudaGetSymbolAddress((void**)&Wl, g_Wl);
    cudaGetSymbolAddress((void**)&WTh, g_WTh); cudaGetSymbolAddress((void**)&WTl, g_WTl);
    cudaGetSymbolAddress((void**)&PTh, g_PTh); cudaGetSymbolAddress((void**)&PTl, g_PTl);
    cudaGetSymbolAddress((void**)&Qh, g_Qh);   cudaGetSymbolAddress((void**)&Ql, g_Ql);
    cudaGetSymbolAddress((void**)&wh, g_wh);
    cudaGetSymbolAddress((void**)&zsq, g_zsq); cudaGetSymbolAddress((void**)&psq2, g_psq2);

    cudaFuncSetAttribute((const void*)hmma_gemm<3, 3, 1>, cudaFuncAttributeMaxDynamicSharedMemorySize, SMEM_TOTAL);
    cudaFuncSetAttribute((const void*)hmma_gemm<2, 2, 0>, cudaFuncAttributeMaxDynamicSharedMemorySize, SMEM_TOTAL);
    cudaFuncSetAttribute((const void*)fused_logits_zsq, cudaFuncAttributeMaxDynamicSharedMemorySize, SMEM_TOTAL);

    cudaMemsetAsync(zsq, 0, BATCH * sizeof(float));

    // psq2 = |p|^2 - 2 p.b
    row_psq2<<<NPROTO, 128>>>(P, b, psq2);

    // operand prep
    split_mat<<<(BATCH * DIM / 4 + 255) / 256, 256>>>((const float4*)x, (uint2*)xh, (uint2*)xl, BATCH * DIM / 4);
    split_mat<<<(DIM * DIM / 4 + 255) / 256, 256>>>((const float4*)W, (uint2*)Wh, (uint2*)Wl, DIM * DIM / 4);
    transpose_split<<<dim3(16, 16), 256>>>(W, WTh, WTl, DIM, DIM);
    transpose_split<<<dim3(16, 32), 256>>>(P, PTh, PTl, NPROTO, DIM);

    // Q = P @ W (3-pass, A=P fp32 split in fill), write fp16 hi/lo
    hmma_gemm<3, 3, 1><<<dim3(DIM / 128, NPROTO / 128), 256, SMEM_TOTAL>>>(
        P, nullptr, WTh, WTl, nullptr, Qh, Ql, DIM, DIM);

    // fused: Sraw = x.q^T (3-pass) + zsq = |x.W^T + b|^2 (1-pass)
    fused_logits_zsq<<<dim3(12, BATCH / 128), 256, SMEM_TOTAL>>>(
        xh, xl, Qh, Ql, Wh, b, weights, zsq);

    // dist + softmax; writes fp32 weights + fp16 wh
    softmax_dist_1024<<<BATCH, 256>>>(weights, zsq, psq2, tr, wh);

    // blended = weights @ P (2-pass, A=wh pure copy)
    hmma_gemm<2, 2, 0><<<dim3(DIM / 128, BATCH / 128), 256, SMEM_TOTAL>>>(
        wh, nullptr, PTh, PTl, blended, nullptr, nullptr, NPROTO, DIM);
}

// round 10
// speedup vs baseline: 2.8589x; 1.1444x over previous
#include <cuda_runtime.h>
#include <cuda_fp16.h>
#include <math.h>
#include <stdint.h>

#define BATCH  65536
#define DIM    512
#define NPROTO 1024

// ---------------- device scratch ----------------
__device__ __half g_xh[(size_t)BATCH * DIM],   g_xl[(size_t)BATCH * DIM];
__device__ __half g_Wh[(size_t)DIM * DIM],     g_Wl[(size_t)DIM * DIM];
__device__ __half g_WTh[(size_t)DIM * DIM],    g_WTl[(size_t)DIM * DIM];
__device__ __half g_PTh[(size_t)DIM * NPROTO], g_PTl[(size_t)DIM * NPROTO];
__device__ __half g_Qh[(size_t)NPROTO * DIM],  g_Ql[(size_t)NPROTO * DIM];
__device__ __half g_wh[(size_t)BATCH * NPROTO];
__device__ float g_zsq[BATCH];
__device__ float g_psq2[NPROTO];   // psq - 2*P.b

// ======================= helpers =======================
__device__ __forceinline__ uint32_t smem_u32(const void* p) {
    uint32_t a;
    asm("{ .reg .u64 t; cvta.to.shared.u64 t, %1; cvt.u32.u64 %0, t; }" : "=r"(a) : "l"(p));
    return a;
}

#define LDSM4(r, addr) \
    asm volatile("ldmatrix.sync.aligned.m8n8.x4.shared.b16 {%0,%1,%2,%3}, [%4];" \
        : "=r"((r)[0]), "=r"((r)[1]), "=r"((r)[2]), "=r"((r)[3]) : "r"(addr))

#define MMA16816(d, a, b0, b1) \
    asm volatile("mma.sync.aligned.m16n8k16.row.col.f32.f16.f16.f32 " \
        "{%0,%1,%2,%3}, {%4,%5,%6,%7}, {%8,%9}, {%0,%1,%2,%3};" \
        : "+f"((d)[0]), "+f"((d)[1]), "+f"((d)[2]), "+f"((d)[3]) \
        : "r"((a)[0]), "r"((a)[1]), "r"((a)[2]), "r"((a)[3]), "r"(b0), "r"(b1))

__device__ __forceinline__ void split_pair(float x, float y, uint32_t& hi, uint32_t& lo) {
    __half hx = __float2half_rn(x), hy = __float2half_rn(y);
    __half2 h2 = __halves2half2(hx, hy);
    hi = *(uint32_t*)&h2;
    __half2 l2 = __floats2half2_rn(x - __half2float(hx), y - __half2float(hy));
    lo = *(uint32_t*)&l2;
}
__device__ __forceinline__ void cvt8(const float4& a, const float4& b,
                                     uint4& hi, uint4& lo) {
    split_pair(a.x, a.y, hi.x, lo.x);
    split_pair(a.z, a.w, hi.y, lo.y);
    split_pair(b.x, b.y, hi.z, lo.z);
    split_pair(b.z, b.w, hi.w, lo.w);
}

// FFMA-pipe exp (args <= 0 here)
__device__ __forceinline__ float fexp(float x) {
    float y = x * 1.4426950408889634f;
    float t = y + 12582912.0f;
    float n = t - 12582912.0f;
    float f = y - n;
    float p = 1.3333558146e-3f;
    p = fmaf(p, f, 9.6181291076e-3f);
    p = fmaf(p, f, 5.5504108664e-2f);
    p = fmaf(p, f, 2.4022650696e-1f);
    p = fmaf(p, f, 6.9314718056e-1f);
    p = fmaf(p, f, 1.0f);
    return __int_as_float(__float_as_int(p) + (((int)n) << 23));
}

// SMEM: per buf 4 matrices (Ahi, Alo, Bhi, Blo), each 128 rows x 24 halves (48B)
#define MATB   6144u
#define BUFB   (4u * MATB)
#define SMEM_TOTAL (2 * BUFB)   // 49152

// ======================= generic HMMA GEMM NT =======================
// C[M,N] = A[M,K] @ Bm[N,K]^T.
// ASRC 0: A fp16 (Aptr=hi, Al=lo). ASRC 1: A fp32, full split in fill (3-pass only).
// NPASS 3: AhBh+AhBl+AlBh ; 2: AhBh+AhBl ; 1: AhBh only
// MODE 2: plain fp32 C ; MODE 3: write fp16 hi/lo (oh, ol)
template <int MODE, int NPASS, int ASRC>
__global__ __launch_bounds__(256, 2) void hmma_gemm(
    const void* __restrict__ Aptr, const __half* __restrict__ Al,
    const __half* __restrict__ Bh, const __half* __restrict__ Bl,
    float* __restrict__ C, __half* __restrict__ oh, __half* __restrict__ ol,
    int K, int ldc) {
    extern __shared__ __align__(128) char smem[];
    const uint32_t sb = smem_u32(smem);
    const int tid = threadIdx.x;
    const int wid = tid >> 5, lane = tid & 31;
    const size_t bm = (size_t)blockIdx.y * 128;
    const size_t bn = (size_t)blockIdx.x * 128;
    const int warp_m = (wid >> 1) * 32;
    const int warp_n = (wid & 1) * 64;

    float acc[2][8][4];
#pragma unroll
    for (int i = 0; i < 2; i++)
#pragma unroll
        for (int j = 0; j < 8; j++)
#pragma unroll
            for (int k = 0; k < 4; k++) acc[i][j][k] = 0.0f;

    const __half* Ahg = (ASRC == 0) ? ((const __half*)Aptr) + bm * K : nullptr;
    const __half* Alg = (ASRC == 0 && NPASS == 3) ? Al + bm * K : nullptr;
    const float*  Afg = (ASRC == 1) ? ((const float*)Aptr) + bm * K : nullptr;
    const __half* Bhg = Bh + bn * K;
    const __half* Blg = (NPASS >= 2) ? Bl + bn * K : nullptr;
    const int NC = K >> 4;

    const int f_r = tid >> 1;
    const int f_s = (tid & 1) << 3;
    const uint32_t soff = (uint32_t)(f_r * 48 + (tid & 1) * 16);

    // ---- prologue ----
    {
        if (ASRC == 0) {
            *(uint4*)(smem + soff) = *(const uint4*)(Ahg + (size_t)f_r * K + f_s);
            if (NPASS == 3)
                *(uint4*)(smem + MATB + soff) = *(const uint4*)(Alg + (size_t)f_r * K + f_s);
        } else {
            float4 a0 = *(const float4*)(Afg + (size_t)f_r * K + f_s);
            float4 a1 = *(const float4*)(Afg + (size_t)f_r * K + f_s + 4);
            uint4 hi, lo;
            cvt8(a0, a1, hi, lo);
            *(uint4*)(smem + soff) = hi;
            *(uint4*)(smem + MATB + soff) = lo;
        }
        *(uint4*)(smem + 2 * MATB + soff) = *(const uint4*)(Bhg + (size_t)f_r * K + f_s);
        if (NPASS >= 2)
            *(uint4*)(smem + 3 * MATB + soff) = *(const uint4*)(Blg + (size_t)f_r * K + f_s);
    }
    __syncthreads();

    const int a_row = lane & 15;
    const int a_kb = ((lane >> 4) << 3) * 2;
    const int b_n = ((lane >> 4) << 3) + (lane & 7);
    const int b_kb = (lane & 8) * 2;

    uint4 pah, pal, pbh, pbl;
    float4 pfa0, pfa1;
    for (int c = 0; c < NC; ++c) {
        const int buf = c & 1;
        const uint32_t base = sb + buf * BUFB;

        if (c + 1 < NC) {
            const int k0 = (c + 1) << 4;
            if (ASRC == 0) {
                pah = *(const uint4*)(Ahg + (size_t)f_r * K + k0 + f_s);
                if (NPASS == 3) pal = *(const uint4*)(Alg + (size_t)f_r * K + k0 + f_s);
            } else {
                pfa0 = *(const float4*)(Afg + (size_t)f_r * K + k0 + f_s);
                pfa1 = *(const float4*)(Afg + (size_t)f_r * K + k0 + f_s + 4);
            }
            pbh = *(const uint4*)(Bhg + (size_t)f_r * K + k0 + f_s);
            if (NPASS >= 2) pbl = *(const uint4*)(Blg + (size_t)f_r * K + k0 + f_s);
        }

        uint32_t ah[2][4], al[2][4];
#pragma unroll
        for (int i = 0; i < 2; i++) {
            uint32_t ra = base + (uint32_t)((warp_m + i * 16 + a_row) * 48) + a_kb;
            LDSM4(ah[i], ra);
            if (NPASS == 3) LDSM4(al[i], ra + MATB);
        }
#pragma unroll
        for (int jp = 0; jp < 4; jp++) {
            uint32_t rb = base + 2 * MATB +
                          (uint32_t)((warp_n + jp * 16 + b_n) * 48) + b_kb;
            uint32_t bh[4], bl[4];
            LDSM4(bh, rb);
            if (NPASS >= 2) LDSM4(bl, rb + MATB);
#pragma unroll
            for (int i = 0; i < 2; i++) {
                MMA16816(acc[i][jp * 2 + 0], ah[i], bh[0], bh[1]);
                if (NPASS >= 2) MMA16816(acc[i][jp * 2 + 0], ah[i], bl[0], bl[1]);
                if (NPASS == 3) MMA16816(acc[i][jp * 2 + 0], al[i], bh[0], bh[1]);
                MMA16816(acc[i][jp * 2 + 1], ah[i], bh[2], bh[3]);
                if (NPASS >= 2) MMA16816(acc[i][jp * 2 + 1], ah[i], bl[2], bl[3]);
                if (NPASS == 3) MMA16816(acc[i][jp * 2 + 1], al[i], bh[2], bh[3]);
            }
        }

        if (c + 1 < NC) {
            const uint32_t nb = (buf ^ 1) * BUFB;
            if (ASRC == 0) {
                *(uint4*)(smem + nb + soff) = pah;
                if (NPASS == 3) *(uint4*)(smem + nb + MATB + soff) = pal;
            } else {
                uint4 hi, lo;
                cvt8(pfa0, pfa1, hi, lo);
                *(uint4*)(smem + nb + soff) = hi;
                *(uint4*)(smem + nb + MATB + soff) = lo;
            }
            *(uint4*)(smem + nb + 2 * MATB + soff) = pbh;
            if (NPASS >= 2) *(uint4*)(smem + nb + 3 * MATB + soff) = pbl;
        }
        __syncthreads();
    }

    // ---- epilogue ----
    const int rbase = warp_m + (lane >> 2);
    const int cbase = warp_n + (lane & 3) * 2;
#pragma unroll
    for (int i = 0; i < 2; i++) {
#pragma unroll
        for (int h = 0; h < 2; h++) {
            const size_t row = bm + rbase + i * 16 + h * 8;
            if (MODE == 3) {
#pragma unroll
                for (int j = 0; j < 8; j++) {
                    const int cg = cbase + j * 8;
                    uint32_t hi, lo;
                    split_pair(acc[i][j][h * 2 + 0], acc[i][j][h * 2 + 1], hi, lo);
                    *(uint32_t*)(oh + row * (size_t)ldc + bn + cg) = hi;
                    *(uint32_t*)(ol + row * (size_t)ldc + bn + cg) = lo;
                }
            } else {
                float* crow = C + row * (size_t)ldc + bn;
#pragma unroll
                for (int j = 0; j < 8; j++) {
                    const int cg = cbase + j * 8;
                    *(float2*)(crow + cg) =
                        make_float2(acc[i][j][h * 2 + 0], acc[i][j][h * 2 + 1]);
                }
            }
        }
    }
}

// ======================= fused logits-raw + zsq kernel =======================
// grid (12, BATCH/128): x<8 -> Q-tile: Sraw = x.q (3-pass)
//                       x>=8 -> W-tile: zsq += |x.w + b|^2 (1-pass)
__global__ __launch_bounds__(256, 2) void fused_logits_zsq(
    const __half* __restrict__ xh, const __half* __restrict__ xl,
    const __half* __restrict__ Qh, const __half* __restrict__ Ql,
    const __half* __restrict__ Wh, const float* __restrict__ bias,
    float* __restrict__ Sraw, float* __restrict__ zsq) {
    extern __shared__ __align__(128) char smem[];
    const uint32_t sb = smem_u32(smem);
    const int tid = threadIdx.x;
    const int wid = tid >> 5, lane = tid & 31;
    const bool is_w = blockIdx.x >= 8;
    const size_t bm = (size_t)blockIdx.y * 128;
    const size_t bn = is_w ? (size_t)(blockIdx.x - 8) * 128 : (size_t)blockIdx.x * 128;
    const int warp_m = (wid >> 1) * 32;
    const int warp_n = (wid & 1) * 64;
    const int K = DIM, NC = DIM >> 4;

    float acc[2][8][4];
#pragma unroll
    for (int i = 0; i < 2; i++)
#pragma unroll
        for (int j = 0; j < 8; j++)
#pragma unroll
            for (int k = 0; k < 4; k++) acc[i][j][k] = 0.0f;

    const __half* Ahg = xh + bm * K;
    const __half* Alg = xl + bm * K;
    const __half* Bhg = (is_w ? Wh : Qh) + bn * K;
    const __half* Blg = (is_w ? Wh : Ql) + bn * K;  // dummy for W (never MMA'd)

    const int f_r = tid >> 1;
    const int f_s = (tid & 1) << 3;
    const uint32_t soff = (uint32_t)(f_r * 48 + (tid & 1) * 16);

    {
        *(uint4*)(smem + soff) = *(const uint4*)(Ahg + (size_t)f_r * K + f_s);
        *(uint4*)(smem + 2 * MATB + soff) = *(const uint4*)(Bhg + (size_t)f_r * K + f_s);
        if (!is_w) {
            *(uint4*)(smem + MATB + soff) = *(const uint4*)(Alg + (size_t)f_r * K + f_s);
            *(uint4*)(smem + 3 * MATB + soff) = *(const uint4*)(Blg + (size_t)f_r * K + f_s);
        }
    }
    __syncthreads();

    const int a_row = lane & 15;
    const int a_kb = ((lane >> 4) << 3) * 2;
    const int b_n = ((lane >> 4) << 3) + (lane & 7);
    const int b_kb = (lane & 8) * 2;

    uint4 pah, pal, pbh, pbl;
    for (int c = 0; c < NC; ++c) {
        const int buf = c & 1;
        const uint32_t base = sb + buf * BUFB;

        if (c + 1 < NC) {
            const int k0 = (c + 1) << 4;
            pah = *(const uint4*)(Ahg + (size_t)f_r * K + k0 + f_s);
            pbh = *(const uint4*)(Bhg + (size_t)f_r * K + k0 + f_s);
            if (!is_w) {
                pal = *(const uint4*)(Alg + (size_t)f_r * K + k0 + f_s);
                pbl = *(const uint4*)(Blg + (size_t)f_r * K + k0 + f_s);
            }
        }

        uint32_t ah[2][4], al[2][4];
#pragma unroll
        for (int i = 0; i < 2; i++) {
            uint32_t ra = base + (uint32_t)((warp_m + i * 16 + a_row) * 48) + a_kb;
            LDSM4(ah[i], ra);
            if (!is_w) LDSM4(al[i], ra + MATB);
        }
#pragma unroll
        for (int jp = 0; jp < 4; jp++) {
            uint32_t rb = base + 2 * MATB +
                          (uint32_t)((warp_n + jp * 16 + b_n) * 48) + b_kb;
            uint32_t bh[4], bl[4];
            LDSM4(bh, rb);
            if (!is_w) LDSM4(bl, rb + MATB);
#pragma unroll
            for (int i = 0; i < 2; i++) {
                MMA16816(acc[i][jp * 2 + 0], ah[i], bh[0], bh[1]);
                MMA16816(acc[i][jp * 2 + 1], ah[i], bh[2], bh[3]);
                if (!is_w) {
                    MMA16816(acc[i][jp * 2 + 0], ah[i], bl[0], bl[1]);
                    MMA16816(acc[i][jp * 2 + 0], al[i], bh[0], bh[1]);
                    MMA16816(acc[i][jp * 2 + 1], ah[i], bl[2], bl[3]);
                    MMA16816(acc[i][jp * 2 + 1], al[i], bh[2], bh[3]);
                }
            }
        }

        if (c + 1 < NC) {
            const uint32_t nb = (buf ^ 1) * BUFB;
            *(uint4*)(smem + nb + soff) = pah;
            *(uint4*)(smem + nb + 2 * MATB + soff) = pbh;
            if (!is_w) {
                *(uint4*)(smem + nb + MATB + soff) = pal;
                *(uint4*)(smem + nb + 3 * MATB + soff) = pbl;
            }
        }
        __syncthreads();
    }

    const int rbase = warp_m + (lane >> 2);
    const int cbase = warp_n + (lane & 3) * 2;
#pragma unroll
    for (int i = 0; i < 2; i++) {
#pragma unroll
        for (int h = 0; h < 2; h++) {
            const size_t row = bm + rbase + i * 16 + h * 8;
            if (is_w) {
                float s = 0.0f;
#pragma unroll
                for (int j = 0; j < 8; j++) {
                    const int cg = cbase + j * 8;
                    float v0 = acc[i][j][h * 2 + 0] + bias[bn + cg];
                    float v1 = acc[i][j][h * 2 + 1] + bias[bn + cg + 1];
                    s += v0 * v0 + v1 * v1;
                }
                s += __shfl_xor_sync(0xffffffffu, s, 1);
                s += __shfl_xor_sync(0xffffffffu, s, 2);
                if ((lane & 3) == 0) atomicAdd(zsq + row, s);
            } else {
                float* crow = Sraw + row * (size_t)NPROTO + bn;
#pragma unroll
                for (int j = 0; j < 8; j++) {
                    const int cg = cbase + j * 8;
                    *(float2*)(crow + cg) =
                        make_float2(acc[i][j][h * 2 + 0], acc[i][j][h * 2 + 1]);
                }
            }
        }
    }
}

// ======================= small kernels =======================
__device__ __forceinline__ float wsum(float v) {
#pragma unroll
    for (int o = 16; o; o >>= 1) v += __shfl_xor_sync(0xffffffffu, v, o);
    return v;
}
__device__ __forceinline__ float wmax(float v) {
#pragma unroll
    for (int o = 16; o; o >>= 1) v = fmaxf(v, __shfl_xor_sync(0xffffffffu, v, o));
    return v;
}

// psq2[row] = sum(P[row]^2) - 2 * dot(P[row], b)
__global__ __launch_bounds__(128) void row_psq2(const float* __restrict__ P,
                                                const float* __restrict__ b,
                                                float* __restrict__ out) {
    size_t row = blockIdx.x;
    const float4* p = (const float4*)(P + row * 512);
    float4 v = p[threadIdx.x];
    float4 bb = ((const float4*)b)[threadIdx.x];
    float s = v.x * v.x + v.y * v.y + v.z * v.z + v.w * v.w
            - 2.0f * (v.x * bb.x + v.y * bb.y + v.z * bb.z + v.w * bb.w);
    s = wsum(s);
    __shared__ float red[4];
    if ((threadIdx.x & 31) == 0) red[threadIdx.x >> 5] = s;
    __syncthreads();
    if (threadIdx.x == 0) out[row] = red[0] + red[1] + red[2] + red[3];
}

// dist + softmax over rows of 1024; reads raw dot, writes fp32 weights + fp16 hi
__global__ __launch_bounds__(256) void softmax_dist_1024(
    float* __restrict__ Wt, const float* __restrict__ zsq,
    const float* __restrict__ psq2, const float* __restrict__ temp_raw,
    __half* __restrict__ wh) {
    size_t row = blockIdx.x;
    float4* p = (float4*)(Wt + row * 1024);
    float4 s4 = p[threadIdx.x];
    float4 pq = ((const float4*)psq2)[threadIdx.x];
    float zr = zsq[row];
    float t = temp_raw[0];
    float temp = 1.0f / (1.0f + expf(-t)) * 0.999f + 0.001f;
    float invt = 1.0f / temp;

    float4 v;
    v.x = -sqrtf(fmaxf(zr + pq.x - 2.0f * s4.x, 1e-12f)) * invt;
    v.y = -sqrtf(fmaxf(zr + pq.y - 2.0f * s4.y, 1e-12f)) * invt;
    v.z = -sqrtf(fmaxf(zr + pq.z - 2.0f * s4.z, 1e-12f)) * invt;
    v.w = -sqrtf(fmaxf(zr + pq.w - 2.0f * s4.w, 1e-12f)) * invt;

    __shared__ float red[8];
    float m = fmaxf(fmaxf(v.x, v.y), fmaxf(v.z, v.w));
    m = wmax(m);
    if ((threadIdx.x & 31) == 0) red[threadIdx.x >> 5] = m;
    __syncthreads();
    if (threadIdx.x < 32) {
        float q = (threadIdx.x < 8) ? red[threadIdx.x] : -INFINITY;
        q = wmax(q);
        if (threadIdx.x == 0) red[0] = q;
    }
    __syncthreads();
    m = red[0];
    __syncthreads();

    v.x = fexp(v.x - m); v.y = fexp(v.y - m);
    v.z = fexp(v.z - m); v.w = fexp(v.w - m);
    float s = v.x + v.y + v.z + v.w;
    s = wsum(s);
    __shared__ float red2[8];
    if ((threadIdx.x & 31) == 0) red2[threadIdx.x >> 5] = s;
    __syncthreads();
    if (threadIdx.x < 32) {
        float q = (threadIdx.x < 8) ? red2[threadIdx.x] : 0.0f;
        q = wsum(q);
        if (threadIdx.x == 0) red2[0] = q;
    }
    __syncthreads();
    float inv = 1.0f / red2[0];
    v.x *= inv; v.y *= inv; v.z *= inv; v.w *= inv;
    p[threadIdx.x] = v;

    __half2 h0 = __floats2half2_rn(v.x, v.y);
    __half2 h1 = __floats2half2_rn(v.z, v.w);
    *(uint2*)(wh + row * 1024 + threadIdx.x * 4) =
        make_uint2(*(uint32_t*)&h0, *(uint32_t*)&h1);
}

// split fp32 array into fp16 hi/lo
__global__ __launch_bounds__(256) void split_mat(const float4* __restrict__ src,
                                                 uint2* __restrict__ hi,
                                                 uint2* __restrict__ lo, int n4) {
    int i = blockIdx.x * 256 + threadIdx.x;
    if (i >= n4) return;
    float4 v = src[i];
    uint32_t h0, l0, h1, l1;
    split_pair(v.x, v.y, h0, l0);
    split_pair(v.z, v.w, h1, l1);
    hi[i] = make_uint2(h0, h1);
    lo[i] = make_uint2(l0, l1);
}

// transpose + split: src [rows, cols] fp32 -> dst [cols, rows] fp16 hi/lo
__global__ __launch_bounds__(256) void transpose_split(const float* __restrict__ src,
                                                       __half* __restrict__ dh,
                                                       __half* __restrict__ dl,
                                                       int rows, int cols) {
    __shared__ float t[32][33];
    int bx = blockIdx.x * 32;
    int by = blockIdx.y * 32;
    int tx = threadIdx.x & 31, ty = (threadIdx.x >> 5) * 4;
#pragma unroll
    for (int i = 0; i < 4; i++)
        t[ty + i][tx] = src[(size_t)(by + ty + i) * cols + bx + tx];
    __syncthreads();
#pragma unroll
    for (int i = 0; i < 4; i++) {
        float v = t[tx][ty + i];
        __half hv = __float2half_rn(v);
        size_t off = (size_t)(bx + ty + i) * rows + by + tx;
        dh[off] = hv;
        dl[off] = __float2half_rn(v - __half2float(hv));
    }
}

extern "C" void kernel_launch(void* const* d_in, const int* in_sizes, int n_in,
                              void* d_out, int out_size) {
    const float* x  = (const float*)d_in[0];
    const float* W  = (const float*)d_in[1];
    const float* b  = (const float*)d_in[2];
    const float* P  = (const float*)d_in[3];
    const float* tr = (const float*)d_in[4];

    float* blended = (float*)d_out;
    float* weights = (float*)d_out + (size_t)BATCH * DIM;

    __half *xh, *xl, *Wh, *Wl, *WTh, *WTl, *PTh, *PTl, *Qh, *Ql, *wh;
    float *zsq, *psq2;
    cudaGetSymbolAddress((void**)&xh, g_xh);   cudaGetSymbolAddress((void**)&xl, g_xl);
    cudaGetSymbolAddress((void**)&Wh, g_Wh);   cudaGetSymbolAddress((void**)&Wl, g_Wl);
    cudaGetSymbolAddress((void**)&WTh, g_WTh); cudaGetSymbolAddress((void**)&WTl, g_WTl);
    cudaGetSymbolAddress((void**)&PTh, g_PTh); cudaGetSymbolAddress((void**)&PTl, g_PTl);
    cudaGetSymbolAddress((void**)&Qh, g_Qh);   cudaGetSymbolAddress((void**)&Ql, g_Ql);
    cudaGetSymbolAddress((void**)&wh, g_wh);
    cudaGetSymbolAddress((void**)&zsq, g_zsq); cudaGetSymbolAddress((void**)&psq2, g_psq2);

    cudaFuncSetAttribute((const void*)hmma_gemm<3, 3, 1>, cudaFuncAttributeMaxDynamicSharedMemorySize, SMEM_TOTAL);
    cudaFuncSetAttribute((const void*)hmma_gemm<2, 1, 0>, cudaFuncAttributeMaxDynamicSharedMemorySize, SMEM_TOTAL);
    cudaFuncSetAttribute((const void*)fused_logits_zsq, cudaFuncAttributeMaxDynamicSharedMemorySize, SMEM_TOTAL);

    cudaMemsetAsync(zsq, 0, BATCH * sizeof(float));

    // psq2 = |p|^2 - 2 p.b
    row_psq2<<<NPROTO, 128>>>(P, b, psq2);

    // operand prep
    split_mat<<<(BATCH * DIM / 4 + 255) / 256, 256>>>((const float4*)x, (uint2*)xh, (uint2*)xl, BATCH * DIM / 4);
    split_mat<<<(DIM * DIM / 4 + 255) / 256, 256>>>((const float4*)W, (uint2*)Wh, (uint2*)Wl, DIM * DIM / 4);
    transpose_split<<<dim3(16, 16), 256>>>(W, WTh, WTl, DIM, DIM);
    transpose_split<<<dim3(16, 32), 256>>>(P, PTh, PTl, NPROTO, DIM);

    // Q = P @ W (3-pass, A=P fp32 split in fill), write fp16 hi/lo
    hmma_gemm<3, 3, 1><<<dim3(DIM / 128, NPROTO / 128), 256, SMEM_TOTAL>>>(
        P, nullptr, WTh, WTl, nullptr, Qh, Ql, DIM, DIM);

    // fused: Sraw = x.q^T (3-pass) + zsq = |x.W^T + b|^2 (1-pass)
    fused_logits_zsq<<<dim3(12, BATCH / 128), 256, SMEM_TOTAL>>>(
        xh, xl, Qh, Ql, Wh, b, weights, zsq);

    // dist + softmax; writes fp32 weights + fp16 wh
    softmax_dist_1024<<<BATCH, 256>>>(weights, zsq, psq2, tr, wh);

    // blended = weights @ P (1-pass: wh x PTh only)
    hmma_gemm<2, 1, 0><<<dim3(DIM / 128, BATCH / 128), 256, SMEM_TOTAL>>>(
        wh, nullptr, PTh, PTh, blended, nullptr, nullptr, NPROTO, DIM);
}

// round 11
// speedup vs baseline: 3.3182x; 1.1607x over previous
#include <cuda_runtime.h>
#include <cuda_fp16.h>
#include <math.h>
#include <stdint.h>

#define BATCH  65536
#define DIM    512
#define NPROTO 1024

// ---------------- device scratch ----------------
__device__ __half g_xh[(size_t)BATCH * DIM];
__device__ __half g_Wh[(size_t)DIM * DIM];
__device__ __half g_WTh[(size_t)DIM * DIM],    g_WTl[(size_t)DIM * DIM];
__device__ __half g_PTh[(size_t)DIM * NPROTO];
__device__ __half g_Qh[(size_t)NPROTO * DIM],  g_Ql[(size_t)NPROTO * DIM];
__device__ __half g_wh[(size_t)BATCH * NPROTO];
__device__ float g_zsq[BATCH];
__device__ float g_psq2[NPROTO];   // psq - 2*P.b

// ======================= helpers =======================
__device__ __forceinline__ uint32_t smem_u32(const void* p) {
    uint32_t a;
    asm("{ .reg .u64 t; cvta.to.shared.u64 t, %1; cvt.u32.u64 %0, t; }" : "=r"(a) : "l"(p));
    return a;
}

#define LDSM4(r, addr) \
    asm volatile("ldmatrix.sync.aligned.m8n8.x4.shared.b16 {%0,%1,%2,%3}, [%4];" \
        : "=r"((r)[0]), "=r"((r)[1]), "=r"((r)[2]), "=r"((r)[3]) : "r"(addr))

#define MMA16816(d, a, b0, b1) \
    asm volatile("mma.sync.aligned.m16n8k16.row.col.f32.f16.f16.f32 " \
        "{%0,%1,%2,%3}, {%4,%5,%6,%7}, {%8,%9}, {%0,%1,%2,%3};" \
        : "+f"((d)[0]), "+f"((d)[1]), "+f"((d)[2]), "+f"((d)[3]) \
        : "r"((a)[0]), "r"((a)[1]), "r"((a)[2]), "r"((a)[3]), "r"(b0), "r"(b1))

__device__ __forceinline__ void split_pair(float x, float y, uint32_t& hi, uint32_t& lo) {
    __half hx = __float2half_rn(x), hy = __float2half_rn(y);
    __half2 h2 = __halves2half2(hx, hy);
    hi = *(uint32_t*)&h2;
    __half2 l2 = __floats2half2_rn(x - __half2float(hx), y - __half2float(hy));
    lo = *(uint32_t*)&l2;
}
__device__ __forceinline__ void cvt8(const float4& a, const float4& b,
                                     uint4& hi, uint4& lo) {
    split_pair(a.x, a.y, hi.x, lo.x);
    split_pair(a.z, a.w, hi.y, lo.y);
    split_pair(b.x, b.y, hi.z, lo.z);
    split_pair(b.z, b.w, hi.w, lo.w);
}

// FFMA-pipe exp (args <= 0 here)
__device__ __forceinline__ float fexp(float x) {
    float y = x * 1.4426950408889634f;
    float t = y + 12582912.0f;
    float n = t - 12582912.0f;
    float f = y - n;
    float p = 1.3333558146e-3f;
    p = fmaf(p, f, 9.6181291076e-3f);
    p = fmaf(p, f, 5.5504108664e-2f);
    p = fmaf(p, f, 2.4022650696e-1f);
    p = fmaf(p, f, 6.9314718056e-1f);
    p = fmaf(p, f, 1.0f);
    return __int_as_float(__float_as_int(p) + (((int)n) << 23));
}

// SMEM: per buf 4 matrices (Ahi, Alo, Bhi, Blo), each 128 rows x 24 halves (48B)
#define MATB   6144u
#define BUFB   (4u * MATB)
#define SMEM_TOTAL (2 * BUFB)   // 49152

// ======================= generic HMMA GEMM NT =======================
// C[M,N] = A[M,K] @ Bm[N,K]^T.
// ASRC 0: A fp16 (Aptr=hi). ASRC 1: A fp32, full split in fill (3-pass only).
// NPASS 3: AhBh+AhBl+AlBh ; 1: AhBh only
// MODE 2: plain fp32 C ; MODE 3: write fp16 hi/lo (oh, ol)
template <int MODE, int NPASS, int ASRC>
__global__ __launch_bounds__(256, 2) void hmma_gemm(
    const void* __restrict__ Aptr,
    const __half* __restrict__ Bh, const __half* __restrict__ Bl,
    float* __restrict__ C, __half* __restrict__ oh, __half* __restrict__ ol,
    int K, int ldc) {
    extern __shared__ __align__(128) char smem[];
    const uint32_t sb = smem_u32(smem);
    const int tid = threadIdx.x;
    const int wid = tid >> 5, lane = tid & 31;
    const size_t bm = (size_t)blockIdx.y * 128;
    const size_t bn = (size_t)blockIdx.x * 128;
    const int warp_m = (wid >> 1) * 32;
    const int warp_n = (wid & 1) * 64;

    float acc[2][8][4];
#pragma unroll
    for (int i = 0; i < 2; i++)
#pragma unroll
        for (int j = 0; j < 8; j++)
#pragma unroll
            for (int k = 0; k < 4; k++) acc[i][j][k] = 0.0f;

    const __half* Ahg = (ASRC == 0) ? ((const __half*)Aptr) + bm * K : nullptr;
    const float*  Afg = (ASRC == 1) ? ((const float*)Aptr) + bm * K : nullptr;
    const __half* Bhg = Bh + bn * K;
    const __half* Blg = (NPASS >= 2) ? Bl + bn * K : nullptr;
    const int NC = K >> 4;

    const int f_r = tid >> 1;
    const int f_s = (tid & 1) << 3;
    const uint32_t soff = (uint32_t)(f_r * 48 + (tid & 1) * 16);

    // ---- prologue ----
    {
        if (ASRC == 0) {
            *(uint4*)(smem + soff) = *(const uint4*)(Ahg + (size_t)f_r * K + f_s);
        } else {
            float4 a0 = *(const float4*)(Afg + (size_t)f_r * K + f_s);
            float4 a1 = *(const float4*)(Afg + (size_t)f_r * K + f_s + 4);
            uint4 hi, lo;
            cvt8(a0, a1, hi, lo);
            *(uint4*)(smem + soff) = hi;
            *(uint4*)(smem + MATB + soff) = lo;
        }
        *(uint4*)(smem + 2 * MATB + soff) = *(const uint4*)(Bhg + (size_t)f_r * K + f_s);
        if (NPASS >= 2)
            *(uint4*)(smem + 3 * MATB + soff) = *(const uint4*)(Blg + (size_t)f_r * K + f_s);
    }
    __syncthreads();

    const int a_row = lane & 15;
    const int a_kb = ((lane >> 4) << 3) * 2;
    const int b_n = ((lane >> 4) << 3) + (lane & 7);
    const int b_kb = (lane & 8) * 2;

    uint4 pah, pbh, pbl;
    float4 pfa0, pfa1;
    for (int c = 0; c < NC; ++c) {
        const int buf = c & 1;
        const uint32_t base = sb + buf * BUFB;

        if (c + 1 < NC) {
            const int k0 = (c + 1) << 4;
            if (ASRC == 0) {
                pah = *(const uint4*)(Ahg + (size_t)f_r * K + k0 + f_s);
            } else {
                pfa0 = *(const float4*)(Afg + (size_t)f_r * K + k0 + f_s);
                pfa1 = *(const float4*)(Afg + (size_t)f_r * K + k0 + f_s + 4);
            }
            pbh = *(const uint4*)(Bhg + (size_t)f_r * K + k0 + f_s);
            if (NPASS >= 2) pbl = *(const uint4*)(Blg + (size_t)f_r * K + k0 + f_s);
        }

        uint32_t ah[2][4], al[2][4];
#pragma unroll
        for (int i = 0; i < 2; i++) {
            uint32_t ra = base + (uint32_t)((warp_m + i * 16 + a_row) * 48) + a_kb;
            LDSM4(ah[i], ra);
            if (NPASS == 3) LDSM4(al[i], ra + MATB);
        }
#pragma unroll
        for (int jp = 0; jp < 4; jp++) {
            uint32_t rb = base + 2 * MATB +
                          (uint32_t)((warp_n + jp * 16 + b_n) * 48) + b_kb;
            uint32_t bh[4], bl[4];
            LDSM4(bh, rb);
            if (NPASS >= 2) LDSM4(bl, rb + MATB);
#pragma unroll
            for (int i = 0; i < 2; i++) {
                MMA16816(acc[i][jp * 2 + 0], ah[i], bh[0], bh[1]);
                if (NPASS >= 2) MMA16816(acc[i][jp * 2 + 0], ah[i], bl[0], bl[1]);
                if (NPASS == 3) MMA16816(acc[i][jp * 2 + 0], al[i], bh[0], bh[1]);
                MMA16816(acc[i][jp * 2 + 1], ah[i], bh[2], bh[3]);
                if (NPASS >= 2) MMA16816(acc[i][jp * 2 + 1], ah[i], bl[2], bl[3]);
                if (NPASS == 3) MMA16816(acc[i][jp * 2 + 1], al[i], bh[2], bh[3]);
            }
        }

        if (c + 1 < NC) {
            const uint32_t nb = (buf ^ 1) * BUFB;
            if (ASRC == 0) {
                *(uint4*)(smem + nb + soff) = pah;
            } else {
                uint4 hi, lo;
                cvt8(pfa0, pfa1, hi, lo);
                *(uint4*)(smem + nb + soff) = hi;
                *(uint4*)(smem + nb + MATB + soff) = lo;
            }
            *(uint4*)(smem + nb + 2 * MATB + soff) = pbh;
            if (NPASS >= 2) *(uint4*)(smem + nb + 3 * MATB + soff) = pbl;
        }
        __syncthreads();
    }

    // ---- epilogue ----
    const int rbase = warp_m + (lane >> 2);
    const int cbase = warp_n + (lane & 3) * 2;
#pragma unroll
    for (int i = 0; i < 2; i++) {
#pragma unroll
        for (int h = 0; h < 2; h++) {
            const size_t row = bm + rbase + i * 16 + h * 8;
            if (MODE == 3) {
#pragma unroll
                for (int j = 0; j < 8; j++) {
                    const int cg = cbase + j * 8;
                    uint32_t hi, lo;
                    split_pair(acc[i][j][h * 2 + 0], acc[i][j][h * 2 + 1], hi, lo);
                    *(uint32_t*)(oh + row * (size_t)ldc + bn + cg) = hi;
                    *(uint32_t*)(ol + row * (size_t)ldc + bn + cg) = lo;
                }
            } else {
                float* crow = C + row * (size_t)ldc + bn;
#pragma unroll
                for (int j = 0; j < 8; j++) {
                    const int cg = cbase + j * 8;
                    *(float2*)(crow + cg) =
                        make_float2(acc[i][j][h * 2 + 0], acc[i][j][h * 2 + 1]);
                }
            }
        }
    }
}

// ======================= fused logits-raw + zsq kernel =======================
// grid (12, BATCH/128): x<8 -> Q-tile: Sraw = x.q (2-pass: xh.Qh + xh.Ql)
//                       x>=8 -> W-tile: zsq += |x.w + b|^2 (1-pass)
__global__ __launch_bounds__(256, 2) void fused_logits_zsq(
    const __half* __restrict__ xh,
    const __half* __restrict__ Qh, const __half* __restrict__ Ql,
    const __half* __restrict__ Wh, const float* __restrict__ bias,
    float* __restrict__ Sraw, float* __restrict__ zsq) {
    extern __shared__ __align__(128) char smem[];
    const uint32_t sb = smem_u32(smem);
    const int tid = threadIdx.x;
    const int wid = tid >> 5, lane = tid & 31;
    const bool is_w = blockIdx.x >= 8;
    const size_t bm = (size_t)blockIdx.y * 128;
    const size_t bn = is_w ? (size_t)(blockIdx.x - 8) * 128 : (size_t)blockIdx.x * 128;
    const int warp_m = (wid >> 1) * 32;
    const int warp_n = (wid & 1) * 64;
    const int K = DIM, NC = DIM >> 4;

    float acc[2][8][4];
#pragma unroll
    for (int i = 0; i < 2; i++)
#pragma unroll
        for (int j = 0; j < 8; j++)
#pragma unroll
            for (int k = 0; k < 4; k++) acc[i][j][k] = 0.0f;

    const __half* Ahg = xh + bm * K;
    const __half* Bhg = (is_w ? Wh : Qh) + bn * K;
    const __half* Blg = (is_w ? Wh : Ql) + bn * K;  // dummy for W (never MMA'd)

    const int f_r = tid >> 1;
    const int f_s = (tid & 1) << 3;
    const uint32_t soff = (uint32_t)(f_r * 48 + (tid & 1) * 16);

    {
        *(uint4*)(smem + soff) = *(const uint4*)(Ahg + (size_t)f_r * K + f_s);
        *(uint4*)(smem + 2 * MATB + soff) = *(const uint4*)(Bhg + (size_t)f_r * K + f_s);
        if (!is_w)
            *(uint4*)(smem + 3 * MATB + soff) = *(const uint4*)(Blg + (size_t)f_r * K + f_s);
    }
    __syncthreads();

    const int a_row = lane & 15;
    const int a_kb = ((lane >> 4) << 3) * 2;
    const int b_n = ((lane >> 4) << 3) + (lane & 7);
    const int b_kb = (lane & 8) * 2;

    uint4 pah, pbh, pbl;
    for (int c = 0; c < NC; ++c) {
        const int buf = c & 1;
        const uint32_t base = sb + buf * BUFB;

        if (c + 1 < NC) {
            const int k0 = (c + 1) << 4;
            pah = *(const uint4*)(Ahg + (size_t)f_r * K + k0 + f_s);
            pbh = *(const uint4*)(Bhg + (size_t)f_r * K + k0 + f_s);
            if (!is_w) pbl = *(const uint4*)(Blg + (size_t)f_r * K + k0 + f_s);
        }

        uint32_t ah[2][4];
#pragma unroll
        for (int i = 0; i < 2; i++) {
            uint32_t ra = base + (uint32_t)((warp_m + i * 16 + a_row) * 48) + a_kb;
            LDSM4(ah[i], ra);
        }
#pragma unroll
        for (int jp = 0; jp < 4; jp++) {
            uint32_t rb = base + 2 * MATB +
                          (uint32_t)((warp_n + jp * 16 + b_n) * 48) + b_kb;
            uint32_t bh[4], bl[4];
            LDSM4(bh, rb);
            if (!is_w) LDSM4(bl, rb + MATB);
#pragma unroll
            for (int i = 0; i < 2; i++) {
                MMA16816(acc[i][jp * 2 + 0], ah[i], bh[0], bh[1]);
                MMA16816(acc[i][jp * 2 + 1], ah[i], bh[2], bh[3]);
                if (!is_w) {
                    MMA16816(acc[i][jp * 2 + 0], ah[i], bl[0], bl[1]);
                    MMA16816(acc[i][jp * 2 + 1], ah[i], bl[2], bl[3]);
                }
            }
        }

        if (c + 1 < NC) {
            const uint32_t nb = (buf ^ 1) * BUFB;
            *(uint4*)(smem + nb + soff) = pah;
            *(uint4*)(smem + nb + 2 * MATB + soff) = pbh;
            if (!is_w) *(uint4*)(smem + nb + 3 * MATB + soff) = pbl;
        }
        __syncthreads();
    }

    const int rbase = warp_m + (lane >> 2);
    const int cbase = warp_n + (lane & 3) * 2;
#pragma unroll
    for (int i = 0; i < 2; i++) {
#pragma unroll
        for (int h = 0; h < 2; h++) {
            const size_t row = bm + rbase + i * 16 + h * 8;
            if (is_w) {
                float s = 0.0f;
#pragma unroll
                for (int j = 0; j < 8; j++) {
                    const int cg = cbase + j * 8;
                    float v0 = acc[i][j][h * 2 + 0] + bias[bn + cg];
                    float v1 = acc[i][j][h * 2 + 1] + bias[bn + cg + 1];
                    s += v0 * v0 + v1 * v1;
                }
                s += __shfl_xor_sync(0xffffffffu, s, 1);
                s += __shfl_xor_sync(0xffffffffu, s, 2);
                if ((lane & 3) == 0) atomicAdd(zsq + row, s);
            } else {
                float* crow = Sraw + row * (size_t)NPROTO + bn;
#pragma unroll
                for (int j = 0; j < 8; j++) {
                    const int cg = cbase + j * 8;
                    *(float2*)(crow + cg) =
                        make_float2(acc[i][j][h * 2 + 0], acc[i][j][h * 2 + 1]);
                }
            }
        }
    }
}

// ======================= small kernels =======================
__device__ __forceinline__ float wsum(float v) {
#pragma unroll
    for (int o = 16; o; o >>= 1) v += __shfl_xor_sync(0xffffffffu, v, o);
    return v;
}
__device__ __forceinline__ float wmax(float v) {
#pragma unroll
    for (int o = 16; o; o >>= 1) v = fmaxf(v, __shfl_xor_sync(0xffffffffu, v, o));
    return v;
}

// psq2[row] = sum(P[row]^2) - 2 * dot(P[row], b)
__global__ __launch_bounds__(128) void row_psq2(const float* __restrict__ P,
                                                const float* __restrict__ b,
                                                float* __restrict__ out) {
    size_t row = blockIdx.x;
    const float4* p = (const float4*)(P + row * 512);
    float4 v = p[threadIdx.x];
    float4 bb = ((const float4*)b)[threadIdx.x];
    float s = v.x * v.x + v.y * v.y + v.z * v.z + v.w * v.w
            - 2.0f * (v.x * bb.x + v.y * bb.y + v.z * bb.z + v.w * bb.w);
    s = wsum(s);
    __shared__ float red[4];
    if ((threadIdx.x & 31) == 0) red[threadIdx.x >> 5] = s;
    __syncthreads();
    if (threadIdx.x == 0) out[row] = red[0] + red[1] + red[2] + red[3];
}

// dist + softmax over rows of 1024; reads raw dot, writes fp32 weights + fp16 hi
__global__ __launch_bounds__(256) void softmax_dist_1024(
    float* __restrict__ Wt, const float* __restrict__ zsq,
    const float* __restrict__ psq2, const float* __restrict__ temp_raw,
    __half* __restrict__ wh) {
    size_t row = blockIdx.x;
    float4* p = (float4*)(Wt + row * 1024);
    float4 s4 = p[threadIdx.x];
    float4 pq = ((const float4*)psq2)[threadIdx.x];
    float zr = zsq[row];
    float t = temp_raw[0];
    float temp = 1.0f / (1.0f + expf(-t)) * 0.999f + 0.001f;
    float invt = 1.0f / temp;

    float4 v;
    v.x = -sqrtf(fmaxf(zr + pq.x - 2.0f * s4.x, 1e-12f)) * invt;
    v.y = -sqrtf(fmaxf(zr + pq.y - 2.0f * s4.y, 1e-12f)) * invt;
    v.z = -sqrtf(fmaxf(zr + pq.z - 2.0f * s4.z, 1e-12f)) * invt;
    v.w = -sqrtf(fmaxf(zr + pq.w - 2.0f * s4.w, 1e-12f)) * invt;

    __shared__ float red[8];
    float m = fmaxf(fmaxf(v.x, v.y), fmaxf(v.z, v.w));
    m = wmax(m);
    if ((threadIdx.x & 31) == 0) red[threadIdx.x >> 5] = m;
    __syncthreads();
    if (threadIdx.x < 32) {
        float q = (threadIdx.x < 8) ? red[threadIdx.x] : -INFINITY;
        q = wmax(q);
        if (threadIdx.x == 0) red[0] = q;
    }
    __syncthreads();
    m = red[0];
    __syncthreads();

    v.x = fexp(v.x - m); v.y = fexp(v.y - m);
    v.z = fexp(v.z - m); v.w = fexp(v.w - m);
    float s = v.x + v.y + v.z + v.w;
    s = wsum(s);
    __shared__ float red2[8];
    if ((threadIdx.x & 31) == 0) red2[threadIdx.x >> 5] = s;
    __syncthreads();
    if (threadIdx.x < 32) {
        float q = (threadIdx.x < 8) ? red2[threadIdx.x] : 0.0f;
        q = wsum(q);
        if (threadIdx.x == 0) red2[0] = q;
    }
    __syncthreads();
    float inv = 1.0f / red2[0];
    v.x *= inv; v.y *= inv; v.z *= inv; v.w *= inv;
    p[threadIdx.x] = v;

    __half2 h0 = __floats2half2_rn(v.x, v.y);
    __half2 h1 = __floats2half2_rn(v.z, v.w);
    *(uint2*)(wh + row * 1024 + threadIdx.x * 4) =
        make_uint2(*(uint32_t*)&h0, *(uint32_t*)&h1);
}

// convert fp32 array to fp16 (hi only)
__global__ __launch_bounds__(256) void split_hi(const float4* __restrict__ src,
                                                uint2* __restrict__ hi, int n4) {
    int i = blockIdx.x * 256 + threadIdx.x;
    if (i >= n4) return;
    float4 v = src[i];
    __half2 h0 = __floats2half2_rn(v.x, v.y);
    __half2 h1 = __floats2half2_rn(v.z, v.w);
    hi[i] = make_uint2(*(uint32_t*)&h0, *(uint32_t*)&h1);
}

// split fp32 array into fp16 hi/lo
__global__ __launch_bounds__(256) void split_mat(const float4* __restrict__ src,
                                                 uint2* __restrict__ hi,
                                                 uint2* __restrict__ lo, int n4) {
    int i = blockIdx.x * 256 + threadIdx.x;
    if (i >= n4) return;
    float4 v = src[i];
    uint32_t h0, l0, h1, l1;
    split_pair(v.x, v.y, h0, l0);
    split_pair(v.z, v.w, h1, l1);
    hi[i] = make_uint2(h0, h1);
    lo[i] = make_uint2(l0, l1);
}

// transpose + split: src [rows, cols] fp32 -> dst [cols, rows] fp16 hi (+ optional lo)
__global__ __launch_bounds__(256) void transpose_split(const float* __restrict__ src,
                                                       __half* __restrict__ dh,
                                                       __half* __restrict__ dl,
                                                       int rows, int cols) {
    __shared__ float t[32][33];
    int bx = blockIdx.x * 32;
    int by = blockIdx.y * 32;
    int tx = threadIdx.x & 31, ty = (threadIdx.x >> 5) * 4;
#pragma unroll
    for (int i = 0; i < 4; i++)
        t[ty + i][tx] = src[(size_t)(by + ty + i) * cols + bx + tx];
    __syncthreads();
#pragma unroll
    for (int i = 0; i < 4; i++) {
        float v = t[tx][ty + i];
        __half hv = __float2half_rn(v);
        size_t off = (size_t)(bx + ty + i) * rows + by + tx;
        dh[off] = hv;
        if (dl) dl[off] = __float2half_rn(v - __half2float(hv));
    }
}

extern "C" void kernel_launch(void* const* d_in, const int* in_sizes, int n_in,
                              void* d_out, int out_size) {
    const float* x  = (const float*)d_in[0];
    const float* W  = (const float*)d_in[1];
    const float* b  = (const float*)d_in[2];
    const float* P  = (const float*)d_in[3];
    const float* tr = (const float*)d_in[4];

    float* blended = (float*)d_out;
    float* weights = (float*)d_out + (size_t)BATCH * DIM;

    __half *xh, *Wh, *WTh, *WTl, *PTh, *Qh, *Ql, *wh;
    float *zsq, *psq2;
    cudaGetSymbolAddress((void**)&xh, g_xh);
    cudaGetSymbolAddress((void**)&Wh, g_Wh);
    cudaGetSymbolAddress((void**)&WTh, g_WTh); cudaGetSymbolAddress((void**)&WTl, g_WTl);
    cudaGetSymbolAddress((void**)&PTh, g_PTh);
    cudaGetSymbolAddress((void**)&Qh, g_Qh);   cudaGetSymbolAddress((void**)&Ql, g_Ql);
    cudaGetSymbolAddress((void**)&wh, g_wh);
    cudaGetSymbolAddress((void**)&zsq, g_zsq); cudaGetSymbolAddress((void**)&psq2, g_psq2);

    cudaFuncSetAttribute((const void*)hmma_gemm<3, 3, 1>, cudaFuncAttributeMaxDynamicSharedMemorySize, SMEM_TOTAL);
    cudaFuncSetAttribute((const void*)hmma_gemm<2, 1, 0>, cudaFuncAttributeMaxDynamicSharedMemorySize, SMEM_TOTAL);
    cudaFuncSetAttribute((const void*)fused_logits_zsq, cudaFuncAttributeMaxDynamicSharedMemorySize, SMEM_TOTAL);

    cudaMemsetAsync(zsq, 0, BATCH * sizeof(float));

    // psq2 = |p|^2 - 2 p.b
    row_psq2<<<NPROTO, 128>>>(P, b, psq2);

    // operand prep
    split_hi<<<(BATCH * DIM / 4 + 255) / 256, 256>>>((const float4*)x, (uint2*)xh, BATCH * DIM / 4);
    split_hi<<<(DIM * DIM / 4 + 255) / 256, 256>>>((const float4*)W, (uint2*)Wh, DIM * DIM / 4);
    transpose_split<<<dim3(16, 16), 256>>>(W, WTh, WTl, DIM, DIM);
    transpose_split<<<dim3(16, 32), 256>>>(P, PTh, nullptr, NPROTO, DIM);

    // Q = P @ W (3-pass, A=P fp32 split in fill), write fp16 hi/lo
    hmma_gemm<3, 3, 1><<<dim3(DIM / 128, NPROTO / 128), 256, SMEM_TOTAL>>>(
        P, WTh, WTl, nullptr, Qh, Ql, DIM, DIM);

    // fused: Sraw = x.q^T (2-pass: xh.Qh + xh.Ql) + zsq = |x.W^T + b|^2 (1-pass)
    fused_logits_zsq<<<dim3(12, BATCH / 128), 256, SMEM_TOTAL>>>(
        xh, Qh, Ql, Wh, b, weights, zsq);

    // dist + softmax; writes fp32 weights + fp16 wh
    softmax_dist_1024<<<BATCH, 256>>>(weights, zsq, psq2, tr, wh);

    // blended = weights @ P (1-pass: wh x PTh only)
    hmma_gemm<2, 1, 0><<<dim3(DIM / 128, BATCH / 128), 256, SMEM_TOTAL>>>(
        wh, PTh, PTh, blended, nullptr, nullptr, NPROTO, DIM);
}

// round 12
// speedup vs baseline: 3.8999x; 1.1753x over previous
#include <cuda_runtime.h>
#include <cuda_fp16.h>
#include <math.h>
#include <stdint.h>

#define BATCH  65536
#define DIM    512
#define NPROTO 1024

// ---------------- device scratch ----------------
__device__ __half g_xh[(size_t)BATCH * DIM];
__device__ __half g_Wh[(size_t)DIM * DIM];
__device__ __half g_WTh[(size_t)DIM * DIM],    g_WTl[(size_t)DIM * DIM];
__device__ __half g_PTh[(size_t)DIM * NPROTO];
__device__ __half g_Qh[(size_t)NPROTO * DIM],  g_Ql[(size_t)NPROTO * DIM];
__device__ __half g_wh[(size_t)BATCH * NPROTO];
__device__ float g_zsq[BATCH];
__device__ float g_psq2[NPROTO];   // psq - 2*P.b

// ======================= helpers =======================
__device__ __forceinline__ uint32_t smem_u32(const void* p) {
    uint32_t a;
    asm("{ .reg .u64 t; cvta.to.shared.u64 t, %1; cvt.u32.u64 %0, t; }" : "=r"(a) : "l"(p));
    return a;
}

#define LDSM4(r, addr) \
    asm volatile("ldmatrix.sync.aligned.m8n8.x4.shared.b16 {%0,%1,%2,%3}, [%4];" \
        : "=r"((r)[0]), "=r"((r)[1]), "=r"((r)[2]), "=r"((r)[3]) : "r"(addr))

#define MMA16816(d, a, b0, b1) \
    asm volatile("mma.sync.aligned.m16n8k16.row.col.f32.f16.f16.f32 " \
        "{%0,%1,%2,%3}, {%4,%5,%6,%7}, {%8,%9}, {%0,%1,%2,%3};" \
        : "+f"((d)[0]), "+f"((d)[1]), "+f"((d)[2]), "+f"((d)[3]) \
        : "r"((a)[0]), "r"((a)[1]), "r"((a)[2]), "r"((a)[3]), "r"(b0), "r"(b1))

__device__ __forceinline__ void split_pair(float x, float y, uint32_t& hi, uint32_t& lo) {
    __half hx = __float2half_rn(x), hy = __float2half_rn(y);
    __half2 h2 = __halves2half2(hx, hy);
    hi = *(uint32_t*)&h2;
    __half2 l2 = __floats2half2_rn(x - __half2float(hx), y - __half2float(hy));
    lo = *(uint32_t*)&l2;
}
__device__ __forceinline__ void cvt8(const float4& a, const float4& b,
                                     uint4& hi, uint4& lo) {
    split_pair(a.x, a.y, hi.x, lo.x);
    split_pair(a.z, a.w, hi.y, lo.y);
    split_pair(b.x, b.y, hi.z, lo.z);
    split_pair(b.z, b.w, hi.w, lo.w);
}

// FFMA-pipe exp (args <= 0 here)
__device__ __forceinline__ float fexp(float x) {
    float y = x * 1.4426950408889634f;
    float t = y + 12582912.0f;
    float n = t - 12582912.0f;
    float f = y - n;
    float p = 1.3333558146e-3f;
    p = fmaf(p, f, 9.6181291076e-3f);
    p = fmaf(p, f, 5.5504108664e-2f);
    p = fmaf(p, f, 2.4022650696e-1f);
    p = fmaf(p, f, 6.9314718056e-1f);
    p = fmaf(p, f, 1.0f);
    return __int_as_float(__float_as_int(p) + (((int)n) << 23));
}

// SMEM: per buf 4 matrices (Ahi, Alo, Bhi, Blo), each 128 rows x 24 halves (48B)
#define MATB   6144u
#define BUFB   (4u * MATB)
#define SMEM_TOTAL (2 * BUFB)   // 49152

// ======================= generic HMMA GEMM NT =======================
// C[M,N] = A[M,K] @ Bm[N,K]^T.
// ASRC 0: A fp16 (Aptr=hi). ASRC 1: A fp32, full split in fill (3-pass only).
// NPASS 3: AhBh+AhBl+AlBh ; 1: AhBh only
// MODE 2: plain fp32 C ; MODE 3: write fp16 hi/lo (oh, ol)
template <int MODE, int NPASS, int ASRC>
__global__ __launch_bounds__(256, 2) void hmma_gemm(
    const void* __restrict__ Aptr,
    const __half* __restrict__ Bh, const __half* __restrict__ Bl,
    float* __restrict__ C, __half* __restrict__ oh, __half* __restrict__ ol,
    int K, int ldc) {
    extern __shared__ __align__(128) char smem[];
    const uint32_t sb = smem_u32(smem);
    const int tid = threadIdx.x;
    const int wid = tid >> 5, lane = tid & 31;
    const size_t bm = (size_t)blockIdx.y * 128;
    const size_t bn = (size_t)blockIdx.x * 128;
    const int warp_m = (wid >> 1) * 32;
    const int warp_n = (wid & 1) * 64;

    float acc[2][8][4];
#pragma unroll
    for (int i = 0; i < 2; i++)
#pragma unroll
        for (int j = 0; j < 8; j++)
#pragma unroll
            for (int k = 0; k < 4; k++) acc[i][j][k] = 0.0f;

    const __half* Ahg = (ASRC == 0) ? ((const __half*)Aptr) + bm * K : nullptr;
    const float*  Afg = (ASRC == 1) ? ((const float*)Aptr) + bm * K : nullptr;
    const __half* Bhg = Bh + bn * K;
    const __half* Blg = (NPASS >= 2) ? Bl + bn * K : nullptr;
    const int NC = K >> 4;

    const int f_r = tid >> 1;
    const int f_s = (tid & 1) << 3;
    const uint32_t soff = (uint32_t)(f_r * 48 + (tid & 1) * 16);

    // ---- prologue ----
    {
        if (ASRC == 0) {
            *(uint4*)(smem + soff) = *(const uint4*)(Ahg + (size_t)f_r * K + f_s);
        } else {
            float4 a0 = *(const float4*)(Afg + (size_t)f_r * K + f_s);
            float4 a1 = *(const float4*)(Afg + (size_t)f_r * K + f_s + 4);
            uint4 hi, lo;
            cvt8(a0, a1, hi, lo);
            *(uint4*)(smem + soff) = hi;
            *(uint4*)(smem + MATB + soff) = lo;
        }
        *(uint4*)(smem + 2 * MATB + soff) = *(const uint4*)(Bhg + (size_t)f_r * K + f_s);
        if (NPASS >= 2)
            *(uint4*)(smem + 3 * MATB + soff) = *(const uint4*)(Blg + (size_t)f_r * K + f_s);
    }
    __syncthreads();

    const int a_row = lane & 15;
    const int a_kb = ((lane >> 4) << 3) * 2;
    const int b_n = ((lane >> 4) << 3) + (lane & 7);
    const int b_kb = (lane & 8) * 2;

    uint4 pah, pbh, pbl;
    float4 pfa0, pfa1;
    for (int c = 0; c < NC; ++c) {
        const int buf = c & 1;
        const uint32_t base = sb + buf * BUFB;

        if (c + 1 < NC) {
            const int k0 = (c + 1) << 4;
            if (ASRC == 0) {
                pah = *(const uint4*)(Ahg + (size_t)f_r * K + k0 + f_s);
            } else {
                pfa0 = *(const float4*)(Afg + (size_t)f_r * K + k0 + f_s);
                pfa1 = *(const float4*)(Afg + (size_t)f_r * K + k0 + f_s + 4);
            }
            pbh = *(const uint4*)(Bhg + (size_t)f_r * K + k0 + f_s);
            if (NPASS >= 2) pbl = *(const uint4*)(Blg + (size_t)f_r * K + k0 + f_s);
        }

        uint32_t ah[2][4], al[2][4];
#pragma unroll
        for (int i = 0; i < 2; i++) {
            uint32_t ra = base + (uint32_t)((warp_m + i * 16 + a_row) * 48) + a_kb;
            LDSM4(ah[i], ra);
            if (NPASS == 3) LDSM4(al[i], ra + MATB);
        }
#pragma unroll
        for (int jp = 0; jp < 4; jp++) {
            uint32_t rb = base + 2 * MATB +
                          (uint32_t)((warp_n + jp * 16 + b_n) * 48) + b_kb;
            uint32_t bh[4], bl[4];
            LDSM4(bh, rb);
            if (NPASS >= 2) LDSM4(bl, rb + MATB);
#pragma unroll
            for (int i = 0; i < 2; i++) {
                MMA16816(acc[i][jp * 2 + 0], ah[i], bh[0], bh[1]);
                if (NPASS >= 2) MMA16816(acc[i][jp * 2 + 0], ah[i], bl[0], bl[1]);
                if (NPASS == 3) MMA16816(acc[i][jp * 2 + 0], al[i], bh[0], bh[1]);
                MMA16816(acc[i][jp * 2 + 1], ah[i], bh[2], bh[3]);
                if (NPASS >= 2) MMA16816(acc[i][jp * 2 + 1], ah[i], bl[2], bl[3]);
                if (NPASS == 3) MMA16816(acc[i][jp * 2 + 1], al[i], bh[2], bh[3]);
            }
        }

        if (c + 1 < NC) {
            const uint32_t nb = (buf ^ 1) * BUFB;
            if (ASRC == 0) {
                *(uint4*)(smem + nb + soff) = pah;
            } else {
                uint4 hi, lo;
                cvt8(pfa0, pfa1, hi, lo);
                *(uint4*)(smem + nb + soff) = hi;
                *(uint4*)(smem + nb + MATB + soff) = lo;
            }
            *(uint4*)(smem + nb + 2 * MATB + soff) = pbh;
            if (NPASS >= 2) *(uint4*)(smem + nb + 3 * MATB + soff) = pbl;
        }
        __syncthreads();
    }

    // ---- epilogue ----
    const int rbase = warp_m + (lane >> 2);
    const int cbase = warp_n + (lane & 3) * 2;
#pragma unroll
    for (int i = 0; i < 2; i++) {
#pragma unroll
        for (int h = 0; h < 2; h++) {
            const size_t row = bm + rbase + i * 16 + h * 8;
            if (MODE == 3) {
#pragma unroll
                for (int j = 0; j < 8; j++) {
                    const int cg = cbase + j * 8;
                    uint32_t hi, lo;
                    split_pair(acc[i][j][h * 2 + 0], acc[i][j][h * 2 + 1], hi, lo);
                    *(uint32_t*)(oh + row * (size_t)ldc + bn + cg) = hi;
                    *(uint32_t*)(ol + row * (size_t)ldc + bn + cg) = lo;
                }
            } else {
                float* crow = C + row * (size_t)ldc + bn;
#pragma unroll
                for (int j = 0; j < 8; j++) {
                    const int cg = cbase + j * 8;
                    *(float2*)(crow + cg) =
                        make_float2(acc[i][j][h * 2 + 0], acc[i][j][h * 2 + 1]);
                }
            }
        }
    }
}

// ======================= fused logits-raw + zsq kernel (all 1-pass) ==========
// grid (12, BATCH/128): x<8 -> Q-tile: Sraw = xh.Qh^T
//                       x>=8 -> W-tile: zsq += |xh.Wh^T + b|^2
__global__ __launch_bounds__(256, 2) void fused_logits_zsq(
    const __half* __restrict__ xh,
    const __half* __restrict__ Qh,
    const __half* __restrict__ Wh, const float* __restrict__ bias,
    float* __restrict__ Sraw, float* __restrict__ zsq) {
    extern __shared__ __align__(128) char smem[];
    const uint32_t sb = smem_u32(smem);
    const int tid = threadIdx.x;
    const int wid = tid >> 5, lane = tid & 31;
    const bool is_w = blockIdx.x >= 8;
    const size_t bm = (size_t)blockIdx.y * 128;
    const size_t bn = is_w ? (size_t)(blockIdx.x - 8) * 128 : (size_t)blockIdx.x * 128;
    const int warp_m = (wid >> 1) * 32;
    const int warp_n = (wid & 1) * 64;
    const int K = DIM, NC = DIM >> 4;

    float acc[2][8][4];
#pragma unroll
    for (int i = 0; i < 2; i++)
#pragma unroll
        for (int j = 0; j < 8; j++)
#pragma unroll
            for (int k = 0; k < 4; k++) acc[i][j][k] = 0.0f;

    const __half* Ahg = xh + bm * K;
    const __half* Bhg = (is_w ? Wh : Qh) + bn * K;

    const int f_r = tid >> 1;
    const int f_s = (tid & 1) << 3;
    const uint32_t soff = (uint32_t)(f_r * 48 + (tid & 1) * 16);

    {
        *(uint4*)(smem + soff) = *(const uint4*)(Ahg + (size_t)f_r * K + f_s);
        *(uint4*)(smem + 2 * MATB + soff) = *(const uint4*)(Bhg + (size_t)f_r * K + f_s);
    }
    __syncthreads();

    const int a_row = lane & 15;
    const int a_kb = ((lane >> 4) << 3) * 2;
    const int b_n = ((lane >> 4) << 3) + (lane & 7);
    const int b_kb = (lane & 8) * 2;

    uint4 pah, pbh;
    for (int c = 0; c < NC; ++c) {
        const int buf = c & 1;
        const uint32_t base = sb + buf * BUFB;

        if (c + 1 < NC) {
            const int k0 = (c + 1) << 4;
            pah = *(const uint4*)(Ahg + (size_t)f_r * K + k0 + f_s);
            pbh = *(const uint4*)(Bhg + (size_t)f_r * K + k0 + f_s);
        }

        uint32_t ah[2][4];
#pragma unroll
        for (int i = 0; i < 2; i++) {
            uint32_t ra = base + (uint32_t)((warp_m + i * 16 + a_row) * 48) + a_kb;
            LDSM4(ah[i], ra);
        }
#pragma unroll
        for (int jp = 0; jp < 4; jp++) {
            uint32_t rb = base + 2 * MATB +
                          (uint32_t)((warp_n + jp * 16 + b_n) * 48) + b_kb;
            uint32_t bh[4];
            LDSM4(bh, rb);
#pragma unroll
            for (int i = 0; i < 2; i++) {
                MMA16816(acc[i][jp * 2 + 0], ah[i], bh[0], bh[1]);
                MMA16816(acc[i][jp * 2 + 1], ah[i], bh[2], bh[3]);
            }
        }

        if (c + 1 < NC) {
            const uint32_t nb = (buf ^ 1) * BUFB;
            *(uint4*)(smem + nb + soff) = pah;
            *(uint4*)(smem + nb + 2 * MATB + soff) = pbh;
        }
        __syncthreads();
    }

    const int rbase = warp_m + (lane >> 2);
    const int cbase = warp_n + (lane & 3) * 2;
#pragma unroll
    for (int i = 0; i < 2; i++) {
#pragma unroll
        for (int h = 0; h < 2; h++) {
            const size_t row = bm + rbase + i * 16 + h * 8;
            if (is_w) {
                float s = 0.0f;
#pragma unroll
                for (int j = 0; j < 8; j++) {
                    const int cg = cbase + j * 8;
                    float v0 = acc[i][j][h * 2 + 0] + bias[bn + cg];
                    float v1 = acc[i][j][h * 2 + 1] + bias[bn + cg + 1];
                    s += v0 * v0 + v1 * v1;
                }
                s += __shfl_xor_sync(0xffffffffu, s, 1);
                s += __shfl_xor_sync(0xffffffffu, s, 2);
                if ((lane & 3) == 0) atomicAdd(zsq + row, s);
            } else {
                float* crow = Sraw + row * (size_t)NPROTO + bn;
#pragma unroll
                for (int j = 0; j < 8; j++) {
                    const int cg = cbase + j * 8;
                    *(float2*)(crow + cg) =
                        make_float2(acc[i][j][h * 2 + 0], acc[i][j][h * 2 + 1]);
                }
            }
        }
    }
}

// ======================= small kernels =======================
__device__ __forceinline__ float wsum(float v) {
#pragma unroll
    for (int o = 16; o; o >>= 1) v += __shfl_xor_sync(0xffffffffu, v, o);
    return v;
}
__device__ __forceinline__ float wmax(float v) {
#pragma unroll
    for (int o = 16; o; o >>= 1) v = fmaxf(v, __shfl_xor_sync(0xffffffffu, v, o));
    return v;
}

// psq2[row] = sum(P[row]^2) - 2 * dot(P[row], b)
__global__ __launch_bounds__(128) void row_psq2(const float* __restrict__ P,
                                                const float* __restrict__ b,
                                                float* __restrict__ out) {
    size_t row = blockIdx.x;
    const float4* p = (const float4*)(P + row * 512);
    float4 v = p[threadIdx.x];
    float4 bb = ((const float4*)b)[threadIdx.x];
    float s = v.x * v.x + v.y * v.y + v.z * v.z + v.w * v.w
            - 2.0f * (v.x * bb.x + v.y * bb.y + v.z * bb.z + v.w * bb.w);
    s = wsum(s);
    __shared__ float red[4];
    if ((threadIdx.x & 31) == 0) red[threadIdx.x >> 5] = s;
    __syncthreads();
    if (threadIdx.x == 0) out[row] = red[0] + red[1] + red[2] + red[3];
}

// dist + softmax over rows of 1024; reads raw dot, writes fp32 weights + fp16 hi
__global__ __launch_bounds__(256) void softmax_dist_1024(
    float* __restrict__ Wt, const float* __restrict__ zsq,
    const float* __restrict__ psq2, const float* __restrict__ temp_raw,
    __half* __restrict__ wh) {
    size_t row = blockIdx.x;
    float4* p = (float4*)(Wt + row * 1024);
    float4 s4 = p[threadIdx.x];
    float4 pq = ((const float4*)psq2)[threadIdx.x];
    float zr = zsq[row];
    float t = temp_raw[0];
    float temp = 1.0f / (1.0f + expf(-t)) * 0.999f + 0.001f;
    float invt = 1.0f / temp;

    float4 v;
    v.x = -sqrtf(fmaxf(zr + pq.x - 2.0f * s4.x, 1e-12f)) * invt;
    v.y = -sqrtf(fmaxf(zr + pq.y - 2.0f * s4.y, 1e-12f)) * invt;
    v.z = -sqrtf(fmaxf(zr + pq.z - 2.0f * s4.z, 1e-12f)) * invt;
    v.w = -sqrtf(fmaxf(zr + pq.w - 2.0f * s4.w, 1e-12f)) * invt;

    __shared__ float red[8];
    float m = fmaxf(fmaxf(v.x, v.y), fmaxf(v.z, v.w));
    m = wmax(m);
    if ((threadIdx.x & 31) == 0) red[threadIdx.x >> 5] = m;
    __syncthreads();
    if (threadIdx.x < 32) {
        float q = (threadIdx.x < 8) ? red[threadIdx.x] : -INFINITY;
        q = wmax(q);
        if (threadIdx.x == 0) red[0] = q;
    }
    __syncthreads();
    m = red[0];
    __syncthreads();

    v.x = fexp(v.x - m); v.y = fexp(v.y - m);
    v.z = fexp(v.z - m); v.w = fexp(v.w - m);
    float s = v.x + v.y + v.z + v.w;
    s = wsum(s);
    __shared__ float red2[8];
    if ((threadIdx.x & 31) == 0) red2[threadIdx.x >> 5] = s;
    __syncthreads();
    if (threadIdx.x < 32) {
        float q = (threadIdx.x < 8) ? red2[threadIdx.x] : 0.0f;
        q = wsum(q);
        if (threadIdx.x == 0) red2[0] = q;
    }
    __syncthreads();
    float inv = 1.0f / red2[0];
    v.x *= inv; v.y *= inv; v.z *= inv; v.w *= inv;
    p[threadIdx.x] = v;

    __half2 h0 = __floats2half2_rn(v.x, v.y);
    __half2 h1 = __floats2half2_rn(v.z, v.w);
    *(uint2*)(wh + row * 1024 + threadIdx.x * 4) =
        make_uint2(*(uint32_t*)&h0, *(uint32_t*)&h1);
}

// convert fp32 array to fp16 (hi only)
__global__ __launch_bounds__(256) void split_hi(const float4* __restrict__ src,
                                                uint2* __restrict__ hi, int n4) {
    int i = blockIdx.x * 256 + threadIdx.x;
    if (i >= n4) return;
    float4 v = src[i];
    __half2 h0 = __floats2half2_rn(v.x, v.y);
    __half2 h1 = __floats2half2_rn(v.z, v.w);
    hi[i] = make_uint2(*(uint32_t*)&h0, *(uint32_t*)&h1);
}

// transpose + split: src [rows, cols] fp32 -> dst [cols, rows] fp16 hi (+ optional lo)
__global__ __launch_bounds__(256) void transpose_split(const float* __restrict__ src,
                                                       __half* __restrict__ dh,
                                                       __half* __restrict__ dl,
                                                       int rows, int cols) {
    __shared__ float t[32][33];
    int bx = blockIdx.x * 32;
    int by = blockIdx.y * 32;
    int tx = threadIdx.x & 31, ty = (threadIdx.x >> 5) * 4;
#pragma unroll
    for (int i = 0; i < 4; i++)
        t[ty + i][tx] = src[(size_t)(by + ty + i) * cols + bx + tx];
    __syncthreads();
#pragma unroll
    for (int i = 0; i < 4; i++) {
        float v = t[tx][ty + i];
        __half hv = __float2half_rn(v);
        size_t off = (size_t)(bx + ty + i) * rows + by + tx;
        dh[off] = hv;
        if (dl) dl[off] = __float2half_rn(v - __half2float(hv));
    }
}

extern "C" void kernel_launch(void* const* d_in, const int* in_sizes, int n_in,
                              void* d_out, int out_size) {
    const float* x  = (const float*)d_in[0];
    const float* W  = (const float*)d_in[1];
    const float* b  = (const float*)d_in[2];
    const float* P  = (const float*)d_in[3];
    const float* tr = (const float*)d_in[4];

    float* blended = (float*)d_out;
    float* weights = (float*)d_out + (size_t)BATCH * DIM;

    __half *xh, *Wh, *WTh, *WTl, *PTh, *Qh, *Ql, *wh;
    float *zsq, *psq2;
    cudaGetSymbolAddress((void**)&xh, g_xh);
    cudaGetSymbolAddress((void**)&Wh, g_Wh);
    cudaGetSymbolAddress((void**)&WTh, g_WTh); cudaGetSymbolAddress((void**)&WTl, g_WTl);
    cudaGetSymbolAddress((void**)&PTh, g_PTh);
    cudaGetSymbolAddress((void**)&Qh, g_Qh);   cudaGetSymbolAddress((void**)&Ql, g_Ql);
    cudaGetSymbolAddress((void**)&wh, g_wh);
    cudaGetSymbolAddress((void**)&zsq, g_zsq); cudaGetSymbolAddress((void**)&psq2, g_psq2);

    cudaFuncSetAttribute((const void*)hmma_gemm<3, 3, 1>, cudaFuncAttributeMaxDynamicSharedMemorySize, SMEM_TOTAL);
    cudaFuncSetAttribute((const void*)hmma_gemm<2, 1, 0>, cudaFuncAttributeMaxDynamicSharedMemorySize, SMEM_TOTAL);
    cudaFuncSetAttribute((const void*)fused_logits_zsq, cudaFuncAttributeMaxDynamicSharedMemorySize, SMEM_TOTAL);

    cudaMemsetAsync(zsq, 0, BATCH * sizeof(float));

    // psq2 = |p|^2 - 2 p.b
    row_psq2<<<NPROTO, 128>>>(P, b, psq2);

    // operand prep
    split_hi<<<(BATCH * DIM / 4 + 255) / 256, 256>>>((const float4*)x, (uint2*)xh, BATCH * DIM / 4);
    split_hi<<<(DIM * DIM / 4 + 255) / 256, 256>>>((const float4*)W, (uint2*)Wh, DIM * DIM / 4);
    transpose_split<<<dim3(16, 16), 256>>>(W, WTh, WTl, DIM, DIM);
    transpose_split<<<dim3(16, 32), 256>>>(P, PTh, nullptr, NPROTO, DIM);

    // Q = P @ W (3-pass, fp32-accurate), write fp16 hi/lo (lo unused downstream)
    hmma_gemm<3, 3, 1><<<dim3(DIM / 128, NPROTO / 128), 256, SMEM_TOTAL>>>(
        P, WTh, WTl, nullptr, Qh, Ql, DIM, DIM);

    // fused: Sraw = xh.Qh^T (1-pass) + zsq = |xh.Wh^T + b|^2 (1-pass)
    fused_logits_zsq<<<dim3(12, BATCH / 128), 256, SMEM_TOTAL>>>(
        xh, Qh, Wh, b, weights, zsq);

    // dist + softmax; writes fp32 weights + fp16 wh
    softmax_dist_1024<<<BATCH, 256>>>(weights, zsq, psq2, tr, wh);

    // blended = weights @ P (1-pass)
    hmma_gemm<2, 1, 0><<<dim3(DIM / 128, BATCH / 128), 256, SMEM_TOTAL>>>(
        wh, PTh, PTh, blended, nullptr, nullptr, NPROTO, DIM);
}

// round 13
// speedup vs baseline: 4.6387x; 1.1894x over previous
#include <cuda_runtime.h>
#include <cuda_fp16.h>
#include <math.h>
#include <stdint.h>

#define BATCH  65536
#define DIM    512
#define NPROTO 1024

// ---------------- device scratch ----------------
__device__ __half g_xh[(size_t)BATCH * DIM];
__device__ __half g_Wh[(size_t)DIM * DIM];
__device__ __half g_WTh[(size_t)DIM * DIM],    g_WTl[(size_t)DIM * DIM];
__device__ __half g_PTh[(size_t)DIM * NPROTO];
__device__ __half g_Qh[(size_t)NPROTO * DIM],  g_Ql[(size_t)NPROTO * DIM];
__device__ __half g_wh[(size_t)BATCH * NPROTO];
__device__ float g_zsq[BATCH];
__device__ float g_psq2[NPROTO];   // psq - 2*P.b

// ======================= helpers =======================
__device__ __forceinline__ uint32_t smem_u32(const void* p) {
    uint32_t a;
    asm("{ .reg .u64 t; cvta.to.shared.u64 t, %1; cvt.u32.u64 %0, t; }" : "=r"(a) : "l"(p));
    return a;
}

#define LDSM4(r, addr) \
    asm volatile("ldmatrix.sync.aligned.m8n8.x4.shared.b16 {%0,%1,%2,%3}, [%4];" \
        : "=r"((r)[0]), "=r"((r)[1]), "=r"((r)[2]), "=r"((r)[3]) : "r"(addr))

#define MMA16816(d, a, b0, b1) \
    asm volatile("mma.sync.aligned.m16n8k16.row.col.f32.f16.f16.f32 " \
        "{%0,%1,%2,%3}, {%4,%5,%6,%7}, {%8,%9}, {%0,%1,%2,%3};" \
        : "+f"((d)[0]), "+f"((d)[1]), "+f"((d)[2]), "+f"((d)[3]) \
        : "r"((a)[0]), "r"((a)[1]), "r"((a)[2]), "r"((a)[3]), "r"(b0), "r"(b1))

__device__ __forceinline__ void split_pair(float x, float y, uint32_t& hi, uint32_t& lo) {
    __half hx = __float2half_rn(x), hy = __float2half_rn(y);
    __half2 h2 = __halves2half2(hx, hy);
    hi = *(uint32_t*)&h2;
    __half2 l2 = __floats2half2_rn(x - __half2float(hx), y - __half2float(hy));
    lo = *(uint32_t*)&l2;
}
__device__ __forceinline__ void cvt8(const float4& a, const float4& b,
                                     uint4& hi, uint4& lo) {
    split_pair(a.x, a.y, hi.x, lo.x);
    split_pair(a.z, a.w, hi.y, lo.y);
    split_pair(b.x, b.y, hi.z, lo.z);
    split_pair(b.z, b.w, hi.w, lo.w);
}

// FFMA-pipe exp (args <= 0 here)
__device__ __forceinline__ float fexp(float x) {
    float y = x * 1.4426950408889634f;
    float t = y + 12582912.0f;
    float n = t - 12582912.0f;
    float f = y - n;
    float p = 1.3333558146e-3f;
    p = fmaf(p, f, 9.6181291076e-3f);
    p = fmaf(p, f, 5.5504108664e-2f);
    p = fmaf(p, f, 2.4022650696e-1f);
    p = fmaf(p, f, 6.9314718056e-1f);
    p = fmaf(p, f, 1.0f);
    return __int_as_float(__float_as_int(p) + (((int)n) << 23));
}

// ======================= 3-pass kernel smem (BK=16, 48B rows) =================
#define MATB   6144u
#define BUFB   (4u * MATB)
#define SMEM_TOTAL (2 * BUFB)   // 49152

// ======================= 1-pass kernel smem (BK=32, 80B rows) =================
#define MAT32  10240u            // 128 rows * 80 B
#define BUF32  (2u * MAT32)      // A + B
#define SMEM32 (2 * BUF32)       // 40960

// ======================= 3-pass HMMA GEMM NT (Q = P@W only) ===================
// MODE 3: write fp16 hi/lo. A fp32 split in fill.
__global__ __launch_bounds__(256, 2) void hmma_gemm3p(
    const float* __restrict__ Afg0,
    const __half* __restrict__ Bh, const __half* __restrict__ Bl,
    __half* __restrict__ oh, __half* __restrict__ ol,
    int K, int ldc) {
    extern __shared__ __align__(128) char smem[];
    const uint32_t sb = smem_u32(smem);
    const int tid = threadIdx.x;
    const int wid = tid >> 5, lane = tid & 31;
    const size_t bm = (size_t)blockIdx.y * 128;
    const size_t bn = (size_t)blockIdx.x * 128;
    const int warp_m = (wid >> 1) * 32;
    const int warp_n = (wid & 1) * 64;

    float acc[2][8][4];
#pragma unroll
    for (int i = 0; i < 2; i++)
#pragma unroll
        for (int j = 0; j < 8; j++)
#pragma unroll
            for (int k = 0; k < 4; k++) acc[i][j][k] = 0.0f;

    const float*  Afg = Afg0 + bm * K;
    const __half* Bhg = Bh + bn * K;
    const __half* Blg = Bl + bn * K;
    const int NC = K >> 4;

    const int f_r = tid >> 1;
    const int f_s = (tid & 1) << 3;
    const uint32_t soff = (uint32_t)(f_r * 48 + (tid & 1) * 16);

    {
        float4 a0 = *(const float4*)(Afg + (size_t)f_r * K + f_s);
        float4 a1 = *(const float4*)(Afg + (size_t)f_r * K + f_s + 4);
        uint4 hi, lo;
        cvt8(a0, a1, hi, lo);
        *(uint4*)(smem + soff) = hi;
        *(uint4*)(smem + MATB + soff) = lo;
        *(uint4*)(smem + 2 * MATB + soff) = *(const uint4*)(Bhg + (size_t)f_r * K + f_s);
        *(uint4*)(smem + 3 * MATB + soff) = *(const uint4*)(Blg + (size_t)f_r * K + f_s);
    }
    __syncthreads();

    const int a_row = lane & 15;
    const int a_kb = ((lane >> 4) << 3) * 2;
    const int b_n = ((lane >> 4) << 3) + (lane & 7);
    const int b_kb = (lane & 8) * 2;

    uint4 pbh, pbl;
    float4 pfa0, pfa1;
    for (int c = 0; c < NC; ++c) {
        const int buf = c & 1;
        const uint32_t base = sb + buf * BUFB;

        if (c + 1 < NC) {
            const int k0 = (c + 1) << 4;
            pfa0 = *(const float4*)(Afg + (size_t)f_r * K + k0 + f_s);
            pfa1 = *(const float4*)(Afg + (size_t)f_r * K + k0 + f_s + 4);
            pbh = *(const uint4*)(Bhg + (size_t)f_r * K + k0 + f_s);
            pbl = *(const uint4*)(Blg + (size_t)f_r * K + k0 + f_s);
        }

        uint32_t ah[2][4], al[2][4];
#pragma unroll
        for (int i = 0; i < 2; i++) {
            uint32_t ra = base + (uint32_t)((warp_m + i * 16 + a_row) * 48) + a_kb;
            LDSM4(ah[i], ra);
            LDSM4(al[i], ra + MATB);
        }
#pragma unroll
        for (int jp = 0; jp < 4; jp++) {
            uint32_t rb = base + 2 * MATB +
                          (uint32_t)((warp_n + jp * 16 + b_n) * 48) + b_kb;
            uint32_t bh[4], bl[4];
            LDSM4(bh, rb);
            LDSM4(bl, rb + MATB);
#pragma unroll
            for (int i = 0; i < 2; i++) {
                MMA16816(acc[i][jp * 2 + 0], ah[i], bh[0], bh[1]);
                MMA16816(acc[i][jp * 2 + 0], ah[i], bl[0], bl[1]);
                MMA16816(acc[i][jp * 2 + 0], al[i], bh[0], bh[1]);
                MMA16816(acc[i][jp * 2 + 1], ah[i], bh[2], bh[3]);
                MMA16816(acc[i][jp * 2 + 1], ah[i], bl[2], bl[3]);
                MMA16816(acc[i][jp * 2 + 1], al[i], bh[2], bh[3]);
            }
        }

        if (c + 1 < NC) {
            const uint32_t nb = (buf ^ 1) * BUFB;
            uint4 hi, lo;
            cvt8(pfa0, pfa1, hi, lo);
            *(uint4*)(smem + nb + soff) = hi;
            *(uint4*)(smem + nb + MATB + soff) = lo;
            *(uint4*)(smem + nb + 2 * MATB + soff) = pbh;
            *(uint4*)(smem + nb + 3 * MATB + soff) = pbl;
        }
        __syncthreads();
    }

    const int rbase = warp_m + (lane >> 2);
    const int cbase = warp_n + (lane & 3) * 2;
#pragma unroll
    for (int i = 0; i < 2; i++) {
#pragma unroll
        for (int h = 0; h < 2; h++) {
            const size_t row = bm + rbase + i * 16 + h * 8;
#pragma unroll
            for (int j = 0; j < 8; j++) {
                const int cg = cbase + j * 8;
                uint32_t hi, lo;
                split_pair(acc[i][j][h * 2 + 0], acc[i][j][h * 2 + 1], hi, lo);
                *(uint32_t*)(oh + row * (size_t)ldc + bn + cg) = hi;
                *(uint32_t*)(ol + row * (size_t)ldc + bn + cg) = lo;
            }
        }
    }
}

// ======================= 1-pass BK=32 mainloop (shared macro body) ============
// SMEM rows: 80 B stride (odd multiple of 16B -> conflict-free ldmatrix)
// Fill: idx = tid + it*256 ; r = idx>>2 ; seg = idx&3 ; 16B per store

// fused logits+zsq: grid (12, BATCH/128); x<8: Sraw = xh.Qh^T ; x>=8: zsq
__global__ __launch_bounds__(256, 2) void fused_logits_zsq_bk32(
    const __half* __restrict__ xh,
    const __half* __restrict__ Qh,
    const __half* __restrict__ Wh, const float* __restrict__ bias,
    float* __restrict__ Sraw, float* __restrict__ zsq) {
    extern __shared__ __align__(128) char smem[];
    const uint32_t sb = smem_u32(smem);
    const int tid = threadIdx.x;
    const int wid = tid >> 5, lane = tid & 31;
    const bool is_w = blockIdx.x >= 8;
    const size_t bm = (size_t)blockIdx.y * 128;
    const size_t bn = is_w ? (size_t)(blockIdx.x - 8) * 128 : (size_t)blockIdx.x * 128;
    const int warp_m = (wid >> 1) * 32;
    const int warp_n = (wid & 1) * 64;
    const int K = DIM, NC = DIM >> 5;   // 16 chunks of 32

    float acc[2][8][4];
#pragma unroll
    for (int i = 0; i < 2; i++)
#pragma unroll
        for (int j = 0; j < 8; j++)
#pragma unroll
            for (int k = 0; k < 4; k++) acc[i][j][k] = 0.0f;

    const __half* Ahg = xh + bm * K;
    const __half* Bhg = (is_w ? Wh : Qh) + bn * K;

    const int f_r0 = tid >> 2, f_r1 = (tid + 256) >> 2;
    const int f_s = (tid & 3) << 3;              // halves offset 0,8,16,24
    const uint32_t so0 = (uint32_t)(f_r0 * 80 + (tid & 3) * 16);
    const uint32_t so1 = (uint32_t)(f_r1 * 80 + (tid & 3) * 16);

    {
        *(uint4*)(smem + so0) = *(const uint4*)(Ahg + (size_t)f_r0 * K + f_s);
        *(uint4*)(smem + so1) = *(const uint4*)(Ahg + (size_t)f_r1 * K + f_s);
        *(uint4*)(smem + MAT32 + so0) = *(const uint4*)(Bhg + (size_t)f_r0 * K + f_s);
        *(uint4*)(smem + MAT32 + so1) = *(const uint4*)(Bhg + (size_t)f_r1 * K + f_s);
    }
    __syncthreads();

    const int a_row = lane & 15;
    const int a_kb = ((lane >> 4) << 3) * 2;
    const int b_n = ((lane >> 4) << 3) + (lane & 7);
    const int b_kb = (lane & 8) * 2;

    uint4 pa0, pa1, pb0, pb1;
    for (int c = 0; c < NC; ++c) {
        const int buf = c & 1;
        const uint32_t base = sb + buf * BUF32;

        if (c + 1 < NC) {
            const int k0 = (c + 1) << 5;
            pa0 = *(const uint4*)(Ahg + (size_t)f_r0 * K + k0 + f_s);
            pa1 = *(const uint4*)(Ahg + (size_t)f_r1 * K + k0 + f_s);
            pb0 = *(const uint4*)(Bhg + (size_t)f_r0 * K + k0 + f_s);
            pb1 = *(const uint4*)(Bhg + (size_t)f_r1 * K + k0 + f_s);
        }

#pragma unroll
        for (int kk = 0; kk < 2; kk++) {
            const int kb = kk * 32;   // 16 halves = 32 B
            uint32_t ah[2][4];
#pragma unroll
            for (int i = 0; i < 2; i++) {
                uint32_t ra = base + (uint32_t)((warp_m + i * 16 + a_row) * 80) + kb + a_kb;
                LDSM4(ah[i], ra);
            }
#pragma unroll
            for (int jp = 0; jp < 4; jp++) {
                uint32_t rb = base + MAT32 +
                              (uint32_t)((warp_n + jp * 16 + b_n) * 80) + kb + b_kb;
                uint32_t bh[4];
                LDSM4(bh, rb);
#pragma unroll
                for (int i = 0; i < 2; i++) {
                    MMA16816(acc[i][jp * 2 + 0], ah[i], bh[0], bh[1]);
                    MMA16816(acc[i][jp * 2 + 1], ah[i], bh[2], bh[3]);
                }
            }
        }

        if (c + 1 < NC) {
            const uint32_t nb = (buf ^ 1) * BUF32;
            *(uint4*)(smem + nb + so0) = pa0;
            *(uint4*)(smem + nb + so1) = pa1;
            *(uint4*)(smem + nb + MAT32 + so0) = pb0;
            *(uint4*)(smem + nb + MAT32 + so1) = pb1;
        }
        __syncthreads();
    }

    const int rbase = warp_m + (lane >> 2);
    const int cbase = warp_n + (lane & 3) * 2;
#pragma unroll
    for (int i = 0; i < 2; i++) {
#pragma unroll
        for (int h = 0; h < 2; h++) {
            const size_t row = bm + rbase + i * 16 + h * 8;
            if (is_w) {
                float s = 0.0f;
#pragma unroll
                for (int j = 0; j < 8; j++) {
                    const int cg = cbase + j * 8;
                    float v0 = acc[i][j][h * 2 + 0] + bias[bn + cg];
                    float v1 = acc[i][j][h * 2 + 1] + bias[bn + cg + 1];
                    s += v0 * v0 + v1 * v1;
                }
                s += __shfl_xor_sync(0xffffffffu, s, 1);
                s += __shfl_xor_sync(0xffffffffu, s, 2);
                if ((lane & 3) == 0) atomicAdd(zsq + row, s);
            } else {
                float* crow = Sraw + row * (size_t)NPROTO + bn;
#pragma unroll
                for (int j = 0; j < 8; j++) {
                    const int cg = cbase + j * 8;
                    *(float2*)(crow + cg) =
                        make_float2(acc[i][j][h * 2 + 0], acc[i][j][h * 2 + 1]);
                }
            }
        }
    }
}

// blended = A(fp16) @ B(fp16)^T, 1-pass, BK=32, fp32 out
__global__ __launch_bounds__(256, 2) void hmma_gemm1p_bk32(
    const __half* __restrict__ Ah, const __half* __restrict__ Bh,
    float* __restrict__ C, int K, int ldc) {
    extern __shared__ __align__(128) char smem[];
    const uint32_t sb = smem_u32(smem);
    const int tid = threadIdx.x;
    const int wid = tid >> 5, lane = tid & 31;
    const size_t bm = (size_t)blockIdx.y * 128;
    const size_t bn = (size_t)blockIdx.x * 128;
    const int warp_m = (wid >> 1) * 32;
    const int warp_n = (wid & 1) * 64;
    const int NC = K >> 5;

    float acc[2][8][4];
#pragma unroll
    for (int i = 0; i < 2; i++)
#pragma unroll
        for (int j = 0; j < 8; j++)
#pragma unroll
            for (int k = 0; k < 4; k++) acc[i][j][k] = 0.0f;

    const __half* Ahg = Ah + bm * K;
    const __half* Bhg = Bh + bn * K;

    const int f_r0 = tid >> 2, f_r1 = (tid + 256) >> 2;
    const int f_s = (tid & 3) << 3;
    const uint32_t so0 = (uint32_t)(f_r0 * 80 + (tid & 3) * 16);
    const uint32_t so1 = (uint32_t)(f_r1 * 80 + (tid & 3) * 16);

    {
        *(uint4*)(smem + so0) = *(const uint4*)(Ahg + (size_t)f_r0 * K + f_s);
        *(uint4*)(smem + so1) = *(const uint4*)(Ahg + (size_t)f_r1 * K + f_s);
        *(uint4*)(smem + MAT32 + so0) = *(const uint4*)(Bhg + (size_t)f_r0 * K + f_s);
        *(uint4*)(smem + MAT32 + so1) = *(const uint4*)(Bhg + (size_t)f_r1 * K + f_s);
    }
    __syncthreads();

    const int a_row = lane & 15;
    const int a_kb = ((lane >> 4) << 3) * 2;
    const int b_n = ((lane >> 4) << 3) + (lane & 7);
    const int b_kb = (lane & 8) * 2;

    uint4 pa0, pa1, pb0, pb1;
    for (int c = 0; c < NC; ++c) {
        const int buf = c & 1;
        const uint32_t base = sb + buf * BUF32;

        if (c + 1 < NC) {
            const int k0 = (c + 1) << 5;
            pa0 = *(const uint4*)(Ahg + (size_t)f_r0 * K + k0 + f_s);
            pa1 = *(const uint4*)(Ahg + (size_t)f_r1 * K + k0 + f_s);
            pb0 = *(const uint4*)(Bhg + (size_t)f_r0 * K + k0 + f_s);
            pb1 = *(const uint4*)(Bhg + (size_t)f_r1 * K + k0 + f_s);
        }

#pragma unroll
        for (int kk = 0; kk < 2; kk++) {
            const int kb = kk * 32;
            uint32_t ah[2][4];
#pragma unroll
            for (int i = 0; i < 2; i++) {
                uint32_t ra = base + (uint32_t)((warp_m + i * 16 + a_row) * 80) + kb + a_kb;
                LDSM4(ah[i], ra);
            }
#pragma unroll
            for (int jp = 0; jp < 4; jp++) {
                uint32_t rb = base + MAT32 +
                              (uint32_t)((warp_n + jp * 16 + b_n) * 80) + kb + b_kb;
                uint32_t bh[4];
                LDSM4(bh, rb);
#pragma unroll
                for (int i = 0; i < 2; i++) {
                    MMA16816(acc[i][jp * 2 + 0], ah[i], bh[0], bh[1]);
                    MMA16816(acc[i][jp * 2 + 1], ah[i], bh[2], bh[3]);
                }
            }
        }

        if (c + 1 < NC) {
            const uint32_t nb = (buf ^ 1) * BUF32;
            *(uint4*)(smem + nb + so0) = pa0;
            *(uint4*)(smem + nb + so1) = pa1;
            *(uint4*)(smem + nb + MAT32 + so0) = pb0;
            *(uint4*)(smem + nb + MAT32 + so1) = pb1;
        }
        __syncthreads();
    }

    const int rbase = warp_m + (lane >> 2);
    const int cbase = warp_n + (lane & 3) * 2;
#pragma unroll
    for (int i = 0; i < 2; i++) {
#pragma unroll
        for (int h = 0; h < 2; h++) {
            const size_t row = bm + rbase + i * 16 + h * 8;
            float* crow = C + row * (size_t)ldc + bn;
#pragma unroll
            for (int j = 0; j < 8; j++) {
                const int cg = cbase + j * 8;
                *(float2*)(crow + cg) =
                    make_float2(acc[i][j][h * 2 + 0], acc[i][j][h * 2 + 1]);
            }
        }
    }
}

// ======================= small kernels =======================
__device__ __forceinline__ float wsum(float v) {
#pragma unroll
    for (int o = 16; o; o >>= 1) v += __shfl_xor_sync(0xffffffffu, v, o);
    return v;
}
__device__ __forceinline__ float wmax(float v) {
#pragma unroll
    for (int o = 16; o; o >>= 1) v = fmaxf(v, __shfl_xor_sync(0xffffffffu, v, o));
    return v;
}

// psq2[row] = sum(P[row]^2) - 2 * dot(P[row], b)
__global__ __launch_bounds__(128) void row_psq2(const float* __restrict__ P,
                                                const float* __restrict__ b,
                                                float* __restrict__ out) {
    size_t row = blockIdx.x;
    const float4* p = (const float4*)(P + row * 512);
    float4 v = p[threadIdx.x];
    float4 bb = ((const float4*)b)[threadIdx.x];
    float s = v.x * v.x + v.y * v.y + v.z * v.z + v.w * v.w
            - 2.0f * (v.x * bb.x + v.y * bb.y + v.z * bb.z + v.w * bb.w);
    s = wsum(s);
    __shared__ float red[4];
    if ((threadIdx.x & 31) == 0) red[threadIdx.x >> 5] = s;
    __syncthreads();
    if (threadIdx.x == 0) out[row] = red[0] + red[1] + red[2] + red[3];
}

// dist + softmax over rows of 1024; reads raw dot, writes fp32 weights + fp16 hi
__global__ __launch_bounds__(256) void softmax_dist_1024(
    float* __restrict__ Wt, const float* __restrict__ zsq,
    const float* __restrict__ psq2, const float* __restrict__ temp_raw,
    __half* __restrict__ wh) {
    size_t row = blockIdx.x;
    float4* p = (float4*)(Wt + row * 1024);
    float4 s4 = p[threadIdx.x];
    float4 pq = ((const float4*)psq2)[threadIdx.x];
    float zr = zsq[row];
    float t = temp_raw[0];
    float temp = 1.0f / (1.0f + expf(-t)) * 0.999f + 0.001f;
    float invt = 1.0f / temp;

    float4 v;
    v.x = -sqrtf(fmaxf(zr + pq.x - 2.0f * s4.x, 1e-12f)) * invt;
    v.y = -sqrtf(fmaxf(zr + pq.y - 2.0f * s4.y, 1e-12f)) * invt;
    v.z = -sqrtf(fmaxf(zr + pq.z - 2.0f * s4.z, 1e-12f)) * invt;
    v.w = -sqrtf(fmaxf(zr + pq.w - 2.0f * s4.w, 1e-12f)) * invt;

    __shared__ float red[8];
    float m = fmaxf(fmaxf(v.x, v.y), fmaxf(v.z, v.w));
    m = wmax(m);
    if ((threadIdx.x & 31) == 0) red[threadIdx.x >> 5] = m;
    __syncthreads();
    if (threadIdx.x < 32) {
        float q = (threadIdx.x < 8) ? red[threadIdx.x] : -INFINITY;
        q = wmax(q);
        if (threadIdx.x == 0) red[0] = q;
    }
    __syncthreads();
    m = red[0];
    __syncthreads();

    v.x = fexp(v.x - m); v.y = fexp(v.y - m);
    v.z = fexp(v.z - m); v.w = fexp(v.w - m);
    float s = v.x + v.y + v.z + v.w;
    s = wsum(s);
    __shared__ float red2[8];
    if ((threadIdx.x & 31) == 0) red2[threadIdx.x >> 5] = s;
    __syncthreads();
    if (threadIdx.x < 32) {
        float q = (threadIdx.x < 8) ? red2[threadIdx.x] : 0.0f;
        q = wsum(q);
        if (threadIdx.x == 0) red2[0] = q;
    }
    __syncthreads();
    float inv = 1.0f / red2[0];
    v.x *= inv; v.y *= inv; v.z *= inv; v.w *= inv;
    p[threadIdx.x] = v;

    __half2 h0 = __floats2half2_rn(v.x, v.y);
    __half2 h1 = __floats2half2_rn(v.z, v.w);
    *(uint2*)(wh + row * 1024 + threadIdx.x * 4) =
        make_uint2(*(uint32_t*)&h0, *(uint32_t*)&h1);
}

// convert fp32 array to fp16 (hi only)
__global__ __launch_bounds__(256) void split_hi(const float4* __restrict__ src,
                                                uint2* __restrict__ hi, int n4) {
    int i = blockIdx.x * 256 + threadIdx.x;
    if (i >= n4) return;
    float4 v = src[i];
    __half2 h0 = __floats2half2_rn(v.x, v.y);
    __half2 h1 = __floats2half2_rn(v.z, v.w);
    hi[i] = make_uint2(*(uint32_t*)&h0, *(uint32_t*)&h1);
}

// transpose + split: src [rows, cols] fp32 -> dst [cols, rows] fp16 hi (+ optional lo)
__global__ __launch_bounds__(256) void transpose_split(const float* __restrict__ src,
                                                       __half* __restrict__ dh,
                                                       __half* __restrict__ dl,
                                                       int rows, int cols) {
    __shared__ float t[32][33];
    int bx = blockIdx.x * 32;
    int by = blockIdx.y * 32;
    int tx = threadIdx.x & 31, ty = (threadIdx.x >> 5) * 4;
#pragma unroll
    for (int i = 0; i < 4; i++)
        t[ty + i][tx] = src[(size_t)(by + ty + i) * cols + bx + tx];
    __syncthreads();
#pragma unroll
    for (int i = 0; i < 4; i++) {
        float v = t[tx][ty + i];
        __half hv = __float2half_rn(v);
        size_t off = (size_t)(bx + ty + i) * rows + by + tx;
        dh[off] = hv;
        if (dl) dl[off] = __float2half_rn(v - __half2float(hv));
    }
}

extern "C" void kernel_launch(void* const* d_in, const int* in_sizes, int n_in,
                              void* d_out, int out_size) {
    const float* x  = (const float*)d_in[0];
    const float* W  = (const float*)d_in[1];
    const float* b  = (const float*)d_in[2];
    const float* P  = (const float*)d_in[3];
    const float* tr = (const float*)d_in[4];

    float* blended = (float*)d_out;
    float* weights = (float*)d_out + (size_t)BATCH * DIM;

    __half *xh, *Wh, *WTh, *WTl, *PTh, *Qh, *Ql, *wh;
    float *zsq, *psq2;
    cudaGetSymbolAddress((void**)&xh, g_xh);
    cudaGetSymbolAddress((void**)&Wh, g_Wh);
    cudaGetSymbolAddress((void**)&WTh, g_WTh); cudaGetSymbolAddress((void**)&WTl, g_WTl);
    cudaGetSymbolAddress((void**)&PTh, g_PTh);
    cudaGetSymbolAddress((void**)&Qh, g_Qh);   cudaGetSymbolAddress((void**)&Ql, g_Ql);
    cudaGetSymbolAddress((void**)&wh, g_wh);
    cudaGetSymbolAddress((void**)&zsq, g_zsq); cudaGetSymbolAddress((void**)&psq2, g_psq2);

    cudaFuncSetAttribute((const void*)hmma_gemm3p, cudaFuncAttributeMaxDynamicSharedMemorySize, SMEM_TOTAL);
    cudaFuncSetAttribute((const void*)fused_logits_zsq_bk32, cudaFuncAttributeMaxDynamicSharedMemorySize, SMEM32);
    cudaFuncSetAttribute((const void*)hmma_gemm1p_bk32, cudaFuncAttributeMaxDynamicSharedMemorySize, SMEM32);

    cudaMemsetAsync(zsq, 0, BATCH * sizeof(float));

    // psq2 = |p|^2 - 2 p.b
    row_psq2<<<NPROTO, 128>>>(P, b, psq2);

    // operand prep
    split_hi<<<(BATCH * DIM / 4 + 255) / 256, 256>>>((const float4*)x, (uint2*)xh, BATCH * DIM / 4);
    split_hi<<<(DIM * DIM / 4 + 255) / 256, 256>>>((const float4*)W, (uint2*)Wh, DIM * DIM / 4);
    transpose_split<<<dim3(16, 16), 256>>>(W, WTh, WTl, DIM, DIM);
    transpose_split<<<dim3(16, 32), 256>>>(P, PTh, nullptr, NPROTO, DIM);

    // Q = P @ W (3-pass, fp32-accurate), write fp16 hi/lo
    hmma_gemm3p<<<dim3(DIM / 128, NPROTO / 128), 256, SMEM_TOTAL>>>(
        P, WTh, WTl, Qh, Ql, DIM, DIM);

    // fused: Sraw = xh.Qh^T + zsq (both 1-pass, BK=32)
    fused_logits_zsq_bk32<<<dim3(12, BATCH / 128), 256, SMEM32>>>(
        xh, Qh, Wh, b, weights, zsq);

    // dist + softmax; writes fp32 weights + fp16 wh
    softmax_dist_1024<<<BATCH, 256>>>(weights, zsq, psq2, tr, wh);

    // blended = weights @ P (1-pass, BK=32)
    hmma_gemm1p_bk32<<<dim3(DIM / 128, BATCH / 128), 256, SMEM32>>>(
        wh, PTh, blended, NPROTO, DIM);
}